// round 1
// baseline (speedup 1.0000x reference)
#include <cuda_runtime.h>
#include <math.h>

#define BB   16
#define CC   256
#define ICC  64
#define HH   56
#define PP   (HH*HH)      // 3136
#define OUTH 58
#define EPSV 1e-5f
#define SCALEV (1.0f/896.0f)   // (56*56*256)^-0.5 exactly

// ---------------- scratch (no allocs allowed) ----------------
__device__ float g_t1 [BB*ICC*PP];
__device__ float g_lq [BB*CC*PP];
__device__ float g_lk [BB*CC*PP];
__device__ float g_lv [BB*CC*PP];
__device__ float g_gk [BB*CC*PP];
__device__ float g_gv [BB*CC*PP];
__device__ float g_f  [BB*CC*PP];
__device__ float g_xbar[BB*CC];
__device__ float g_gqs [BB*CC];

// ---------------- epilogue modes ----------------
#define EPI_NONE 0
#define EPI_BIAS 1
#define EPI_BN   2
#define EPI_BNLR 3
#define EPI_PAD  4

// ---------------- batched SGEMM: Y[b] = W(MxK) @ X[b](KxP) ----------------
// BN=64, BK=16, 256 threads, thread tile TM x 4, TM = BM/16.
template<int BM, int EPI>
__global__ __launch_bounds__(256)
void gemm_kernel(const float* __restrict__ W, const float* __restrict__ X,
                 float* __restrict__ Y, int K,
                 const float* __restrict__ bias,
                 const float* __restrict__ gamma,
                 const float* __restrict__ beta)
{
    constexpr int BN = 64, BK = 16;
    constexpr int TM = BM / 16;
    __shared__ float As[BK][BM];
    __shared__ float Bs[BK][BN];

    const int tid = threadIdx.x;
    const int tx = tid & 15, ty = tid >> 4;
    const int n0 = blockIdx.x * BN;
    const int m0 = blockIdx.y * BM;
    const int b  = blockIdx.z;
    const int Mtot = gridDim.y * BM;
    const float* Xb = X + (size_t)b * K * PP;

    float acc[TM][4];
    #pragma unroll
    for (int i = 0; i < TM; i++)
        #pragma unroll
        for (int j = 0; j < 4; j++) acc[i][j] = 0.f;

    const int brow = tid >> 4;          // 0..15
    const int bcol = (tid & 15) << 2;   // 0..60 step 4
    constexpr int AV = (BM * BK) / (256 * 4);   // float4 per thread for A

    for (int kt = 0; kt < K; kt += BK) {
        #pragma unroll
        for (int q = 0; q < AV; q++) {
            int vid = tid + q * 256;
            int row = vid >> 2;
            int kq  = (vid & 3) << 2;
            const float4 va = *reinterpret_cast<const float4*>(
                W + (size_t)(m0 + row) * K + kt + kq);
            As[kq + 0][row] = va.x; As[kq + 1][row] = va.y;
            As[kq + 2][row] = va.z; As[kq + 3][row] = va.w;
        }
        *reinterpret_cast<float4*>(&Bs[brow][bcol]) =
            *reinterpret_cast<const float4*>(Xb + (size_t)(kt + brow) * PP + n0 + bcol);
        __syncthreads();

        #pragma unroll
        for (int kk = 0; kk < BK; kk++) {
            float av[TM];
            #pragma unroll
            for (int v = 0; v < TM / 4; v++) {
                float4 a4 = *reinterpret_cast<const float4*>(&As[kk][ty * TM + v * 4]);
                av[v*4+0] = a4.x; av[v*4+1] = a4.y; av[v*4+2] = a4.z; av[v*4+3] = a4.w;
            }
            float4 b4 = *reinterpret_cast<const float4*>(&Bs[kk][tx << 2]);
            float bv[4] = {b4.x, b4.y, b4.z, b4.w};
            #pragma unroll
            for (int i = 0; i < TM; i++)
                #pragma unroll
                for (int j = 0; j < 4; j++)
                    acc[i][j] = fmaf(av[i], bv[j], acc[i][j]);
        }
        __syncthreads();
    }

    // epilogue
    #pragma unroll
    for (int i = 0; i < TM; i++) {
        const int row = m0 + ty * TM + i;
        float add0 = 0.f, sc = 1.f, sh = 0.f;
        if (EPI == EPI_BIAS || EPI == EPI_PAD) add0 = bias[row];
        if (EPI == EPI_BN || EPI == EPI_BNLR) {
            add0 = bias[row];
            sc = gamma[row] * rsqrtf(1.0f + EPSV);
            sh = beta[row];
        }
        if (EPI == EPI_PAD) {
            #pragma unroll
            for (int j = 0; j < 4; j++) {
                int col = n0 + (tx << 2) + j;
                int h = col / HH, w = col - h * HH;
                Y[((size_t)(b * CC + row) * OUTH + (h + 1)) * OUTH + (w + 1)]
                    = acc[i][j] + add0;
            }
        } else {
            float vs[4];
            #pragma unroll
            for (int j = 0; j < 4; j++) {
                float y = acc[i][j];
                if (EPI == EPI_BIAS) y += add0;
                if (EPI == EPI_BN || EPI == EPI_BNLR) y = (y + add0) * sc + sh;
                if (EPI == EPI_BNLR) y = (y >= 0.f) ? y : 0.2f * y;
                vs[j] = y;
            }
            float4 o; o.x = vs[0]; o.y = vs[1]; o.z = vs[2]; o.w = vs[3];
            *reinterpret_cast<float4*>(
                Y + ((size_t)b * Mtot + row) * PP + n0 + (tx << 2)) = o;
        }
    }
}

// ---------------- per-(b,c) mean of x_mt ----------------
__global__ void mean_kernel(const float* __restrict__ x, float* __restrict__ xbar)
{
    __shared__ float red[256];
    const int bc = blockIdx.x;
    const float* p = x + (size_t)bc * PP;
    float s = 0.f;
    for (int i = threadIdx.x; i < PP; i += 256) s += p[i];
    red[threadIdx.x] = s;
    __syncthreads();
    for (int o = 128; o > 0; o >>= 1) {
        if (threadIdx.x < o) red[threadIdx.x] += red[threadIdx.x + o];
        __syncthreads();
    }
    if (threadIdx.x == 0) xbar[bc] = red[0] * (1.0f / PP);
}

// ---------------- global-branch query MLP: gqs[b,c] = SCALE * g_q[b,c] ----------------
__global__ void gq_kernel(const float* __restrict__ xbar,
                          const float* __restrict__ c11_w, const float* __restrict__ c11_b,
                          const float* __restrict__ ga_w1, const float* __restrict__ ga_b1,
                          const float* __restrict__ ga_g1, const float* __restrict__ ga_be1,
                          const float* __restrict__ ga_w2, const float* __restrict__ ga_b2,
                          const float* __restrict__ ga_g2, const float* __restrict__ ga_be2,
                          float* __restrict__ gqs)
{
    __shared__ float xb[CC], pv[CC], tv[ICC];
    const int b = blockIdx.x, t = threadIdx.x;
    const float rs = rsqrtf(1.0f + EPSV);
    xb[t] = xbar[b * CC + t];
    __syncthreads();
    // p = c11_w @ xbar + c11_b
    {
        float d = 0.f;
        const float* wr = c11_w + (size_t)t * CC;
        for (int c = 0; c < CC; c++) d = fmaf(wr[c], xb[c], d);
        pv[t] = d + c11_b[t];
    }
    __syncthreads();
    // t = lrelu(bn(ga_w1 @ p + ga_b1))
    if (t < ICC) {
        float d = 0.f;
        const float* wr = ga_w1 + (size_t)t * CC;
        for (int c = 0; c < CC; c++) d = fmaf(wr[c], pv[c], d);
        d = (d + ga_b1[t]) * (ga_g1[t] * rs) + ga_be1[t];
        tv[t] = (d >= 0.f) ? d : 0.2f * d;
    }
    __syncthreads();
    // u = bn(ga_w2 @ t + ga_b2); gqs = u * SCALE
    {
        float d = 0.f;
        const float* wr = ga_w2 + (size_t)t * ICC;
        for (int i = 0; i < ICC; i++) d = fmaf(wr[i], tv[i], d);
        d = (d + ga_b2[t]) * (ga_g2[t] * rs) + ga_be2[t];
        gqs[b * CC + t] = d * SCALEV;
    }
}

// ---------------- per-(b,c) local+global attention -> f ----------------
__global__ __launch_bounds__(256)
void attn_kernel(const float* __restrict__ lq, const float* __restrict__ lk,
                 const float* __restrict__ lv, const float* __restrict__ gk,
                 const float* __restrict__ gv, const float* __restrict__ gqs,
                 float* __restrict__ f)
{
    __shared__ float s0[HH * 57];
    __shared__ float s1[HH * 57];
    __shared__ float s2[HH * 57];
    const int bc = blockIdx.x;
    const size_t base = (size_t)bc * PP;
    const int t = threadIdx.x;
    const int hg = t >> 4, wg = t & 15;
    const bool act = (hg < 14) && (wg < 14);
    const int h0 = hg * 4, w0 = wg * 4;

    // P1: load l_q -> s0, l_k -> s1
    for (int idx = t; idx < PP; idx += 256) {
        int h = idx / HH, w = idx - h * HH;
        s0[h * 57 + w] = lq[base + idx];
        s1[h * 57 + w] = lk[base + idx];
    }
    __syncthreads();

    // P2: scores A[h,v] = SCALE * sum_w q[h,w]*k[v,w]  -> s2
    if (act) {
        float a[4][4];
        #pragma unroll
        for (int i = 0; i < 4; i++)
            #pragma unroll
            for (int j = 0; j < 4; j++) a[i][j] = 0.f;
        for (int w = 0; w < HH; w++) {
            float qa[4], kb[4];
            #pragma unroll
            for (int i = 0; i < 4; i++) qa[i] = s0[(h0 + i) * 57 + w];
            #pragma unroll
            for (int j = 0; j < 4; j++) kb[j] = s1[(w0 + j) * 57 + w];
            #pragma unroll
            for (int i = 0; i < 4; i++)
                #pragma unroll
                for (int j = 0; j < 4; j++) a[i][j] = fmaf(qa[i], kb[j], a[i][j]);
        }
        #pragma unroll
        for (int i = 0; i < 4; i++)
            #pragma unroll
            for (int j = 0; j < 4; j++)
                s2[(h0 + i) * 57 + (w0 + j)] = a[i][j] * SCALEV;
    }
    __syncthreads();

    // P3: row softmax of s2
    if (t < HH) {
        float* r = s2 + t * 57;
        float m = -1e30f;
        for (int j = 0; j < HH; j++) m = fmaxf(m, r[j]);
        float s = 0.f;
        for (int j = 0; j < HH; j++) { float e = __expf(r[j] - m); r[j] = e; s += e; }
        float inv = 1.f / s;
        for (int j = 0; j < HH; j++) r[j] *= inv;
    }
    __syncthreads();

    // P4: load l_v -> s0, g_k -> s1
    for (int idx = t; idx < PP; idx += 256) {
        int h = idx / HH, w = idx - h * HH;
        s0[h * 57 + w] = lv[base + idx];
        s1[h * 57 + w] = gk[base + idx];
    }
    __syncthreads();

    // P5: out = A @ l_v
    float outv[4][4];
    #pragma unroll
    for (int i = 0; i < 4; i++)
        #pragma unroll
        for (int j = 0; j < 4; j++) outv[i][j] = 0.f;
    if (act) {
        for (int v = 0; v < HH; v++) {
            float aa[4], vb[4];
            #pragma unroll
            for (int i = 0; i < 4; i++) aa[i] = s2[(h0 + i) * 57 + v];
            #pragma unroll
            for (int j = 0; j < 4; j++) vb[j] = s0[v * 57 + w0 + j];
            #pragma unroll
            for (int i = 0; i < 4; i++)
                #pragma unroll
                for (int j = 0; j < 4; j++) outv[i][j] = fmaf(aa[i], vb[j], outv[i][j]);
        }
    }
    __syncthreads();

    // P6: load g_v -> s0; global softmax rows: s2[h,k] = softmax_k(gq * g_k[h,k])
    for (int idx = t; idx < PP; idx += 256) {
        int h = idx / HH, w = idx - h * HH;
        s0[h * 57 + w] = gv[base + idx];
    }
    const float gq = gqs[bc];
    if (t < HH) {
        const float* r1 = s1 + t * 57;
        float* r2 = s2 + t * 57;
        float m = -1e30f;
        for (int k = 0; k < HH; k++) m = fmaxf(m, gq * r1[k]);
        float s = 0.f;
        for (int k = 0; k < HH; k++) { float e = __expf(gq * r1[k] - m); r2[k] = e; s += e; }
        float inv = 1.f / s;
        for (int k = 0; k < HH; k++) r2[k] *= inv;
    }
    __syncthreads();

    // P7: out += Gatt @ g_v
    if (act) {
        for (int v = 0; v < HH; v++) {
            float aa[4], vb[4];
            #pragma unroll
            for (int i = 0; i < 4; i++) aa[i] = s2[(h0 + i) * 57 + v];
            #pragma unroll
            for (int j = 0; j < 4; j++) vb[j] = s0[v * 57 + w0 + j];
            #pragma unroll
            for (int i = 0; i < 4; i++)
                #pragma unroll
                for (int j = 0; j < 4; j++) outv[i][j] = fmaf(aa[i], vb[j], outv[i][j]);
        }
        // P8: store f
        #pragma unroll
        for (int i = 0; i < 4; i++)
            #pragma unroll
            for (int j = 0; j < 4; j++)
                f[base + (h0 + i) * HH + (w0 + j)] = outv[i][j];
    }
}

// ---------------- output border/bias fill ----------------
__global__ void fill_bias_kernel(float* __restrict__ out, const float* __restrict__ bias)
{
    int idx = blockIdx.x * 256 + threadIdx.x;
    if (idx < BB * CC * OUTH * OUTH) {
        int o = (idx / (OUTH * OUTH)) % CC;
        out[idx] = bias[o];
    }
}

// ---------------- launch ----------------
extern "C" void kernel_launch(void* const* d_in, const int* in_sizes, int n_in,
                              void* d_out, int out_size)
{
    const float* x_s    = (const float*)d_in[0];
    const float* x_fq   = (const float*)d_in[1];
    const float* x_mt   = (const float*)d_in[2];
    const float* la_w1  = (const float*)d_in[3];
    const float* la_b1  = (const float*)d_in[4];
    const float* la_g1  = (const float*)d_in[5];
    const float* la_be1 = (const float*)d_in[6];
    const float* la_w2  = (const float*)d_in[7];
    const float* la_b2  = (const float*)d_in[8];
    const float* la_g2  = (const float*)d_in[9];
    const float* la_be2 = (const float*)d_in[10];
    const float* lk_w   = (const float*)d_in[11];
    const float* lk_b   = (const float*)d_in[12];
    const float* lv_w   = (const float*)d_in[13];
    const float* ga_w1  = (const float*)d_in[14];
    const float* ga_b1  = (const float*)d_in[15];
    const float* ga_g1  = (const float*)d_in[16];
    const float* ga_be1 = (const float*)d_in[17];
    const float* ga_w2  = (const float*)d_in[18];
    const float* ga_b2  = (const float*)d_in[19];
    const float* ga_g2  = (const float*)d_in[20];
    const float* ga_be2 = (const float*)d_in[21];
    const float* gk_w   = (const float*)d_in[22];
    const float* gk_b   = (const float*)d_in[23];
    const float* gv_w   = (const float*)d_in[24];
    const float* c11_w  = (const float*)d_in[25];
    const float* c11_b  = (const float*)d_in[26];
    const float* c1_w   = (const float*)d_in[27];
    const float* c1_b   = (const float*)d_in[28];
    float* out = (float*)d_out;

    float *t1, *lq, *lk, *lv, *gk, *gv, *fbuf, *xbar, *gqs;
    cudaGetSymbolAddress((void**)&t1,   g_t1);
    cudaGetSymbolAddress((void**)&lq,   g_lq);
    cudaGetSymbolAddress((void**)&lk,   g_lk);
    cudaGetSymbolAddress((void**)&lv,   g_lv);
    cudaGetSymbolAddress((void**)&gk,   g_gk);
    cudaGetSymbolAddress((void**)&gv,   g_gv);
    cudaGetSymbolAddress((void**)&fbuf, g_f);
    cudaGetSymbolAddress((void**)&xbar, g_xbar);
    cudaGetSymbolAddress((void**)&gqs,  g_gqs);

    const int total_out = BB * CC * OUTH * OUTH;
    fill_bias_kernel<<<(total_out + 255) / 256, 256>>>(out, c1_b);

    mean_kernel<<<BB * CC, 256>>>(x_mt, xbar);
    gq_kernel<<<BB, 256>>>(xbar, c11_w, c11_b,
                           ga_w1, ga_b1, ga_g1, ga_be1,
                           ga_w2, ga_b2, ga_g2, ga_be2, gqs);

    {   // t1 = lrelu(bn(la_w1 @ x_s + la_b1))   (M=64, K=256)
        dim3 g(PP / 64, ICC / 64, BB);
        gemm_kernel<64, EPI_BNLR><<<g, 256>>>(la_w1, x_s, t1, CC, la_b1, la_g1, la_be1);
    }
    {
        dim3 g(PP / 64, CC / 128, BB);
        // l_q = bn(la_w2 @ t1 + la_b2)          (M=256, K=64)
        gemm_kernel<128, EPI_BN  ><<<g, 256>>>(la_w2, t1,   lq, ICC, la_b2, la_g2, la_be2);
        // l_k / l_v / g_k / g_v                 (M=256, K=256)
        gemm_kernel<128, EPI_BIAS><<<g, 256>>>(lk_w, x_s,  lk, CC, lk_b, lk_b, lk_b);
        gemm_kernel<128, EPI_NONE><<<g, 256>>>(lv_w, x_s,  lv, CC, lk_b, lk_b, lk_b);
        gemm_kernel<128, EPI_BIAS><<<g, 256>>>(gk_w, x_fq, gk, CC, gk_b, gk_b, gk_b);
        gemm_kernel<128, EPI_NONE><<<g, 256>>>(gv_w, x_fq, gv, CC, gk_b, gk_b, gk_b);
    }

    attn_kernel<<<BB * CC, 256>>>(lq, lk, lv, gk, gv, gqs, fbuf);

    {   // out interior = c1_w @ f + c1_b, padded store
        dim3 g(PP / 64, CC / 128, BB);
        gemm_kernel<128, EPI_PAD><<<g, 256>>>(c1_w, fbuf, out, CC, c1_b, c1_b, c1_b);
    }
}

// round 2
// speedup vs baseline: 1.0071x; 1.0071x over previous
#include <cuda_runtime.h>
#include <math.h>

#define BB   16
#define CC   256
#define ICC  64
#define HH   56
#define PP   (HH*HH)      // 3136
#define OUTH 58
#define EPSV 1e-5f
#define SCALEV (1.0f/896.0f)   // (56*56*256)^-0.5 exactly

// ---------------- scratch (no allocs allowed) ----------------
__device__ float g_t1 [BB*ICC*PP];
__device__ float g_lq [BB*CC*PP];
__device__ float g_lk [BB*CC*PP];
__device__ float g_lv [BB*CC*PP];
__device__ float g_gk [BB*CC*PP];
__device__ float g_gv [BB*CC*PP];
__device__ float g_f  [BB*CC*PP];
__device__ float g_xbar[BB*CC];
__device__ float g_gqs [BB*CC];

// ---------------- epilogue modes ----------------
#define EPI_NONE 0
#define EPI_BIAS 1
#define EPI_BN   2
#define EPI_BNLR 3
#define EPI_PAD  4

// ---------------- batched SGEMM: Y[b] = W(MxK) @ X[b](KxP) ----------------
// BN=64, BK=16, 256 threads, thread tile TM x 4, TM = BM/16.
template<int BM, int EPI>
__global__ __launch_bounds__(256)
void gemm_kernel(const float* __restrict__ W, const float* __restrict__ X,
                 float* __restrict__ Y, int K,
                 const float* __restrict__ bias,
                 const float* __restrict__ gamma,
                 const float* __restrict__ beta)
{
    constexpr int BN = 64, BK = 16;
    constexpr int TM = BM / 16;
    __shared__ float As[BK][BM];
    __shared__ float Bs[BK][BN];

    const int tid = threadIdx.x;
    const int tx = tid & 15, ty = tid >> 4;
    const int n0 = blockIdx.x * BN;
    const int m0 = blockIdx.y * BM;
    const int b  = blockIdx.z;
    const int Mtot = gridDim.y * BM;
    const float* Xb = X + (size_t)b * K * PP;

    float acc[TM][4];
    #pragma unroll
    for (int i = 0; i < TM; i++)
        #pragma unroll
        for (int j = 0; j < 4; j++) acc[i][j] = 0.f;

    const int brow = tid >> 4;          // 0..15
    const int bcol = (tid & 15) << 2;   // 0..60 step 4
    constexpr int AV = (BM * BK) / (256 * 4);   // float4 per thread for A

    for (int kt = 0; kt < K; kt += BK) {
        #pragma unroll
        for (int q = 0; q < AV; q++) {
            int vid = tid + q * 256;
            int row = vid >> 2;
            int kq  = (vid & 3) << 2;
            const float4 va = *reinterpret_cast<const float4*>(
                W + (size_t)(m0 + row) * K + kt + kq);
            As[kq + 0][row] = va.x; As[kq + 1][row] = va.y;
            As[kq + 2][row] = va.z; As[kq + 3][row] = va.w;
        }
        *reinterpret_cast<float4*>(&Bs[brow][bcol]) =
            *reinterpret_cast<const float4*>(Xb + (size_t)(kt + brow) * PP + n0 + bcol);
        __syncthreads();

        #pragma unroll
        for (int kk = 0; kk < BK; kk++) {
            float av[TM];
            #pragma unroll
            for (int v = 0; v < TM / 4; v++) {
                float4 a4 = *reinterpret_cast<const float4*>(&As[kk][ty * TM + v * 4]);
                av[v*4+0] = a4.x; av[v*4+1] = a4.y; av[v*4+2] = a4.z; av[v*4+3] = a4.w;
            }
            float4 b4 = *reinterpret_cast<const float4*>(&Bs[kk][tx << 2]);
            float bv[4] = {b4.x, b4.y, b4.z, b4.w};
            #pragma unroll
            for (int i = 0; i < TM; i++)
                #pragma unroll
                for (int j = 0; j < 4; j++)
                    acc[i][j] = fmaf(av[i], bv[j], acc[i][j]);
        }
        __syncthreads();
    }

    // epilogue
    #pragma unroll
    for (int i = 0; i < TM; i++) {
        const int row = m0 + ty * TM + i;
        float add0 = 0.f, sc = 1.f, sh = 0.f;
        if (EPI == EPI_BIAS || EPI == EPI_PAD) add0 = bias[row];
        if (EPI == EPI_BN || EPI == EPI_BNLR) {
            add0 = bias[row];
            sc = gamma[row] * rsqrtf(1.0f + EPSV);
            sh = beta[row];
        }
        if (EPI == EPI_PAD) {
            #pragma unroll
            for (int j = 0; j < 4; j++) {
                int col = n0 + (tx << 2) + j;
                int h = col / HH, w = col - h * HH;
                Y[((size_t)(b * CC + row) * OUTH + (h + 1)) * OUTH + (w + 1)]
                    = acc[i][j] + add0;
            }
        } else {
            float vs[4];
            #pragma unroll
            for (int j = 0; j < 4; j++) {
                float y = acc[i][j];
                if (EPI == EPI_BIAS) y += add0;
                if (EPI == EPI_BN || EPI == EPI_BNLR) y = (y + add0) * sc + sh;
                if (EPI == EPI_BNLR) y = (y >= 0.f) ? y : 0.2f * y;
                vs[j] = y;
            }
            float4 o; o.x = vs[0]; o.y = vs[1]; o.z = vs[2]; o.w = vs[3];
            *reinterpret_cast<float4*>(
                Y + ((size_t)b * Mtot + row) * PP + n0 + (tx << 2)) = o;
        }
    }
}

// ---------------- per-(b,c) mean of x_mt ----------------
__global__ void mean_kernel(const float* __restrict__ x, float* __restrict__ xbar)
{
    __shared__ float red[256];
    const int bc = blockIdx.x;
    const float* p = x + (size_t)bc * PP;
    float s = 0.f;
    for (int i = threadIdx.x; i < PP; i += 256) s += p[i];
    red[threadIdx.x] = s;
    __syncthreads();
    for (int o = 128; o > 0; o >>= 1) {
        if (threadIdx.x < o) red[threadIdx.x] += red[threadIdx.x + o];
        __syncthreads();
    }
    if (threadIdx.x == 0) xbar[bc] = red[0] * (1.0f / PP);
}

// ---------------- global-branch query MLP: gqs[b,c] = SCALE * g_q[b,c] ----------------
__global__ void gq_kernel(const float* __restrict__ xbar,
                          const float* __restrict__ c11_w, const float* __restrict__ c11_b,
                          const float* __restrict__ ga_w1, const float* __restrict__ ga_b1,
                          const float* __restrict__ ga_g1, const float* __restrict__ ga_be1,
                          const float* __restrict__ ga_w2, const float* __restrict__ ga_b2,
                          const float* __restrict__ ga_g2, const float* __restrict__ ga_be2,
                          float* __restrict__ gqs)
{
    __shared__ float xb[CC], pv[CC], tv[ICC];
    const int b = blockIdx.x, t = threadIdx.x;
    const float rs = rsqrtf(1.0f + EPSV);
    xb[t] = xbar[b * CC + t];
    __syncthreads();
    // p = c11_w @ xbar + c11_b
    {
        float d = 0.f;
        const float* wr = c11_w + (size_t)t * CC;
        for (int c = 0; c < CC; c++) d = fmaf(wr[c], xb[c], d);
        pv[t] = d + c11_b[t];
    }
    __syncthreads();
    // t = lrelu(bn(ga_w1 @ p + ga_b1))
    if (t < ICC) {
        float d = 0.f;
        const float* wr = ga_w1 + (size_t)t * CC;
        for (int c = 0; c < CC; c++) d = fmaf(wr[c], pv[c], d);
        d = (d + ga_b1[t]) * (ga_g1[t] * rs) + ga_be1[t];
        tv[t] = (d >= 0.f) ? d : 0.2f * d;
    }
    __syncthreads();
    // u = bn(ga_w2 @ t + ga_b2); gqs = u * SCALE
    {
        float d = 0.f;
        const float* wr = ga_w2 + (size_t)t * ICC;
        for (int i = 0; i < ICC; i++) d = fmaf(wr[i], tv[i], d);
        d = (d + ga_b2[t]) * (ga_g2[t] * rs) + ga_be2[t];
        gqs[b * CC + t] = d * SCALEV;
    }
}

// ---------------- per-(b,c) local+global attention -> f ----------------
__global__ __launch_bounds__(256)
void attn_kernel(const float* __restrict__ lq, const float* __restrict__ lk,
                 const float* __restrict__ lv, const float* __restrict__ gk,
                 const float* __restrict__ gv, const float* __restrict__ gqs,
                 float* __restrict__ f)
{
    __shared__ float s0[HH * 57];
    __shared__ float s1[HH * 57];
    __shared__ float s2[HH * 57];
    const int bc = blockIdx.x;
    const size_t base = (size_t)bc * PP;
    const int t = threadIdx.x;
    const int hg = t >> 4, wg = t & 15;
    const bool act = (hg < 14) && (wg < 14);
    const int h0 = hg * 4, w0 = wg * 4;

    // P1: load l_q -> s0, l_k -> s1
    for (int idx = t; idx < PP; idx += 256) {
        int h = idx / HH, w = idx - h * HH;
        s0[h * 57 + w] = lq[base + idx];
        s1[h * 57 + w] = lk[base + idx];
    }
    __syncthreads();

    // P2: scores A[h,v] = SCALE * sum_w q[h,w]*k[v,w]  -> s2
    if (act) {
        float a[4][4];
        #pragma unroll
        for (int i = 0; i < 4; i++)
            #pragma unroll
            for (int j = 0; j < 4; j++) a[i][j] = 0.f;
        for (int w = 0; w < HH; w++) {
            float qa[4], kb[4];
            #pragma unroll
            for (int i = 0; i < 4; i++) qa[i] = s0[(h0 + i) * 57 + w];
            #pragma unroll
            for (int j = 0; j < 4; j++) kb[j] = s1[(w0 + j) * 57 + w];
            #pragma unroll
            for (int i = 0; i < 4; i++)
                #pragma unroll
                for (int j = 0; j < 4; j++) a[i][j] = fmaf(qa[i], kb[j], a[i][j]);
        }
        #pragma unroll
        for (int i = 0; i < 4; i++)
            #pragma unroll
            for (int j = 0; j < 4; j++)
                s2[(h0 + i) * 57 + (w0 + j)] = a[i][j] * SCALEV;
    }
    __syncthreads();

    // P3: row softmax of s2
    if (t < HH) {
        float* r = s2 + t * 57;
        float m = -1e30f;
        for (int j = 0; j < HH; j++) m = fmaxf(m, r[j]);
        float s = 0.f;
        for (int j = 0; j < HH; j++) { float e = __expf(r[j] - m); r[j] = e; s += e; }
        float inv = 1.f / s;
        for (int j = 0; j < HH; j++) r[j] *= inv;
    }
    __syncthreads();

    // P4: load l_v -> s0, g_k -> s1
    for (int idx = t; idx < PP; idx += 256) {
        int h = idx / HH, w = idx - h * HH;
        s0[h * 57 + w] = lv[base + idx];
        s1[h * 57 + w] = gk[base + idx];
    }
    __syncthreads();

    // P5: out = A @ l_v
    float outv[4][4];
    #pragma unroll
    for (int i = 0; i < 4; i++)
        #pragma unroll
        for (int j = 0; j < 4; j++) outv[i][j] = 0.f;
    if (act) {
        for (int v = 0; v < HH; v++) {
            float aa[4], vb[4];
            #pragma unroll
            for (int i = 0; i < 4; i++) aa[i] = s2[(h0 + i) * 57 + v];
            #pragma unroll
            for (int j = 0; j < 4; j++) vb[j] = s0[v * 57 + w0 + j];
            #pragma unroll
            for (int i = 0; i < 4; i++)
                #pragma unroll
                for (int j = 0; j < 4; j++) outv[i][j] = fmaf(aa[i], vb[j], outv[i][j]);
        }
    }
    __syncthreads();

    // P6: load g_v -> s0; global softmax rows: s2[h,k] = softmax_k(gq * g_k[h,k])
    for (int idx = t; idx < PP; idx += 256) {
        int h = idx / HH, w = idx - h * HH;
        s0[h * 57 + w] = gv[base + idx];
    }
    const float gq = gqs[bc];
    if (t < HH) {
        const float* r1 = s1 + t * 57;
        float* r2 = s2 + t * 57;
        float m = -1e30f;
        for (int k = 0; k < HH; k++) m = fmaxf(m, gq * r1[k]);
        float s = 0.f;
        for (int k = 0; k < HH; k++) { float e = __expf(gq * r1[k] - m); r2[k] = e; s += e; }
        float inv = 1.f / s;
        for (int k = 0; k < HH; k++) r2[k] *= inv;
    }
    __syncthreads();

    // P7: out += Gatt @ g_v
    if (act) {
        for (int v = 0; v < HH; v++) {
            float aa[4], vb[4];
            #pragma unroll
            for (int i = 0; i < 4; i++) aa[i] = s2[(h0 + i) * 57 + v];
            #pragma unroll
            for (int j = 0; j < 4; j++) vb[j] = s0[v * 57 + w0 + j];
            #pragma unroll
            for (int i = 0; i < 4; i++)
                #pragma unroll
                for (int j = 0; j < 4; j++) outv[i][j] = fmaf(aa[i], vb[j], outv[i][j]);
        }
        // P8: store f
        #pragma unroll
        for (int i = 0; i < 4; i++)
            #pragma unroll
            for (int j = 0; j < 4; j++)
                f[base + (h0 + i) * HH + (w0 + j)] = outv[i][j];
    }
}

// ---------------- output border/bias fill ----------------
__global__ void fill_bias_kernel(float* __restrict__ out, const float* __restrict__ bias)
{
    int idx = blockIdx.x * 256 + threadIdx.x;
    if (idx < BB * CC * OUTH * OUTH) {
        int o = (idx / (OUTH * OUTH)) % CC;
        out[idx] = bias[o];
    }
}

// ---------------- launch ----------------
extern "C" void kernel_launch(void* const* d_in, const int* in_sizes, int n_in,
                              void* d_out, int out_size)
{
    const float* x_s    = (const float*)d_in[0];
    const float* x_fq   = (const float*)d_in[1];
    const float* x_mt   = (const float*)d_in[2];
    const float* la_w1  = (const float*)d_in[3];
    const float* la_b1  = (const float*)d_in[4];
    const float* la_g1  = (const float*)d_in[5];
    const float* la_be1 = (const float*)d_in[6];
    const float* la_w2  = (const float*)d_in[7];
    const float* la_b2  = (const float*)d_in[8];
    const float* la_g2  = (const float*)d_in[9];
    const float* la_be2 = (const float*)d_in[10];
    const float* lk_w   = (const float*)d_in[11];
    const float* lk_b   = (const float*)d_in[12];
    const float* lv_w   = (const float*)d_in[13];
    const float* ga_w1  = (const float*)d_in[14];
    const float* ga_b1  = (const float*)d_in[15];
    const float* ga_g1  = (const float*)d_in[16];
    const float* ga_be1 = (const float*)d_in[17];
    const float* ga_w2  = (const float*)d_in[18];
    const float* ga_b2  = (const float*)d_in[19];
    const float* ga_g2  = (const float*)d_in[20];
    const float* ga_be2 = (const float*)d_in[21];
    const float* gk_w   = (const float*)d_in[22];
    const float* gk_b   = (const float*)d_in[23];
    const float* gv_w   = (const float*)d_in[24];
    const float* c11_w  = (const float*)d_in[25];
    const float* c11_b  = (const float*)d_in[26];
    const float* c1_w   = (const float*)d_in[27];
    const float* c1_b   = (const float*)d_in[28];
    float* out = (float*)d_out;

    float *t1, *lq, *lk, *lv, *gk, *gv, *fbuf, *xbar, *gqs;
    cudaGetSymbolAddress((void**)&t1,   g_t1);
    cudaGetSymbolAddress((void**)&lq,   g_lq);
    cudaGetSymbolAddress((void**)&lk,   g_lk);
    cudaGetSymbolAddress((void**)&lv,   g_lv);
    cudaGetSymbolAddress((void**)&gk,   g_gk);
    cudaGetSymbolAddress((void**)&gv,   g_gv);
    cudaGetSymbolAddress((void**)&fbuf, g_f);
    cudaGetSymbolAddress((void**)&xbar, g_xbar);
    cudaGetSymbolAddress((void**)&gqs,  g_gqs);

    const int total_out = BB * CC * OUTH * OUTH;
    fill_bias_kernel<<<(total_out + 255) / 256, 256>>>(out, c1_b);

    mean_kernel<<<BB * CC, 256>>>(x_mt, xbar);
    gq_kernel<<<BB, 256>>>(xbar, c11_w, c11_b,
                           ga_w1, ga_b1, ga_g1, ga_be1,
                           ga_w2, ga_b2, ga_g2, ga_be2, gqs);

    {   // t1 = lrelu(bn(la_w1 @ x_s + la_b1))   (M=64, K=256)
        dim3 g(PP / 64, ICC / 64, BB);
        gemm_kernel<64, EPI_BNLR><<<g, 256>>>(la_w1, x_s, t1, CC, la_b1, la_g1, la_be1);
    }
    {
        dim3 g(PP / 64, CC / 128, BB);
        // l_q = bn(la_w2 @ t1 + la_b2)          (M=256, K=64)
        gemm_kernel<128, EPI_BN  ><<<g, 256>>>(la_w2, t1,   lq, ICC, la_b2, la_g2, la_be2);
        // l_k / l_v / g_k / g_v                 (M=256, K=256)
        gemm_kernel<128, EPI_BIAS><<<g, 256>>>(lk_w, x_s,  lk, CC, lk_b, lk_b, lk_b);
        gemm_kernel<128, EPI_NONE><<<g, 256>>>(lv_w, x_s,  lv, CC, lk_b, lk_b, lk_b);
        gemm_kernel<128, EPI_BIAS><<<g, 256>>>(gk_w, x_fq, gk, CC, gk_b, gk_b, gk_b);
        gemm_kernel<128, EPI_NONE><<<g, 256>>>(gv_w, x_fq, gv, CC, gk_b, gk_b, gk_b);
    }

    attn_kernel<<<BB * CC, 256>>>(lq, lk, lv, gk, gv, gqs, fbuf);

    {   // out interior = c1_w @ f + c1_b, padded store
        dim3 g(PP / 64, CC / 128, BB);
        gemm_kernel<128, EPI_PAD><<<g, 256>>>(c1_w, fbuf, out, CC, c1_b, c1_b, c1_b);
    }
}

// round 4
// speedup vs baseline: 1.3648x; 1.3551x over previous
#include <cuda_runtime.h>
#include <math.h>
#include <stdint.h>

#define BB   16
#define CC   256
#define ICC  64
#define HH   56
#define PP   (HH*HH)
#define OUTH 58
#define EPSV 1e-5f
#define SCALEV (1.0f/896.0f)

// ---------------- scratch ----------------
__device__ float g_t1 [BB*ICC*PP];
__device__ float g_lq [BB*CC*PP];
__device__ float g_lk [BB*CC*PP];
__device__ float g_lv [BB*CC*PP];
__device__ float g_gk [BB*CC*PP];
__device__ float g_gv [BB*CC*PP];
__device__ float g_f  [BB*CC*PP];
__device__ float g_xrs [BB*CC*PP];
__device__ float g_xrfq[BB*CC*PP];
__device__ float g_xbar[BB*CC];
__device__ float g_gqs [BB*CC];
__device__ float g_wr [5*CC*CC + 2*CC*ICC];

#define EPI_NONE 0
#define EPI_BIAS 1
#define EPI_BN   2
#define EPI_BNLR 3
#define EPI_PAD  4

__device__ __forceinline__ float rn_tf32(float x){
    uint32_t u; asm("cvt.rna.tf32.f32 %0, %1;":"=r"(u):"f"(x));
    return __uint_as_float(u);
}
__device__ __forceinline__ void mma8(float c[4],
    uint32_t a0, uint32_t a1, uint32_t a2, uint32_t a3, uint32_t b0, uint32_t b1){
    asm volatile(
        "mma.sync.aligned.m16n8k8.row.col.f32.tf32.tf32.f32 "
        "{%0,%1,%2,%3}, {%4,%5,%6,%7}, {%8,%9}, {%0,%1,%2,%3};"
        : "+f"(c[0]),"+f"(c[1]),"+f"(c[2]),"+f"(c[3])
        : "r"(a0),"r"(a1),"r"(a2),"r"(a3),"r"(b0),"r"(b1));
}

// ---------------- tf32 tensor-core batched GEMM ----------------
// Y[b, m, p] = sum_k W[m,k] * X[b,k,p]  (+epilogue). W, X pre-rounded to tf32.
// BN=128, BK=16, 256 thr, warps 2(M)x4(N), warp tile (BM/2)x32.
template<int BM, int EPI>
__global__ __launch_bounds__(256)
void mma_gemm(const float* __restrict__ W, const float* __restrict__ X,
              float* __restrict__ Y, int K, int Mtot,
              const float* __restrict__ bias,
              const float* __restrict__ gamma,
              const float* __restrict__ beta)
{
    constexpr int BN=128, BK=16;
    constexpr int MT = BM/32;      // m16 tiles per warp
    constexpr int NT = 4;          // n8 tiles per warp
    __shared__ float As[BK][BM+8];
    __shared__ float Bs[BK][BN+8];

    const int tid=threadIdx.x, wid=tid>>5, lane=tid&31;
    const int gid=lane>>2, tig=lane&3;
    const int warpM=wid>>2, warpN=wid&3;
    const int m0=blockIdx.y*BM, n0=blockIdx.x*BN, b=blockIdx.z;
    const float* Wt = W + (size_t)m0*K;
    const float* Xb = X + (size_t)b*K*PP;

    float c[MT][NT][4];
    #pragma unroll
    for(int m=0;m<MT;m++)
        #pragma unroll
        for(int n=0;n<NT;n++)
            #pragma unroll
            for(int q=0;q<4;q++) c[m][n][q]=0.f;

    for(int kt=0; kt<K; kt+=BK){
        #pragma unroll
        for(int idx=tid; idx<BM*4; idx+=256){
            int row = idx>>2, c4 = (idx&3)<<2;
            float4 v = *reinterpret_cast<const float4*>(Wt + (size_t)row*K + kt + c4);
            As[c4+0][row]=v.x; As[c4+1][row]=v.y; As[c4+2][row]=v.z; As[c4+3][row]=v.w;
        }
        #pragma unroll
        for(int idx=tid; idx<512; idx+=256){
            int kr = idx>>5, c4 = (idx&31)<<2;
            int p = n0 + c4;
            float4 v;
            if(p < PP) v = *reinterpret_cast<const float4*>(Xb + (size_t)(kt+kr)*PP + p);
            else { v.x=0.f; v.y=0.f; v.z=0.f; v.w=0.f; }
            Bs[kr][c4+0]=v.x; Bs[kr][c4+1]=v.y; Bs[kr][c4+2]=v.z; Bs[kr][c4+3]=v.w;
        }
        __syncthreads();

        #pragma unroll
        for(int kk=0; kk<BK; kk+=8){
            uint32_t a[MT][4], bb[NT][2];
            #pragma unroll
            for(int m=0;m<MT;m++){
                int mr = warpM*(BM/2) + m*16;
                a[m][0]=__float_as_uint(As[kk+tig  ][mr+gid  ]);
                a[m][1]=__float_as_uint(As[kk+tig  ][mr+gid+8]);
                a[m][2]=__float_as_uint(As[kk+tig+4][mr+gid  ]);
                a[m][3]=__float_as_uint(As[kk+tig+4][mr+gid+8]);
            }
            #pragma unroll
            for(int n=0;n<NT;n++){
                int nc = warpN*32 + n*8;
                bb[n][0]=__float_as_uint(Bs[kk+tig  ][nc+gid]);
                bb[n][1]=__float_as_uint(Bs[kk+tig+4][nc+gid]);
            }
            #pragma unroll
            for(int m=0;m<MT;m++)
                #pragma unroll
                for(int n=0;n<NT;n++)
                    mma8(c[m][n], a[m][0],a[m][1],a[m][2],a[m][3], bb[n][0],bb[n][1]);
        }
        __syncthreads();
    }

    // ---- epilogue ----
    const float rs = rsqrtf(1.0f+EPSV);
    #pragma unroll
    for(int m=0;m<MT;m++){
        #pragma unroll
        for(int half=0; half<2; half++){
            const int row = m0 + warpM*(BM/2) + m*16 + gid + half*8;
            float add0=0.f, sc=1.f, sh=0.f;
            if(EPI==EPI_BIAS || EPI==EPI_PAD) add0=bias[row];
            if(EPI==EPI_BN || EPI==EPI_BNLR){
                add0=bias[row]; sc=gamma[row]*rs; sh=beta[row];
            }
            #pragma unroll
            for(int n=0;n<NT;n++){
                const int col = n0 + warpN*32 + n*8 + 2*tig;
                #pragma unroll
                for(int q=0;q<2;q++){
                    int p = col+q;
                    if(p < PP){
                        float y = c[m][n][half*2+q];
                        if(EPI==EPI_BIAS) y += add0;
                        if(EPI==EPI_BN)   y = (y+add0)*sc+sh;
                        if(EPI==EPI_BNLR){
                            y = (y+add0)*sc+sh;
                            y = (y>=0.f)? y : 0.2f*y;
                            y = rn_tf32(y);        // consumed by tf32 GEMM
                        }
                        if(EPI==EPI_PAD){
                            int h=p/HH, w=p-h*HH;
                            Y[((size_t)(b*CC+row)*OUTH + h+1)*OUTH + w+1] = y + add0;
                        } else {
                            Y[((size_t)b*Mtot + row)*PP + p] = y;
                        }
                    }
                }
            }
        }
    }
}

// ---------------- tf32 round copy ----------------
__global__ void round_copy(const float* __restrict__ s, float* __restrict__ d, int n)
{
    int i=blockIdx.x*256+threadIdx.x;
    if(i<n) d[i]=rn_tf32(s[i]);
}

// ---------------- per-(b,c) mean ----------------
__global__ void mean_kernel(const float* __restrict__ x, float* __restrict__ xbar)
{
    __shared__ float red[256];
    const int bc=blockIdx.x;
    const float* p = x + (size_t)bc*PP;
    float s=0.f;
    for(int i=threadIdx.x;i<PP;i+=256) s+=p[i];
    red[threadIdx.x]=s; __syncthreads();
    for(int o=128;o>0;o>>=1){ if(threadIdx.x<o) red[threadIdx.x]+=red[threadIdx.x+o]; __syncthreads(); }
    if(threadIdx.x==0) xbar[bc]=red[0]*(1.0f/PP);
}

// ---------------- global-branch query MLP ----------------
__global__ void gq_kernel(const float* __restrict__ xbar,
                          const float* __restrict__ c11_w, const float* __restrict__ c11_b,
                          const float* __restrict__ ga_w1, const float* __restrict__ ga_b1,
                          const float* __restrict__ ga_g1, const float* __restrict__ ga_be1,
                          const float* __restrict__ ga_w2, const float* __restrict__ ga_b2,
                          const float* __restrict__ ga_g2, const float* __restrict__ ga_be2,
                          float* __restrict__ gqs)
{
    __shared__ float xb[CC], pv[CC], tv[ICC];
    const int b=blockIdx.x, t=threadIdx.x;
    const float rs=rsqrtf(1.0f+EPSV);
    xb[t]=xbar[b*CC+t]; __syncthreads();
    { float d=0.f; const float* wr=c11_w+(size_t)t*CC;
      for(int c=0;c<CC;c++) d=fmaf(wr[c],xb[c],d);
      pv[t]=d+c11_b[t]; }
    __syncthreads();
    if(t<ICC){ float d=0.f; const float* wr=ga_w1+(size_t)t*CC;
      for(int c=0;c<CC;c++) d=fmaf(wr[c],pv[c],d);
      d=(d+ga_b1[t])*(ga_g1[t]*rs)+ga_be1[t];
      tv[t]=(d>=0.f)?d:0.2f*d; }
    __syncthreads();
    { float d=0.f; const float* wr=ga_w2+(size_t)t*ICC;
      for(int i=0;i<ICC;i++) d=fmaf(wr[i],tv[i],d);
      d=(d+ga_b2[t])*(ga_g2[t]*rs)+ga_be2[t];
      gqs[b*CC+t]=d*SCALEV; }
}

// ---------------- per-(b,c) attention ----------------
__global__ __launch_bounds__(256)
void attn_kernel(const float* __restrict__ lq, const float* __restrict__ lk,
                 const float* __restrict__ lv, const float* __restrict__ gk,
                 const float* __restrict__ gv, const float* __restrict__ gqs,
                 float* __restrict__ f)
{
    __shared__ float s0[HH*57];
    __shared__ float s1[HH*57];
    __shared__ float s2[HH*57];
    const int bc=blockIdx.x;
    const size_t base=(size_t)bc*PP;
    const int t=threadIdx.x;
    const int hg=t>>4, wg=t&15;
    const bool act=(hg<14)&&(wg<14);
    const int h0=hg*4, w0=wg*4;

    for(int idx=t; idx<PP; idx+=256){
        int h=idx/HH, w=idx-h*HH;
        s0[h*57+w]=lq[base+idx];
        s1[h*57+w]=lk[base+idx];
    }
    __syncthreads();
    if(act){
        float a[4][4];
        #pragma unroll
        for(int i=0;i<4;i++)
            #pragma unroll
            for(int j=0;j<4;j++) a[i][j]=0.f;
        for(int w=0;w<HH;w++){
            float qa[4],kb[4];
            #pragma unroll
            for(int i=0;i<4;i++) qa[i]=s0[(h0+i)*57+w];
            #pragma unroll
            for(int j=0;j<4;j++) kb[j]=s1[(w0+j)*57+w];
            #pragma unroll
            for(int i=0;i<4;i++)
                #pragma unroll
                for(int j=0;j<4;j++) a[i][j]=fmaf(qa[i],kb[j],a[i][j]);
        }
        #pragma unroll
        for(int i=0;i<4;i++)
            #pragma unroll
            for(int j=0;j<4;j++) s2[(h0+i)*57+(w0+j)]=a[i][j]*SCALEV;
    }
    __syncthreads();
    if(t<HH){
        float* r=s2+t*57;
        float m=-1e30f;
        for(int j=0;j<HH;j++) m=fmaxf(m,r[j]);
        float s=0.f;
        for(int j=0;j<HH;j++){ float e=__expf(r[j]-m); r[j]=e; s+=e; }
        float inv=1.f/s;
        for(int j=0;j<HH;j++) r[j]*=inv;
    }
    __syncthreads();
    for(int idx=t; idx<PP; idx+=256){
        int h=idx/HH, w=idx-h*HH;
        s0[h*57+w]=lv[base+idx];
        s1[h*57+w]=gk[base+idx];
    }
    __syncthreads();
    float outv[4][4];
    #pragma unroll
    for(int i=0;i<4;i++)
        #pragma unroll
        for(int j=0;j<4;j++) outv[i][j]=0.f;
    if(act){
        for(int v=0;v<HH;v++){
            float aa[4],vb[4];
            #pragma unroll
            for(int i=0;i<4;i++) aa[i]=s2[(h0+i)*57+v];
            #pragma unroll
            for(int j=0;j<4;j++) vb[j]=s0[v*57+w0+j];
            #pragma unroll
            for(int i=0;i<4;i++)
                #pragma unroll
                for(int j=0;j<4;j++) outv[i][j]=fmaf(aa[i],vb[j],outv[i][j]);
        }
    }
    __syncthreads();
    for(int idx=t; idx<PP; idx+=256){
        int h=idx/HH, w=idx-h*HH;
        s0[h*57+w]=gv[base+idx];
    }
    const float gq=gqs[bc];
    if(t<HH){
        const float* r1=s1+t*57;
        float* r2=s2+t*57;
        float m=-1e30f;
        for(int k=0;k<HH;k++) m=fmaxf(m,gq*r1[k]);
        float s=0.f;
        for(int k=0;k<HH;k++){ float e=__expf(gq*r1[k]-m); r2[k]=e; s+=e; }
        float inv=1.f/s;
        for(int k=0;k<HH;k++) r2[k]*=inv;
    }
    __syncthreads();
    if(act){
        for(int v=0;v<HH;v++){
            float aa[4],vb[4];
            #pragma unroll
            for(int i=0;i<4;i++) aa[i]=s2[(h0+i)*57+v];
            #pragma unroll
            for(int j=0;j<4;j++) vb[j]=s0[v*57+w0+j];
            #pragma unroll
            for(int i=0;i<4;i++)
                #pragma unroll
                for(int j=0;j<4;j++) outv[i][j]=fmaf(aa[i],vb[j],outv[i][j]);
        }
        #pragma unroll
        for(int i=0;i<4;i++)
            #pragma unroll
            for(int j=0;j<4;j++)
                f[base+(h0+i)*HH+(w0+j)] = rn_tf32(outv[i][j]);   // feeds tf32 c1 GEMM
    }
}

__global__ void fill_bias_kernel(float* __restrict__ out, const float* __restrict__ bias)
{
    int idx=blockIdx.x*256+threadIdx.x;
    if(idx < BB*CC*OUTH*OUTH){
        int o=(idx/(OUTH*OUTH))%CC;
        out[idx]=bias[o];
    }
}

// ---------------- launch ----------------
extern "C" void kernel_launch(void* const* d_in, const int* in_sizes, int n_in,
                              void* d_out, int out_size)
{
    const float* x_s  =(const float*)d_in[0];
    const float* x_fq =(const float*)d_in[1];
    const float* x_mt =(const float*)d_in[2];
    const float* la_w1=(const float*)d_in[3];
    const float* la_b1=(const float*)d_in[4];
    const float* la_g1=(const float*)d_in[5];
    const float* la_be1=(const float*)d_in[6];
    const float* la_w2=(const float*)d_in[7];
    const float* la_b2=(const float*)d_in[8];
    const float* la_g2=(const float*)d_in[9];
    const float* la_be2=(const float*)d_in[10];
    const float* lk_w =(const float*)d_in[11];
    const float* lk_b =(const float*)d_in[12];
    const float* lv_w =(const float*)d_in[13];
    const float* ga_w1=(const float*)d_in[14];
    const float* ga_b1=(const float*)d_in[15];
    const float* ga_g1=(const float*)d_in[16];
    const float* ga_be1=(const float*)d_in[17];
    const float* ga_w2=(const float*)d_in[18];
    const float* ga_b2=(const float*)d_in[19];
    const float* ga_g2=(const float*)d_in[20];
    const float* ga_be2=(const float*)d_in[21];
    const float* gk_w =(const float*)d_in[22];
    const float* gk_b =(const float*)d_in[23];
    const float* gv_w =(const float*)d_in[24];
    const float* c11_w=(const float*)d_in[25];
    const float* c11_b=(const float*)d_in[26];
    const float* c1_w =(const float*)d_in[27];
    const float* c1_b =(const float*)d_in[28];
    float* out=(float*)d_out;

    float *t1,*lq,*lk,*lv,*gk,*gv,*fbuf,*xrs,*xrfq,*xbar,*gqs,*wr;
    cudaGetSymbolAddress((void**)&t1,  g_t1);
    cudaGetSymbolAddress((void**)&lq,  g_lq);
    cudaGetSymbolAddress((void**)&lk,  g_lk);
    cudaGetSymbolAddress((void**)&lv,  g_lv);
    cudaGetSymbolAddress((void**)&gk,  g_gk);
    cudaGetSymbolAddress((void**)&gv,  g_gv);
    cudaGetSymbolAddress((void**)&fbuf,g_f);
    cudaGetSymbolAddress((void**)&xrs, g_xrs);
    cudaGetSymbolAddress((void**)&xrfq,g_xrfq);
    cudaGetSymbolAddress((void**)&xbar,g_xbar);
    cudaGetSymbolAddress((void**)&gqs, g_gqs);
    cudaGetSymbolAddress((void**)&wr,  g_wr);

    float* wr_lk = wr;
    float* wr_lv = wr + 1*CC*CC;
    float* wr_gk = wr + 2*CC*CC;
    float* wr_gv = wr + 3*CC*CC;
    float* wr_c1 = wr + 4*CC*CC;
    float* wr_la2= wr + 5*CC*CC;              // 256x64
    float* wr_la1= wr + 5*CC*CC + CC*ICC;     // 64x256

    const int total_out = BB*CC*OUTH*OUTH;
    fill_bias_kernel<<<(total_out+255)/256, 256>>>(out, c1_b);

    mean_kernel<<<BB*CC, 256>>>(x_mt, xbar);
    gq_kernel<<<BB, 256>>>(xbar, c11_w, c11_b, ga_w1, ga_b1, ga_g1, ga_be1,
                           ga_w2, ga_b2, ga_g2, ga_be2, gqs);

    round_copy<<<CC*CC/256, 256>>>(lk_w, wr_lk, CC*CC);
    round_copy<<<CC*CC/256, 256>>>(lv_w, wr_lv, CC*CC);
    round_copy<<<CC*CC/256, 256>>>(gk_w, wr_gk, CC*CC);
    round_copy<<<CC*CC/256, 256>>>(gv_w, wr_gv, CC*CC);
    round_copy<<<CC*CC/256, 256>>>(c1_w, wr_c1, CC*CC);
    round_copy<<<CC*ICC/256, 256>>>(la_w2, wr_la2, CC*ICC);
    round_copy<<<CC*ICC/256, 256>>>(la_w1, wr_la1, CC*ICC);

    const int NX = BB*CC*PP;
    round_copy<<<(NX+255)/256, 256>>>(x_s,  xrs,  NX);
    round_copy<<<(NX+255)/256, 256>>>(x_fq, xrfq, NX);

    const int NB = (PP + 127)/128;   // 25 n-tiles
    {   // t1 = lrelu(bn(la_w1 @ x_s)), output rounded (BM=64)
        dim3 g(NB, 1, BB);
        mma_gemm<64, EPI_BNLR><<<g, 256>>>(wr_la1, xrs, t1, CC, ICC, la_b1, la_g1, la_be1);
    }
    {   dim3 g(NB, CC/128, BB);
        mma_gemm<128, EPI_BN  ><<<g, 256>>>(wr_la2, t1,   lq, ICC, CC, la_b2, la_g2, la_be2);
        mma_gemm<128, EPI_BIAS><<<g, 256>>>(wr_lk,  xrs,  lk, CC,  CC, lk_b, lk_b, lk_b);
        mma_gemm<128, EPI_NONE><<<g, 256>>>(wr_lv,  xrs,  lv, CC,  CC, lk_b, lk_b, lk_b);
        mma_gemm<128, EPI_BIAS><<<g, 256>>>(wr_gk,  xrfq, gk, CC,  CC, gk_b, gk_b, gk_b);
        mma_gemm<128, EPI_NONE><<<g, 256>>>(wr_gv,  xrfq, gv, CC,  CC, gk_b, gk_b, gk_b);
    }

    attn_kernel<<<BB*CC, 256>>>(lq, lk, lv, gk, gv, gqs, fbuf);

    {   dim3 g(NB, CC/128, BB);
        mma_gemm<128, EPI_PAD><<<g, 256>>>(wr_c1, fbuf, out, CC, CC, c1_b, c1_b, c1_b);
    }
}

// round 5
// speedup vs baseline: 1.6802x; 1.2310x over previous
#include <cuda_runtime.h>
#include <math.h>
#include <stdint.h>

#define BB   16
#define CC   256
#define ICC  64
#define HH   56
#define PP   (HH*HH)
#define OUTH 58
#define EPSV 1e-5f
#define SCALEV (1.0f/896.0f)

// ---------------- scratch ----------------
__device__ float g_t1 [BB*ICC*PP];
__device__ float g_lq [BB*CC*PP];
__device__ float g_lk [BB*CC*PP];
__device__ float g_lv [BB*CC*PP];
__device__ float g_gk [BB*CC*PP];
__device__ float g_gv [BB*CC*PP];
__device__ float g_f  [BB*CC*PP];
__device__ float g_xrs [BB*CC*PP];
__device__ float g_xrfq[BB*CC*PP];
__device__ float g_xbar[BB*CC];
__device__ float g_gqs [BB*CC];
__device__ float g_wr [5*CC*CC + 2*CC*ICC];

#define EPI_NONE 0
#define EPI_BIAS 1
#define EPI_BN   2
#define EPI_BNLR 3
#define EPI_PAD  4

__device__ __forceinline__ uint32_t smem_u32(const void* p){
    uint32_t a;
    asm("{ .reg .u64 t; cvta.to.shared.u64 t, %1; cvt.u32.u64 %0, t; }":"=r"(a):"l"(p));
    return a;
}
__device__ __forceinline__ float rn_tf32(float x){
    uint32_t u; asm("cvt.rna.tf32.f32 %0, %1;":"=r"(u):"f"(x));
    return __uint_as_float(u);
}
__device__ __forceinline__ void mma8(float c[4],
    uint32_t a0, uint32_t a1, uint32_t a2, uint32_t a3, uint32_t b0, uint32_t b1){
    asm volatile(
        "mma.sync.aligned.m16n8k8.row.col.f32.tf32.tf32.f32 "
        "{%0,%1,%2,%3}, {%4,%5,%6,%7}, {%8,%9}, {%0,%1,%2,%3};"
        : "+f"(c[0]),"+f"(c[1]),"+f"(c[2]),"+f"(c[3])
        : "r"(a0),"r"(a1),"r"(a2),"r"(a3),"r"(b0),"r"(b1));
}

// ================= tf32 tensor-core batched GEMM (pipelined) =================
// Y[b,m,p] = sum_k W[m,k] * X[b,k,p] (+epilogue). W,X pre-rounded tf32.
// 128 threads (4 warps). BM=128: warps 2Mx2N, warp tile 64x64 (MT=4,NT=8).
// BM=64: warps 1Mx4N, warp tile 64x32 (MT=4,NT=4). BN=128, BK=16.
template<int BM, int EPI>
__global__ __launch_bounds__(128)
void mma_gemm(const float* __restrict__ W, const float* __restrict__ X,
              float* __restrict__ Y, int K, int Mtot,
              const float* __restrict__ bias,
              const float* __restrict__ gamma,
              const float* __restrict__ beta)
{
    constexpr int BN = 128, BK = 16;
    constexpr int WM = (BM == 128) ? 2 : 1;     // warps along M
    constexpr int WN = 4 / WM;                  // warps along N
    constexpr int MT = 4;                       // 16-row tiles per warp (warp M = 64)
    constexpr int NT = BN / (WN * 8);           // 8-col tiles per warp
    constexpr int ASTR = 20;                    // As row pad (floats)
    constexpr int BSTR = 136;                   // Bs row pad (floats)
    constexpr int ASZ = BM * ASTR;
    constexpr int BSZ = BK * BSTR;

    __shared__ float sA[2 * ASZ];
    __shared__ float sB[2 * BSZ];

    const int tid = threadIdx.x, wid = tid >> 5, lane = tid & 31;
    const int gid = lane >> 2, tig = lane & 3;
    const int warpM = wid / WN, warpN = wid - warpM * WN;
    const int m0 = blockIdx.y * BM, n0 = blockIdx.x * BN, b = blockIdx.z;
    const float* Wt = W + (size_t)m0 * K;
    const float* Xb = X + (size_t)b * K * PP;

    const uint32_t sAb = smem_u32(sA);
    const uint32_t sBb = smem_u32(sB);

    float c[MT][NT][4];
    #pragma unroll
    for(int m=0;m<MT;m++)
        #pragma unroll
        for(int n=0;n<NT;n++)
            #pragma unroll
            for(int q=0;q<4;q++) c[m][n][q]=0.f;

    const int NK = K >> 4;

    auto load_tile = [&](int kt, int s){
        // A: BM rows x 16 k (4x 16B per row)
        #pragma unroll
        for(int i = tid; i < BM*4; i += 128){
            int m = i >> 2, k4 = (i & 3) << 2;
            uint32_t dst = sAb + (s*ASZ + m*ASTR + k4) * 4;
            asm volatile("cp.async.cg.shared.global [%0], [%1], 16;"
                :: "r"(dst), "l"(Wt + (size_t)m*K + kt*16 + k4));
        }
        // B: 16 k-rows x 128 cols (zero-fill past PP)
        #pragma unroll
        for(int i = tid; i < 512; i += 128){
            int kr = i >> 5, c4 = (i & 31) << 2;
            int p = n0 + c4;
            const float* src = (p < PP) ? (Xb + (size_t)(kt*16 + kr)*PP + p) : Xb;
            uint32_t sz = (p < PP) ? 16u : 0u;
            uint32_t dst = sBb + (s*BSZ + kr*BSTR + c4) * 4;
            asm volatile("cp.async.cg.shared.global [%0], [%1], 16, %2;"
                :: "r"(dst), "l"(src), "r"(sz));
        }
        asm volatile("cp.async.commit_group;" ::: "memory");
    };

    load_tile(0, 0);

    for(int kt = 0; kt < NK; kt++){
        const int s = kt & 1;
        if(kt + 1 < NK){
            load_tile(kt + 1, 1 - s);
            asm volatile("cp.async.wait_group 1;" ::: "memory");
        } else {
            asm volatile("cp.async.wait_group 0;" ::: "memory");
        }
        __syncthreads();

        const float* As = sA + s*ASZ;
        const float* Bs = sB + s*BSZ;
        #pragma unroll
        for(int kk = 0; kk < BK; kk += 8){
            uint32_t a[MT][4], bb[NT][2];
            #pragma unroll
            for(int m=0;m<MT;m++){
                int mr = warpM*64 + m*16;
                a[m][0]=__float_as_uint(As[(mr+gid  )*ASTR + kk+tig  ]);
                a[m][1]=__float_as_uint(As[(mr+gid+8)*ASTR + kk+tig  ]);
                a[m][2]=__float_as_uint(As[(mr+gid  )*ASTR + kk+tig+4]);
                a[m][3]=__float_as_uint(As[(mr+gid+8)*ASTR + kk+tig+4]);
            }
            #pragma unroll
            for(int n=0;n<NT;n++){
                int nc = warpN*(NT*8) + n*8;
                bb[n][0]=__float_as_uint(Bs[(kk+tig  )*BSTR + nc+gid]);
                bb[n][1]=__float_as_uint(Bs[(kk+tig+4)*BSTR + nc+gid]);
            }
            #pragma unroll
            for(int m=0;m<MT;m++)
                #pragma unroll
                for(int n=0;n<NT;n++)
                    mma8(c[m][n], a[m][0],a[m][1],a[m][2],a[m][3], bb[n][0],bb[n][1]);
        }
        __syncthreads();
    }

    // ---- epilogue ----
    const float rs = rsqrtf(1.0f + EPSV);
    #pragma unroll
    for(int m=0;m<MT;m++){
        #pragma unroll
        for(int half=0; half<2; half++){
            const int row = m0 + warpM*64 + m*16 + gid + half*8;
            float add0=0.f, sc=1.f, sh=0.f;
            if(EPI==EPI_BIAS || EPI==EPI_PAD) add0=bias[row];
            if(EPI==EPI_BN || EPI==EPI_BNLR){
                add0=bias[row]; sc=gamma[row]*rs; sh=beta[row];
            }
            #pragma unroll
            for(int n=0;n<NT;n++){
                const int p = n0 + warpN*(NT*8) + n*8 + 2*tig;
                if(p < PP){
                    float y0 = c[m][n][half*2+0];
                    float y1 = c[m][n][half*2+1];
                    if(EPI==EPI_BIAS){ y0+=add0; y1+=add0; }
                    if(EPI==EPI_BN){ y0=(y0+add0)*sc+sh; y1=(y1+add0)*sc+sh; }
                    if(EPI==EPI_BNLR){
                        y0=(y0+add0)*sc+sh; y0=(y0>=0.f)?y0:0.2f*y0; y0=rn_tf32(y0);
                        y1=(y1+add0)*sc+sh; y1=(y1>=0.f)?y1:0.2f*y1; y1=rn_tf32(y1);
                    }
                    if(EPI==EPI_PAD){
                        int h=p/HH, w=p-h*HH;
                        float* yb = Y + ((size_t)(b*CC+row)*OUTH)*OUTH;
                        yb[(h+1)*OUTH + w+1] = y0 + add0;
                        int p1=p+1, h1=p1/HH, w1=p1-h1*HH;
                        yb[(h1+1)*OUTH + w1+1] = y1 + add0;
                    } else {
                        float2 v; v.x=y0; v.y=y1;
                        *reinterpret_cast<float2*>(
                            Y + ((size_t)b*Mtot + row)*PP + p) = v;
                    }
                }
            }
        }
    }
}

// ---------------- tf32 round copies ----------------
__global__ void round_copy(const float* __restrict__ s, float* __restrict__ d, int n)
{
    int i=blockIdx.x*256+threadIdx.x;
    if(i<n) d[i]=rn_tf32(s[i]);
}
__global__ void round_copy4(const float* __restrict__ s, float* __restrict__ d, int n4)
{
    int i=blockIdx.x*256+threadIdx.x;
    if(i<n4){
        float4 v = reinterpret_cast<const float4*>(s)[i];
        v.x=rn_tf32(v.x); v.y=rn_tf32(v.y); v.z=rn_tf32(v.z); v.w=rn_tf32(v.w);
        reinterpret_cast<float4*>(d)[i]=v;
    }
}

// ---------------- per-(b,c) mean ----------------
__global__ void mean_kernel(const float* __restrict__ x, float* __restrict__ xbar)
{
    __shared__ float red[256];
    const int bc=blockIdx.x;
    const float* p = x + (size_t)bc*PP;
    float s=0.f;
    for(int i=threadIdx.x;i<PP;i+=256) s+=p[i];
    red[threadIdx.x]=s; __syncthreads();
    for(int o=128;o>0;o>>=1){ if(threadIdx.x<o) red[threadIdx.x]+=red[threadIdx.x+o]; __syncthreads(); }
    if(threadIdx.x==0) xbar[bc]=red[0]*(1.0f/PP);
}

// ---------------- global-branch query MLP ----------------
__global__ void gq_kernel(const float* __restrict__ xbar,
                          const float* __restrict__ c11_w, const float* __restrict__ c11_b,
                          const float* __restrict__ ga_w1, const float* __restrict__ ga_b1,
                          const float* __restrict__ ga_g1, const float* __restrict__ ga_be1,
                          const float* __restrict__ ga_w2, const float* __restrict__ ga_b2,
                          const float* __restrict__ ga_g2, const float* __restrict__ ga_be2,
                          float* __restrict__ gqs)
{
    __shared__ float xb[CC], pv[CC], tv[ICC];
    const int b=blockIdx.x, t=threadIdx.x;
    const float rs=rsqrtf(1.0f+EPSV);
    xb[t]=xbar[b*CC+t]; __syncthreads();
    { float d=0.f; const float* wr=c11_w+(size_t)t*CC;
      for(int c=0;c<CC;c++) d=fmaf(wr[c],xb[c],d);
      pv[t]=d+c11_b[t]; }
    __syncthreads();
    if(t<ICC){ float d=0.f; const float* wr=ga_w1+(size_t)t*CC;
      for(int c=0;c<CC;c++) d=fmaf(wr[c],pv[c],d);
      d=(d+ga_b1[t])*(ga_g1[t]*rs)+ga_be1[t];
      tv[t]=(d>=0.f)?d:0.2f*d; }
    __syncthreads();
    { float d=0.f; const float* wr=ga_w2+(size_t)t*ICC;
      for(int i=0;i<ICC;i++) d=fmaf(wr[i],tv[i],d);
      d=(d+ga_b2[t])*(ga_g2[t]*rs)+ga_be2[t];
      gqs[b*CC+t]=d*SCALEV; }
}

// ---------------- per-(b,c) attention ----------------
__global__ __launch_bounds__(256)
void attn_kernel(const float* __restrict__ lq, const float* __restrict__ lk,
                 const float* __restrict__ lv, const float* __restrict__ gk,
                 const float* __restrict__ gv, const float* __restrict__ gqs,
                 float* __restrict__ f)
{
    __shared__ float s0[HH*57];
    __shared__ float s1[HH*57];
    __shared__ float s2[HH*57];
    const int bc=blockIdx.x;
    const size_t base=(size_t)bc*PP;
    const int t=threadIdx.x;
    const int hg=t>>4, wg=t&15;
    const bool act=(hg<14)&&(wg<14);
    const int h0=hg*4, w0=wg*4;

    for(int idx=t; idx<PP; idx+=256){
        int h=idx/HH, w=idx-h*HH;
        s0[h*57+w]=lq[base+idx];
        s1[h*57+w]=lk[base+idx];
    }
    __syncthreads();
    if(act){
        float a[4][4];
        #pragma unroll
        for(int i=0;i<4;i++)
            #pragma unroll
            for(int j=0;j<4;j++) a[i][j]=0.f;
        for(int w=0;w<HH;w++){
            float qa[4],kb[4];
            #pragma unroll
            for(int i=0;i<4;i++) qa[i]=s0[(h0+i)*57+w];
            #pragma unroll
            for(int j=0;j<4;j++) kb[j]=s1[(w0+j)*57+w];
            #pragma unroll
            for(int i=0;i<4;i++)
                #pragma unroll
                for(int j=0;j<4;j++) a[i][j]=fmaf(qa[i],kb[j],a[i][j]);
        }
        #pragma unroll
        for(int i=0;i<4;i++)
            #pragma unroll
            for(int j=0;j<4;j++) s2[(h0+i)*57+(w0+j)]=a[i][j]*SCALEV;
    }
    __syncthreads();
    if(t<HH){
        float* r=s2+t*57;
        float m=-1e30f;
        for(int j=0;j<HH;j++) m=fmaxf(m,r[j]);
        float s=0.f;
        for(int j=0;j<HH;j++){ float e=__expf(r[j]-m); r[j]=e; s+=e; }
        float inv=1.f/s;
        for(int j=0;j<HH;j++) r[j]*=inv;
    }
    __syncthreads();
    for(int idx=t; idx<PP; idx+=256){
        int h=idx/HH, w=idx-h*HH;
        s0[h*57+w]=lv[base+idx];
        s1[h*57+w]=gk[base+idx];
    }
    __syncthreads();
    float outv[4][4];
    #pragma unroll
    for(int i=0;i<4;i++)
        #pragma unroll
        for(int j=0;j<4;j++) outv[i][j]=0.f;
    if(act){
        for(int v=0;v<HH;v++){
            float aa[4],vb[4];
            #pragma unroll
            for(int i=0;i<4;i++) aa[i]=s2[(h0+i)*57+v];
            #pragma unroll
            for(int j=0;j<4;j++) vb[j]=s0[v*57+w0+j];
            #pragma unroll
            for(int i=0;i<4;i++)
                #pragma unroll
                for(int j=0;j<4;j++) outv[i][j]=fmaf(aa[i],vb[j],outv[i][j]);
        }
    }
    __syncthreads();
    for(int idx=t; idx<PP; idx+=256){
        int h=idx/HH, w=idx-h*HH;
        s0[h*57+w]=gv[base+idx];
    }
    const float gq=gqs[bc];
    if(t<HH){
        const float* r1=s1+t*57;
        float* r2=s2+t*57;
        float m=-1e30f;
        for(int k=0;k<HH;k++) m=fmaxf(m,gq*r1[k]);
        float s=0.f;
        for(int k=0;k<HH;k++){ float e=__expf(gq*r1[k]-m); r2[k]=e; s+=e; }
        float inv=1.f/s;
        for(int k=0;k<HH;k++) r2[k]*=inv;
    }
    __syncthreads();
    if(act){
        for(int v=0;v<HH;v++){
            float aa[4],vb[4];
            #pragma unroll
            for(int i=0;i<4;i++) aa[i]=s2[(h0+i)*57+v];
            #pragma unroll
            for(int j=0;j<4;j++) vb[j]=s0[v*57+w0+j];
            #pragma unroll
            for(int i=0;i<4;i++)
                #pragma unroll
                for(int j=0;j<4;j++) outv[i][j]=fmaf(aa[i],vb[j],outv[i][j]);
        }
        #pragma unroll
        for(int i=0;i<4;i++)
            #pragma unroll
            for(int j=0;j<4;j++)
                f[base+(h0+i)*HH+(w0+j)] = rn_tf32(outv[i][j]);
    }
}

__global__ void fill_bias_kernel(float* __restrict__ out, const float* __restrict__ bias)
{
    int idx=blockIdx.x*256+threadIdx.x;
    if(idx < BB*CC*OUTH*OUTH){
        int o=(idx/(OUTH*OUTH))%CC;
        out[idx]=bias[o];
    }
}

// ---------------- launch ----------------
extern "C" void kernel_launch(void* const* d_in, const int* in_sizes, int n_in,
                              void* d_out, int out_size)
{
    const float* x_s  =(const float*)d_in[0];
    const float* x_fq =(const float*)d_in[1];
    const float* x_mt =(const float*)d_in[2];
    const float* la_w1=(const float*)d_in[3];
    const float* la_b1=(const float*)d_in[4];
    const float* la_g1=(const float*)d_in[5];
    const float* la_be1=(const float*)d_in[6];
    const float* la_w2=(const float*)d_in[7];
    const float* la_b2=(const float*)d_in[8];
    const float* la_g2=(const float*)d_in[9];
    const float* la_be2=(const float*)d_in[10];
    const float* lk_w =(const float*)d_in[11];
    const float* lk_b =(const float*)d_in[12];
    const float* lv_w =(const float*)d_in[13];
    const float* ga_w1=(const float*)d_in[14];
    const float* ga_b1=(const float*)d_in[15];
    const float* ga_g1=(const float*)d_in[16];
    const float* ga_be1=(const float*)d_in[17];
    const float* ga_w2=(const float*)d_in[18];
    const float* ga_b2=(const float*)d_in[19];
    const float* ga_g2=(const float*)d_in[20];
    const float* ga_be2=(const float*)d_in[21];
    const float* gk_w =(const float*)d_in[22];
    const float* gk_b =(const float*)d_in[23];
    const float* gv_w =(const float*)d_in[24];
    const float* c11_w=(const float*)d_in[25];
    const float* c11_b=(const float*)d_in[26];
    const float* c1_w =(const float*)d_in[27];
    const float* c1_b =(const float*)d_in[28];
    float* out=(float*)d_out;

    float *t1,*lq,*lk,*lv,*gk,*gv,*fbuf,*xrs,*xrfq,*xbar,*gqs,*wr;
    cudaGetSymbolAddress((void**)&t1,  g_t1);
    cudaGetSymbolAddress((void**)&lq,  g_lq);
    cudaGetSymbolAddress((void**)&lk,  g_lk);
    cudaGetSymbolAddress((void**)&lv,  g_lv);
    cudaGetSymbolAddress((void**)&gk,  g_gk);
    cudaGetSymbolAddress((void**)&gv,  g_gv);
    cudaGetSymbolAddress((void**)&fbuf,g_f);
    cudaGetSymbolAddress((void**)&xrs, g_xrs);
    cudaGetSymbolAddress((void**)&xrfq,g_xrfq);
    cudaGetSymbolAddress((void**)&xbar,g_xbar);
    cudaGetSymbolAddress((void**)&gqs, g_gqs);
    cudaGetSymbolAddress((void**)&wr,  g_wr);

    float* wr_lk = wr;
    float* wr_lv = wr + 1*CC*CC;
    float* wr_gk = wr + 2*CC*CC;
    float* wr_gv = wr + 3*CC*CC;
    float* wr_c1 = wr + 4*CC*CC;
    float* wr_la2= wr + 5*CC*CC;              // 256x64
    float* wr_la1= wr + 5*CC*CC + CC*ICC;     // 64x256

    const int total_out = BB*CC*OUTH*OUTH;
    fill_bias_kernel<<<(total_out+255)/256, 256>>>(out, c1_b);

    mean_kernel<<<BB*CC, 256>>>(x_mt, xbar);
    gq_kernel<<<BB, 256>>>(xbar, c11_w, c11_b, ga_w1, ga_b1, ga_g1, ga_be1,
                           ga_w2, ga_b2, ga_g2, ga_be2, gqs);

    round_copy<<<CC*CC/256, 256>>>(lk_w, wr_lk, CC*CC);
    round_copy<<<CC*CC/256, 256>>>(lv_w, wr_lv, CC*CC);
    round_copy<<<CC*CC/256, 256>>>(gk_w, wr_gk, CC*CC);
    round_copy<<<CC*CC/256, 256>>>(gv_w, wr_gv, CC*CC);
    round_copy<<<CC*CC/256, 256>>>(c1_w, wr_c1, CC*CC);
    round_copy<<<CC*ICC/256, 256>>>(la_w2, wr_la2, CC*ICC);
    round_copy<<<CC*ICC/256, 256>>>(la_w1, wr_la1, CC*ICC);

    const int NX4 = BB*CC*PP/4;
    round_copy4<<<(NX4+255)/256, 256>>>(x_s,  xrs,  NX4);
    round_copy4<<<(NX4+255)/256, 256>>>(x_fq, xrfq, NX4);

    const int NB = (PP + 127)/128;   // 25 n-tiles
    {   // t1 = lrelu(bn(la_w1 @ x_s)), output rounded (BM=64)
        dim3 g(NB, 1, BB);
        mma_gemm<64, EPI_BNLR><<<g, 128>>>(wr_la1, xrs, t1, CC, ICC, la_b1, la_g1, la_be1);
    }
    {   dim3 g(NB, CC/128, BB);
        mma_gemm<128, EPI_BN  ><<<g, 128>>>(wr_la2, t1,   lq, ICC, CC, la_b2, la_g2, la_be2);
        mma_gemm<128, EPI_BIAS><<<g, 128>>>(wr_lk,  xrs,  lk, CC,  CC, lk_b, lk_b, lk_b);
        mma_gemm<128, EPI_NONE><<<g, 128>>>(wr_lv,  xrs,  lv, CC,  CC, lk_b, lk_b, lk_b);
        mma_gemm<128, EPI_BIAS><<<g, 128>>>(wr_gk,  xrfq, gk, CC,  CC, gk_b, gk_b, gk_b);
        mma_gemm<128, EPI_NONE><<<g, 128>>>(wr_gv,  xrfq, gv, CC,  CC, gk_b, gk_b, gk_b);
    }

    attn_kernel<<<BB*CC, 256>>>(lq, lk, lv, gk, gv, gqs, fbuf);

    {   dim3 g(NB, CC/128, BB);
        mma_gemm<128, EPI_PAD><<<g, 128>>>(wr_c1, fbuf, out, CC, CC, c1_b, c1_b, c1_b);
    }
}

// round 6
// speedup vs baseline: 1.8180x; 1.0820x over previous
#include <cuda_runtime.h>
#include <math.h>
#include <stdint.h>

#define BB   16
#define CC   256
#define ICC  64
#define HH   56
#define PP   (HH*HH)
#define OUTH 58
#define EPSV 1e-5f
#define SCALEV (1.0f/896.0f)

// ---------------- scratch ----------------
__device__ float g_t1  [BB*ICC*PP];
__device__ float g_lq  [BB*CC*PP];
__device__ float g_kvs [BB*2*CC*PP];   // [b][512][PP]: rows 0-255 l_k, 256-511 l_v
__device__ float g_kvfq[BB*2*CC*PP];   // same for g_k / g_v
__device__ float g_f   [BB*CC*PP];
__device__ float g_xbar[BB*CC];
__device__ float g_gqs [BB*CC];
__device__ float g_wr  [5*CC*CC + 2*CC*ICC];   // 360448 floats
__device__ float g_sb  [1024];                 // stacked biases: [0:512) s-branch, [512:1024) fq

#define EPI_BIAS 1
#define EPI_BN   2
#define EPI_BNLR 3
#define EPI_PAD  4

__device__ __forceinline__ uint32_t smem_u32(const void* p){
    uint32_t a;
    asm("{ .reg .u64 t; cvta.to.shared.u64 t, %1; cvt.u32.u64 %0, t; }":"=r"(a):"l"(p));
    return a;
}
__device__ __forceinline__ float rn_tf32(float x){
    uint32_t u; asm("cvt.rna.tf32.f32 %0, %1;":"=r"(u):"f"(x));
    return __uint_as_float(u);
}
__device__ __forceinline__ uint32_t rn_tf32_u(uint32_t x){
    uint32_t u; asm("cvt.rna.tf32.f32 %0, %1;":"=r"(u):"f"(__uint_as_float(x)));
    return u;
}
__device__ __forceinline__ void mma8(float c[4],
    uint32_t a0, uint32_t a1, uint32_t a2, uint32_t a3, uint32_t b0, uint32_t b1){
    asm volatile(
        "mma.sync.aligned.m16n8k8.row.col.f32.tf32.tf32.f32 "
        "{%0,%1,%2,%3}, {%4,%5,%6,%7}, {%8,%9}, {%0,%1,%2,%3};"
        : "+f"(c[0]),"+f"(c[1]),"+f"(c[2]),"+f"(c[3])
        : "r"(a0),"r"(a1),"r"(a2),"r"(a3),"r"(b0),"r"(b1));
}

// ================= tf32 tensor-core batched GEMM (pipelined) =================
// Y[b,m,p] = sum_k W[m,k] * X[b,k,p] (+epilogue). W pre-rounded; B fragments
// rounded in-register when RB (so X can be raw fp32).
template<int BM, int EPI, bool RB>
__global__ __launch_bounds__(128)
void mma_gemm(const float* __restrict__ W, const float* __restrict__ X,
              float* __restrict__ Y, int K, int Mtot,
              const float* __restrict__ bias,
              const float* __restrict__ gamma,
              const float* __restrict__ beta)
{
    constexpr int BN = 128, BK = 16;
    constexpr int WM = (BM == 128) ? 2 : 1;
    constexpr int WN = 4 / WM;
    constexpr int MT = 4;
    constexpr int NT = BN / (WN * 8);
    constexpr int ASTR = 20;
    constexpr int BSTR = 136;
    constexpr int ASZ = BM * ASTR;
    constexpr int BSZ = BK * BSTR;

    __shared__ float sA[2 * ASZ];
    __shared__ float sB[2 * BSZ];

    const int tid = threadIdx.x, wid = tid >> 5, lane = tid & 31;
    const int gid = lane >> 2, tig = lane & 3;
    const int warpM = wid / WN, warpN = wid - warpM * WN;
    const int m0 = blockIdx.y * BM, n0 = blockIdx.x * BN, b = blockIdx.z;
    const float* Wt = W + (size_t)m0 * K;
    const float* Xb = X + (size_t)b * K * PP;

    const uint32_t sAb = smem_u32(sA);
    const uint32_t sBb = smem_u32(sB);

    float c[MT][NT][4];
    #pragma unroll
    for(int m=0;m<MT;m++)
        #pragma unroll
        for(int n=0;n<NT;n++)
            #pragma unroll
            for(int q=0;q<4;q++) c[m][n][q]=0.f;

    const int NK = K >> 4;

    auto load_tile = [&](int kt, int s){
        #pragma unroll
        for(int i = tid; i < BM*4; i += 128){
            int m = i >> 2, k4 = (i & 3) << 2;
            uint32_t dst = sAb + (s*ASZ + m*ASTR + k4) * 4;
            asm volatile("cp.async.cg.shared.global [%0], [%1], 16;"
                :: "r"(dst), "l"(Wt + (size_t)m*K + kt*16 + k4));
        }
        #pragma unroll
        for(int i = tid; i < 512; i += 128){
            int kr = i >> 5, c4 = (i & 31) << 2;
            int p = n0 + c4;
            const float* src = (p < PP) ? (Xb + (size_t)(kt*16 + kr)*PP + p) : Xb;
            uint32_t sz = (p < PP) ? 16u : 0u;
            uint32_t dst = sBb + (s*BSZ + kr*BSTR + c4) * 4;
            asm volatile("cp.async.cg.shared.global [%0], [%1], 16, %2;"
                :: "r"(dst), "l"(src), "r"(sz));
        }
        asm volatile("cp.async.commit_group;" ::: "memory");
    };

    load_tile(0, 0);

    for(int kt = 0; kt < NK; kt++){
        const int s = kt & 1;
        if(kt + 1 < NK){
            load_tile(kt + 1, 1 - s);
            asm volatile("cp.async.wait_group 1;" ::: "memory");
        } else {
            asm volatile("cp.async.wait_group 0;" ::: "memory");
        }
        __syncthreads();

        const float* As = sA + s*ASZ;
        const float* Bs = sB + s*BSZ;
        #pragma unroll
        for(int kk = 0; kk < BK; kk += 8){
            uint32_t a[MT][4], bb[NT][2];
            #pragma unroll
            for(int m=0;m<MT;m++){
                int mr = warpM*64 + m*16;
                a[m][0]=__float_as_uint(As[(mr+gid  )*ASTR + kk+tig  ]);
                a[m][1]=__float_as_uint(As[(mr+gid+8)*ASTR + kk+tig  ]);
                a[m][2]=__float_as_uint(As[(mr+gid  )*ASTR + kk+tig+4]);
                a[m][3]=__float_as_uint(As[(mr+gid+8)*ASTR + kk+tig+4]);
            }
            #pragma unroll
            for(int n=0;n<NT;n++){
                int nc = warpN*(NT*8) + n*8;
                bb[n][0]=__float_as_uint(Bs[(kk+tig  )*BSTR + nc+gid]);
                bb[n][1]=__float_as_uint(Bs[(kk+tig+4)*BSTR + nc+gid]);
                if(RB){
                    bb[n][0]=rn_tf32_u(bb[n][0]);
                    bb[n][1]=rn_tf32_u(bb[n][1]);
                }
            }
            #pragma unroll
            for(int m=0;m<MT;m++)
                #pragma unroll
                for(int n=0;n<NT;n++)
                    mma8(c[m][n], a[m][0],a[m][1],a[m][2],a[m][3], bb[n][0],bb[n][1]);
        }
        __syncthreads();
    }

    // ---- epilogue ----
    const float rs = rsqrtf(1.0f + EPSV);
    #pragma unroll
    for(int m=0;m<MT;m++){
        #pragma unroll
        for(int half=0; half<2; half++){
            const int row = m0 + warpM*64 + m*16 + gid + half*8;
            float add0=0.f, sc=1.f, sh=0.f;
            if(EPI==EPI_BIAS || EPI==EPI_PAD) add0=bias[row];
            if(EPI==EPI_BN || EPI==EPI_BNLR){
                add0=bias[row]; sc=gamma[row]*rs; sh=beta[row];
            }
            #pragma unroll
            for(int n=0;n<NT;n++){
                const int p = n0 + warpN*(NT*8) + n*8 + 2*tig;
                if(p < PP){
                    float y0 = c[m][n][half*2+0];
                    float y1 = c[m][n][half*2+1];
                    if(EPI==EPI_BIAS){ y0+=add0; y1+=add0; }
                    if(EPI==EPI_BN){ y0=(y0+add0)*sc+sh; y1=(y1+add0)*sc+sh; }
                    if(EPI==EPI_BNLR){
                        y0=(y0+add0)*sc+sh; y0=(y0>=0.f)?y0:0.2f*y0; y0=rn_tf32(y0);
                        y1=(y1+add0)*sc+sh; y1=(y1>=0.f)?y1:0.2f*y1; y1=rn_tf32(y1);
                    }
                    if(EPI==EPI_PAD){
                        int h=p/HH, w=p-h*HH;
                        float* yb = Y + ((size_t)(b*CC+row)*OUTH)*OUTH;
                        yb[(h+1)*OUTH + w+1] = y0 + add0;
                        int p1=p+1, h1=p1/HH, w1=p1-h1*HH;
                        yb[(h1+1)*OUTH + w1+1] = y1 + add0;
                    } else {
                        float2 v; v.x=y0; v.y=y1;
                        *reinterpret_cast<float2*>(
                            Y + ((size_t)b*Mtot + row)*PP + p) = v;
                    }
                }
            }
        }
    }
}

// ---------------- weight prep: round + stack, and stacked biases ----------------
// wr layout: [0:131072) kv_s (512x256), [131072:262144) kv_fq,
//            [262144:327680) c1, [327680:344064) la2, [344064:360448) la1
__global__ void prep_kernel(const float* __restrict__ lk_w, const float* __restrict__ lv_w,
                            const float* __restrict__ gk_w, const float* __restrict__ gv_w,
                            const float* __restrict__ c1_w, const float* __restrict__ la_w2,
                            const float* __restrict__ la_w1,
                            const float* __restrict__ lk_b, const float* __restrict__ gk_b,
                            float* __restrict__ wr, float* __restrict__ sb)
{
    const int i = blockIdx.x*256 + threadIdx.x;
    const int KV = 512*256;
    if(i < KV){
        wr[i]      = rn_tf32(i < 65536 ? lk_w[i] : lv_w[i-65536]);
        wr[KV + i] = rn_tf32(i < 65536 ? gk_w[i] : gv_w[i-65536]);
    } else if(i < KV + 65536){
        int j = i - KV;
        wr[2*KV + j] = rn_tf32(c1_w[j]);
    } else if(i < KV + 65536 + 16384){
        int j = i - KV - 65536;
        wr[2*KV + 65536 + j] = rn_tf32(la_w2[j]);
    } else if(i < KV + 65536 + 32768){
        int j = i - KV - 65536 - 16384;
        wr[2*KV + 65536 + 16384 + j] = rn_tf32(la_w1[j]);
    }
    if(i < 512){
        sb[i]       = (i < 256) ? lk_b[i] : 0.f;
        sb[512 + i] = (i < 256) ? gk_b[i] : 0.f;
    }
}

// ---------------- border fill (228 cells per (b,c)) ----------------
__global__ void border_fill_kernel(float* __restrict__ out, const float* __restrict__ bias)
{
    const int idx = blockIdx.x*256 + threadIdx.x;
    const int total = BB*CC*228;
    if(idx >= total) return;
    const int bc = idx / 228, j = idx - bc*228;
    int h, w;
    if(j < 58){ h = 0; w = j; }
    else if(j < 116){ h = 57; w = j - 58; }
    else { int j2 = j - 116; h = 1 + (j2 >> 1); w = (j2 & 1) * 57; }
    out[((size_t)bc*OUTH + h)*OUTH + w] = bias[bc & 255];
}

// ---------------- per-(b,c) mean ----------------
__global__ void mean_kernel(const float* __restrict__ x, float* __restrict__ xbar)
{
    __shared__ float red[256];
    const int bc=blockIdx.x;
    const float* p = x + (size_t)bc*PP;
    float s=0.f;
    for(int i=threadIdx.x;i<PP;i+=256) s+=p[i];
    red[threadIdx.x]=s; __syncthreads();
    for(int o=128;o>0;o>>=1){ if(threadIdx.x<o) red[threadIdx.x]+=red[threadIdx.x+o]; __syncthreads(); }
    if(threadIdx.x==0) xbar[bc]=red[0]*(1.0f/PP);
}

// ---------------- global-branch query MLP ----------------
__global__ void gq_kernel(const float* __restrict__ xbar,
                          const float* __restrict__ c11_w, const float* __restrict__ c11_b,
                          const float* __restrict__ ga_w1, const float* __restrict__ ga_b1,
                          const float* __restrict__ ga_g1, const float* __restrict__ ga_be1,
                          const float* __restrict__ ga_w2, const float* __restrict__ ga_b2,
                          const float* __restrict__ ga_g2, const float* __restrict__ ga_be2,
                          float* __restrict__ gqs)
{
    __shared__ float xb[CC], pv[CC], tv[ICC];
    const int b=blockIdx.x, t=threadIdx.x;
    const float rs=rsqrtf(1.0f+EPSV);
    xb[t]=xbar[b*CC+t]; __syncthreads();
    { float d=0.f; const float* wr=c11_w+(size_t)t*CC;
      for(int c=0;c<CC;c++) d=fmaf(wr[c],xb[c],d);
      pv[t]=d+c11_b[t]; }
    __syncthreads();
    if(t<ICC){ float d=0.f; const float* wr=ga_w1+(size_t)t*CC;
      for(int c=0;c<CC;c++) d=fmaf(wr[c],pv[c],d);
      d=(d+ga_b1[t])*(ga_g1[t]*rs)+ga_be1[t];
      tv[t]=(d>=0.f)?d:0.2f*d; }
    __syncthreads();
    { float d=0.f; const float* wr=ga_w2+(size_t)t*ICC;
      for(int i=0;i<ICC;i++) d=fmaf(wr[i],tv[i],d);
      d=(d+ga_b2[t])*(ga_g2[t]*rs)+ga_be2[t];
      gqs[b*CC+t]=d*SCALEV; }
}

// ---------------- per-(b,c) attention ----------------
__global__ __launch_bounds__(256)
void attn_kernel(const float* __restrict__ lq, const float* __restrict__ kvs,
                 const float* __restrict__ kvfq, const float* __restrict__ gqs,
                 float* __restrict__ f)
{
    __shared__ float s0[HH*57];
    __shared__ float s1[HH*57];
    __shared__ float s2[HH*57];
    const int bc=blockIdx.x;
    const int b = bc >> 8, ch = bc & 255;
    const size_t base_q = (size_t)bc*PP;
    const size_t base_k = ((size_t)(b*512 + ch))*PP;
    const size_t base_v = base_k + (size_t)256*PP;
    const int t=threadIdx.x;
    const int hg=t>>4, wg=t&15;
    const bool act=(hg<14)&&(wg<14);
    const int h0=hg*4, w0=wg*4;

    for(int idx=t; idx<PP; idx+=256){
        int h=idx/HH, w=idx-h*HH;
        s0[h*57+w]=lq[base_q+idx];
        s1[h*57+w]=kvs[base_k+idx];
    }
    __syncthreads();
    if(act){
        float a[4][4];
        #pragma unroll
        for(int i=0;i<4;i++)
            #pragma unroll
            for(int j=0;j<4;j++) a[i][j]=0.f;
        for(int w=0;w<HH;w++){
            float qa[4],kb[4];
            #pragma unroll
            for(int i=0;i<4;i++) qa[i]=s0[(h0+i)*57+w];
            #pragma unroll
            for(int j=0;j<4;j++) kb[j]=s1[(w0+j)*57+w];
            #pragma unroll
            for(int i=0;i<4;i++)
                #pragma unroll
                for(int j=0;j<4;j++) a[i][j]=fmaf(qa[i],kb[j],a[i][j]);
        }
        #pragma unroll
        for(int i=0;i<4;i++)
            #pragma unroll
            for(int j=0;j<4;j++) s2[(h0+i)*57+(w0+j)]=a[i][j]*SCALEV;
    }
    __syncthreads();
    if(t<HH){
        float* r=s2+t*57;
        float m=-1e30f;
        for(int j=0;j<HH;j++) m=fmaxf(m,r[j]);
        float s=0.f;
        for(int j=0;j<HH;j++){ float e=__expf(r[j]-m); r[j]=e; s+=e; }
        float inv=1.f/s;
        for(int j=0;j<HH;j++) r[j]*=inv;
    }
    __syncthreads();
    for(int idx=t; idx<PP; idx+=256){
        int h=idx/HH, w=idx-h*HH;
        s0[h*57+w]=kvs[base_v+idx];
        s1[h*57+w]=kvfq[base_k+idx];
    }
    __syncthreads();
    float outv[4][4];
    #pragma unroll
    for(int i=0;i<4;i++)
        #pragma unroll
        for(int j=0;j<4;j++) outv[i][j]=0.f;
    if(act){
        for(int v=0;v<HH;v++){
            float aa[4],vb[4];
            #pragma unroll
            for(int i=0;i<4;i++) aa[i]=s2[(h0+i)*57+v];
            #pragma unroll
            for(int j=0;j<4;j++) vb[j]=s0[v*57+w0+j];
            #pragma unroll
            for(int i=0;i<4;i++)
                #pragma unroll
                for(int j=0;j<4;j++) outv[i][j]=fmaf(aa[i],vb[j],outv[i][j]);
        }
    }
    __syncthreads();
    for(int idx=t; idx<PP; idx+=256){
        int h=idx/HH, w=idx-h*HH;
        s0[h*57+w]=kvfq[base_v+idx];
    }
    const float gq=gqs[bc];
    if(t<HH){
        const float* r1=s1+t*57;
        float* r2=s2+t*57;
        float m=-1e30f;
        for(int k=0;k<HH;k++) m=fmaxf(m,gq*r1[k]);
        float s=0.f;
        for(int k=0;k<HH;k++){ float e=__expf(gq*r1[k]-m); r2[k]=e; s+=e; }
        float inv=1.f/s;
        for(int k=0;k<HH;k++) r2[k]*=inv;
    }
    __syncthreads();
    if(act){
        for(int v=0;v<HH;v++){
            float aa[4],vb[4];
            #pragma unroll
            for(int i=0;i<4;i++) aa[i]=s2[(h0+i)*57+v];
            #pragma unroll
            for(int j=0;j<4;j++) vb[j]=s0[v*57+w0+j];
            #pragma unroll
            for(int i=0;i<4;i++)
                #pragma unroll
                for(int j=0;j<4;j++) outv[i][j]=fmaf(aa[i],vb[j],outv[i][j]);
        }
        #pragma unroll
        for(int i=0;i<4;i++)
            #pragma unroll
            for(int j=0;j<4;j++)
                f[base_q+(h0+i)*HH+(w0+j)] = rn_tf32(outv[i][j]);
    }
}

// ---------------- launch ----------------
extern "C" void kernel_launch(void* const* d_in, const int* in_sizes, int n_in,
                              void* d_out, int out_size)
{
    const float* x_s  =(const float*)d_in[0];
    const float* x_fq =(const float*)d_in[1];
    const float* x_mt =(const float*)d_in[2];
    const float* la_w1=(const float*)d_in[3];
    const float* la_b1=(const float*)d_in[4];
    const float* la_g1=(const float*)d_in[5];
    const float* la_be1=(const float*)d_in[6];
    const float* la_w2=(const float*)d_in[7];
    const float* la_b2=(const float*)d_in[8];
    const float* la_g2=(const float*)d_in[9];
    const float* la_be2=(const float*)d_in[10];
    const float* lk_w =(const float*)d_in[11];
    const float* lk_b =(const float*)d_in[12];
    const float* lv_w =(const float*)d_in[13];
    const float* ga_w1=(const float*)d_in[14];
    const float* ga_b1=(const float*)d_in[15];
    const float* ga_g1=(const float*)d_in[16];
    const float* ga_be1=(const float*)d_in[17];
    const float* ga_w2=(const float*)d_in[18];
    const float* ga_b2=(const float*)d_in[19];
    const float* ga_g2=(const float*)d_in[20];
    const float* ga_be2=(const float*)d_in[21];
    const float* gk_w =(const float*)d_in[22];
    const float* gk_b =(const float*)d_in[23];
    const float* gv_w =(const float*)d_in[24];
    const float* c11_w=(const float*)d_in[25];
    const float* c11_b=(const float*)d_in[26];
    const float* c1_w =(const float*)d_in[27];
    const float* c1_b =(const float*)d_in[28];
    float* out=(float*)d_out;

    float *t1,*lq,*kvs,*kvfq,*fbuf,*xbar,*gqs,*wr,*sb;
    cudaGetSymbolAddress((void**)&t1,  g_t1);
    cudaGetSymbolAddress((void**)&lq,  g_lq);
    cudaGetSymbolAddress((void**)&kvs, g_kvs);
    cudaGetSymbolAddress((void**)&kvfq,g_kvfq);
    cudaGetSymbolAddress((void**)&fbuf,g_f);
    cudaGetSymbolAddress((void**)&xbar,g_xbar);
    cudaGetSymbolAddress((void**)&gqs, g_gqs);
    cudaGetSymbolAddress((void**)&wr,  g_wr);
    cudaGetSymbolAddress((void**)&sb,  g_sb);

    const int KV = 512*256;
    float* wr_kvs  = wr;
    float* wr_kvfq = wr + KV;
    float* wr_c1   = wr + 2*KV;
    float* wr_la2  = wr + 2*KV + 65536;
    float* wr_la1  = wr + 2*KV + 65536 + 16384;

    // 1: border fill
    border_fill_kernel<<<(BB*CC*228 + 255)/256, 256>>>(out, c1_b);
    // 2: mean
    mean_kernel<<<BB*CC, 256>>>(x_mt, xbar);
    // 3: gq MLP
    gq_kernel<<<BB, 256>>>(xbar, c11_w, c11_b, ga_w1, ga_b1, ga_g1, ga_be1,
                           ga_w2, ga_b2, ga_g2, ga_be2, gqs);
    // 4: weight prep
    prep_kernel<<<(KV + 65536 + 32768 + 255)/256, 256>>>(
        lk_w, lv_w, gk_w, gv_w, c1_w, la_w2, la_w1, lk_b, gk_b, wr, sb);

    const int NB = (PP + 127)/128;   // 25 n-tiles
    // 5: t1 = lrelu(bn(la_w1 @ x_s)), rounded output
    {   dim3 g(NB, 1, BB);
        mma_gemm<64, EPI_BNLR, true><<<g, 128>>>(wr_la1, x_s, t1, CC, ICC, la_b1, la_g1, la_be1);
    }
    // 6: fused l_k/l_v   (ncu -s 5 captures this launch)
    {   dim3 g(NB, 4, BB);
        mma_gemm<128, EPI_BIAS, true><<<g, 128>>>(wr_kvs, x_s, kvs, CC, 512, sb, sb, sb);
    }
    // 7: fused g_k/g_v
    {   dim3 g(NB, 4, BB);
        mma_gemm<128, EPI_BIAS, true><<<g, 128>>>(wr_kvfq, x_fq, kvfq, CC, 512, sb+512, sb, sb);
    }
    // 8: l_q = bn(la_w2 @ t1)
    {   dim3 g(NB, CC/128, BB);
        mma_gemm<128, EPI_BN, false><<<g, 128>>>(wr_la2, t1, lq, ICC, CC, la_b2, la_g2, la_be2);
    }
    // 9: attention
    attn_kernel<<<BB*CC, 256>>>(lq, kvs, kvfq, gqs, fbuf);
    // 10: padded output conv
    {   dim3 g(NB, CC/128, BB);
        mma_gemm<128, EPI_PAD, false><<<g, 128>>>(wr_c1, fbuf, out, CC, CC, c1_b, c1_b, c1_b);
    }
}

// round 7
// speedup vs baseline: 1.9614x; 1.0789x over previous
#include <cuda_runtime.h>
#include <cuda_fp16.h>
#include <math.h>
#include <stdint.h>

#define BB   16
#define CC   256
#define ICC  64
#define HH   56
#define PP   (HH*HH)
#define OUTH 58
#define EPSV 1e-5f
#define SCALEV (1.0f/896.0f)

// ---------------- scratch ----------------
__device__ __half g_xsT [BB*PP*CC];    // x_s  transposed [b][p][c] half
__device__ __half g_xfqT[BB*PP*CC];    // x_fq transposed
__device__ __half g_t1T [BB*PP*ICC];   // t1   transposed [b][p][ic] half
__device__ float  g_lq  [BB*CC*PP];
__device__ float  g_kvs [BB*2*CC*PP];  // rows 0-255 l_k, 256-511 l_v
__device__ float  g_kvfq[BB*2*CC*PP];
__device__ float  g_f   [BB*CC*PP];
__device__ float  g_xbar[BB*CC];
__device__ float  g_gqs [BB*CC];
__device__ __half g_wh  [2*512*256 + 2*64*256];  // kv_s, kv_fq, la1, la2
__device__ float  g_wc1 [CC*CC];                 // c1 tf32-rounded
__device__ float  g_sb  [1024];

#define EPI_BIAS 1
#define EPI_BN   2
#define EPI_T1   3
#define EPI_PAD  4

__device__ __forceinline__ uint32_t smem_u32(const void* p){
    uint32_t a;
    asm("{ .reg .u64 t; cvta.to.shared.u64 t, %1; cvt.u32.u64 %0, t; }":"=r"(a):"l"(p));
    return a;
}
__device__ __forceinline__ float rn_tf32(float x){
    uint32_t u; asm("cvt.rna.tf32.f32 %0, %1;":"=r"(u):"f"(x));
    return __uint_as_float(u);
}
__device__ __forceinline__ void mma16(float c[4],
    uint32_t a0, uint32_t a1, uint32_t a2, uint32_t a3, uint32_t b0, uint32_t b1){
    asm volatile(
        "mma.sync.aligned.m16n8k16.row.col.f32.f16.f16.f32 "
        "{%0,%1,%2,%3}, {%4,%5,%6,%7}, {%8,%9}, {%0,%1,%2,%3};"
        : "+f"(c[0]),"+f"(c[1]),"+f"(c[2]),"+f"(c[3])
        : "r"(a0),"r"(a1),"r"(a2),"r"(a3),"r"(b0),"r"(b1));
}
__device__ __forceinline__ void mma8t(float c[4],
    uint32_t a0, uint32_t a1, uint32_t a2, uint32_t a3, uint32_t b0, uint32_t b1){
    asm volatile(
        "mma.sync.aligned.m16n8k8.row.col.f32.tf32.tf32.f32 "
        "{%0,%1,%2,%3}, {%4,%5,%6,%7}, {%8,%9}, {%0,%1,%2,%3};"
        : "+f"(c[0]),"+f"(c[1]),"+f"(c[2]),"+f"(c[3])
        : "r"(a0),"r"(a1),"r"(a2),"r"(a3),"r"(b0),"r"(b1));
}

// ================= fp16 tensor-core batched GEMM =================
// Y[b,m,p] = sum_k W[m,k]*X[b,p,k]  (B operand = XT, [p][k] half, k contiguous)
// 128 thr. BM=128: warps 2Mx2N (warp 64x64). BM=64: 1Mx4N (warp 64x32). BK=32.
template<int BM, int EPI>
__global__ __launch_bounds__(128)
void hgemm(const __half* __restrict__ W, const __half* __restrict__ XT,
           void* __restrict__ Yv, int K, int Mtot,
           const float* __restrict__ bias,
           const float* __restrict__ gamma,
           const float* __restrict__ beta)
{
    constexpr int BN = 128;
    constexpr int WM = (BM == 128) ? 2 : 1;
    constexpr int WN = 4 / WM;
    constexpr int MT = 4;
    constexpr int NT = BN / (WN * 8);
    constexpr int ASTR = 40;                // halfs per A row (32 + pad 8)
    constexpr int BSTR = 40;
    constexpr int ASZ = BM * ASTR;
    constexpr int BSZ = BN * BSTR;

    __shared__ __half smh[2*ASZ + 2*BSZ];
    __half* sA = smh;
    __half* sB = smh + 2*ASZ;

    const int tid = threadIdx.x, wid = tid >> 5, lane = tid & 31;
    const int gid = lane >> 2, tig = lane & 3;
    const int warpM = wid / WN, warpN = wid - warpM * WN;
    const int m0 = blockIdx.y * BM, n0 = blockIdx.x * BN, b = blockIdx.z;
    const __half* Wt = W + (size_t)m0 * K;
    const __half* XTb = XT + (size_t)b * PP * K;
    const uint32_t sAb = smem_u32(sA);
    const uint32_t sBb = smem_u32(sB);

    float c[MT][NT][4];
    #pragma unroll
    for(int m=0;m<MT;m++)
        #pragma unroll
        for(int n=0;n<NT;n++)
            #pragma unroll
            for(int q=0;q<4;q++) c[m][n][q]=0.f;

    const int NK = K >> 5;

    auto load_tile = [&](int kt, int s){
        #pragma unroll
        for(int i = tid; i < BM*4; i += 128){
            int m = i >> 2, k8 = (i & 3) << 3;
            uint32_t dst = sAb + (s*ASZ + m*ASTR + k8) * 2;
            asm volatile("cp.async.cg.shared.global [%0], [%1], 16;"
                :: "r"(dst), "l"(Wt + (size_t)m*K + kt*32 + k8));
        }
        #pragma unroll
        for(int i = tid; i < 512; i += 128){
            int n = i >> 2, k8 = (i & 3) << 3;
            int p = n0 + n;
            const __half* src = (p < PP) ? (XTb + (size_t)p*K + kt*32 + k8) : XTb;
            uint32_t sz = (p < PP) ? 16u : 0u;
            uint32_t dst = sBb + (s*BSZ + n*BSTR + k8) * 2;
            asm volatile("cp.async.cg.shared.global [%0], [%1], 16, %2;"
                :: "r"(dst), "l"(src), "r"(sz));
        }
        asm volatile("cp.async.commit_group;" ::: "memory");
    };

    load_tile(0, 0);

    for(int kt = 0; kt < NK; kt++){
        const int s = kt & 1;
        if(kt + 1 < NK){
            load_tile(kt + 1, 1 - s);
            asm volatile("cp.async.wait_group 1;" ::: "memory");
        } else {
            asm volatile("cp.async.wait_group 0;" ::: "memory");
        }
        __syncthreads();

        const __half* As = sA + s*ASZ;
        const __half* Bs = sB + s*BSZ;
        #pragma unroll
        for(int kk = 0; kk < 32; kk += 16){
            uint32_t a[MT][4], bb[NT][2];
            #pragma unroll
            for(int m=0;m<MT;m++){
                int mr = warpM*64 + m*16;
                const __half* r0 = As + (mr+gid  )*ASTR + kk + 2*tig;
                const __half* r1 = As + (mr+gid+8)*ASTR + kk + 2*tig;
                a[m][0]=*reinterpret_cast<const uint32_t*>(r0);
                a[m][1]=*reinterpret_cast<const uint32_t*>(r1);
                a[m][2]=*reinterpret_cast<const uint32_t*>(r0+8);
                a[m][3]=*reinterpret_cast<const uint32_t*>(r1+8);
            }
            #pragma unroll
            for(int n=0;n<NT;n++){
                int nc = warpN*(NT*8) + n*8;
                const __half* br = Bs + (nc+gid)*BSTR + kk + 2*tig;
                bb[n][0]=*reinterpret_cast<const uint32_t*>(br);
                bb[n][1]=*reinterpret_cast<const uint32_t*>(br+8);
            }
            #pragma unroll
            for(int m=0;m<MT;m++)
                #pragma unroll
                for(int n=0;n<NT;n++)
                    mma16(c[m][n], a[m][0],a[m][1],a[m][2],a[m][3], bb[n][0],bb[n][1]);
        }
        __syncthreads();
    }

    const float rs = rsqrtf(1.0f + EPSV);

    if(EPI == EPI_T1){
        // stage -> transposed half output [p][BM]
        __syncthreads();
        __half* stage = smh;
        constexpr int SST = BM + 8;      // halfs per stage row (row start 16B-aligned: 72*2=144)
        #pragma unroll
        for(int m=0;m<MT;m++){
            #pragma unroll
            for(int half_=0; half_<2; half_++){
                const int row = warpM*64 + m*16 + gid + half_*8;
                const int gr = m0 + row;
                float add0 = bias[gr], sc = gamma[gr]*rs, sh = beta[gr];
                #pragma unroll
                for(int n=0;n<NT;n++){
                    #pragma unroll
                    for(int q=0;q<2;q++){
                        int nl = warpN*(NT*8) + n*8 + 2*tig + q;
                        float y = (c[m][n][half_*2+q] + add0)*sc + sh;
                        y = (y>=0.f)? y : 0.2f*y;
                        stage[nl*SST + row] = __float2half(y);
                    }
                }
            }
        }
        __syncthreads();
        __half* Yh = (__half*)Yv;
        for(int r = tid; r < BN; r += 128){
            int p = n0 + r;
            if(p < PP){
                uint4* dst = reinterpret_cast<uint4*>(Yh + ((size_t)b*PP + p)*BM);
                const uint4* src = reinterpret_cast<const uint4*>(stage + r*SST);
                #pragma unroll
                for(int q=0;q<BM/8;q++) dst[q] = src[q];
            }
        }
        return;
    }

    float* Y = (float*)Yv;
    #pragma unroll
    for(int m=0;m<MT;m++){
        #pragma unroll
        for(int half_=0; half_<2; half_++){
            const int row = m0 + warpM*64 + m*16 + gid + half_*8;
            float add0=0.f, sc=1.f, sh=0.f;
            if(EPI==EPI_BIAS) add0=bias[row];
            if(EPI==EPI_BN){ add0=bias[row]; sc=gamma[row]*rs; sh=beta[row]; }
            #pragma unroll
            for(int n=0;n<NT;n++){
                const int p = n0 + warpN*(NT*8) + n*8 + 2*tig;
                if(p < PP){
                    float y0 = c[m][n][half_*2+0];
                    float y1 = c[m][n][half_*2+1];
                    if(EPI==EPI_BIAS){ y0+=add0; y1+=add0; }
                    if(EPI==EPI_BN){ y0=(y0+add0)*sc+sh; y1=(y1+add0)*sc+sh; }
                    float2 v; v.x=y0; v.y=y1;
                    *reinterpret_cast<float2*>(Y + ((size_t)b*Mtot + row)*PP + p) = v;
                }
            }
        }
    }
}

// ================= tf32 GEMM (c1 only, padded store) =================
__global__ __launch_bounds__(128)
void tgemm_pad(const float* __restrict__ W, const float* __restrict__ X,
               float* __restrict__ Y, const float* __restrict__ bias)
{
    constexpr int BM=128, BN=128, BK=16;
    constexpr int MT=4, NT=8;
    constexpr int ASTR=20, BSTR=136;
    constexpr int ASZ=BM*ASTR, BSZ=BK*BSTR;
    __shared__ float sA[2*ASZ];
    __shared__ float sB[2*BSZ];
    const int K = CC;
    const int tid=threadIdx.x, wid=tid>>5, lane=tid&31;
    const int gid=lane>>2, tig=lane&3;
    const int warpM=wid>>1, warpN=wid&1;
    const int m0=blockIdx.y*BM, n0=blockIdx.x*BN, b=blockIdx.z;
    const float* Wt = W + (size_t)m0*K;
    const float* Xb = X + (size_t)b*K*PP;
    const uint32_t sAb=smem_u32(sA), sBb=smem_u32(sB);

    float c[MT][NT][4];
    #pragma unroll
    for(int m=0;m<MT;m++)
        #pragma unroll
        for(int n=0;n<NT;n++)
            #pragma unroll
            for(int q=0;q<4;q++) c[m][n][q]=0.f;

    const int NK = K >> 4;
    auto load_tile = [&](int kt, int s){
        #pragma unroll
        for(int i=tid; i<BM*4; i+=128){
            int m=i>>2, k4=(i&3)<<2;
            uint32_t dst = sAb + (s*ASZ + m*ASTR + k4)*4;
            asm volatile("cp.async.cg.shared.global [%0], [%1], 16;"
                :: "r"(dst), "l"(Wt + (size_t)m*K + kt*16 + k4));
        }
        #pragma unroll
        for(int i=tid; i<512; i+=128){
            int kr=i>>5, c4=(i&31)<<2;
            int p=n0+c4;
            const float* src = (p<PP)? (Xb + (size_t)(kt*16+kr)*PP + p) : Xb;
            uint32_t sz = (p<PP)?16u:0u;
            uint32_t dst = sBb + (s*BSZ + kr*BSTR + c4)*4;
            asm volatile("cp.async.cg.shared.global [%0], [%1], 16, %2;"
                :: "r"(dst), "l"(src), "r"(sz));
        }
        asm volatile("cp.async.commit_group;" ::: "memory");
    };
    load_tile(0,0);
    for(int kt=0; kt<NK; kt++){
        const int s=kt&1;
        if(kt+1<NK){ load_tile(kt+1,1-s); asm volatile("cp.async.wait_group 1;":::"memory"); }
        else { asm volatile("cp.async.wait_group 0;":::"memory"); }
        __syncthreads();
        const float* As=sA+s*ASZ;
        const float* Bs=sB+s*BSZ;
        #pragma unroll
        for(int kk=0;kk<BK;kk+=8){
            uint32_t a[MT][4], bb[NT][2];
            #pragma unroll
            for(int m=0;m<MT;m++){
                int mr=warpM*64+m*16;
                a[m][0]=__float_as_uint(As[(mr+gid  )*ASTR + kk+tig  ]);
                a[m][1]=__float_as_uint(As[(mr+gid+8)*ASTR + kk+tig  ]);
                a[m][2]=__float_as_uint(As[(mr+gid  )*ASTR + kk+tig+4]);
                a[m][3]=__float_as_uint(As[(mr+gid+8)*ASTR + kk+tig+4]);
            }
            #pragma unroll
            for(int n=0;n<NT;n++){
                int nc=warpN*64+n*8;
                bb[n][0]=__float_as_uint(Bs[(kk+tig  )*BSTR + nc+gid]);
                bb[n][1]=__float_as_uint(Bs[(kk+tig+4)*BSTR + nc+gid]);
            }
            #pragma unroll
            for(int m=0;m<MT;m++)
                #pragma unroll
                for(int n=0;n<NT;n++)
                    mma8t(c[m][n], a[m][0],a[m][1],a[m][2],a[m][3], bb[n][0],bb[n][1]);
        }
        __syncthreads();
    }
    #pragma unroll
    for(int m=0;m<MT;m++){
        #pragma unroll
        for(int half_=0; half_<2; half_++){
            const int row = m0 + warpM*64 + m*16 + gid + half_*8;
            const float add0 = bias[row];
            #pragma unroll
            for(int n=0;n<NT;n++){
                const int p = n0 + warpN*64 + n*8 + 2*tig;
                if(p < PP){
                    float y0 = c[m][n][half_*2+0] + add0;
                    float y1 = c[m][n][half_*2+1] + add0;
                    int h=p/HH, w=p-h*HH;
                    float* yb = Y + ((size_t)(b*CC+row)*OUTH)*OUTH;
                    yb[(h+1)*OUTH + w+1] = y0;
                    int p1=p+1, h1=p1/HH, w1=p1-h1*HH;
                    yb[(h1+1)*OUTH + w1+1] = y1;
                }
            }
        }
    }
}

// ---------------- convert + transpose: [C][P] fp32 -> [P][C] half ----------------
__global__ void cvt_kernel(const float* __restrict__ X, __half* __restrict__ XT, int C)
{
    __shared__ float t[32][33];
    const int b=blockIdx.z, p0=blockIdx.x*32, c0=blockIdx.y*32;
    const int tx=threadIdx.x, ty=threadIdx.y;
    const float* Xb = X + (size_t)b*C*PP;
    __half* Tb = XT + (size_t)b*PP*C;
    #pragma unroll
    for(int i=0;i<4;i++)
        t[ty+8*i][tx] = Xb[(size_t)(c0+ty+8*i)*PP + p0 + tx];
    __syncthreads();
    #pragma unroll
    for(int i=0;i<4;i++)
        Tb[(size_t)(p0+ty+8*i)*C + c0 + tx] = __float2half(t[tx][ty+8*i]);
}

// ---------------- weight prep ----------------
// wh: [0:131072) kv_s, [131072:262144) kv_fq, [262144:278528) la1, [278528:294912) la2
__global__ void prep_kernel(const float* __restrict__ lk_w, const float* __restrict__ lv_w,
                            const float* __restrict__ gk_w, const float* __restrict__ gv_w,
                            const float* __restrict__ la_w1, const float* __restrict__ la_w2,
                            const float* __restrict__ c1_w,
                            const float* __restrict__ lk_b, const float* __restrict__ gk_b,
                            __half* __restrict__ wh, float* __restrict__ wc1,
                            float* __restrict__ sb)
{
    const int i = blockIdx.x*256 + threadIdx.x;
    if(i < 131072){
        wh[i]          = __float2half(i < 65536 ? lk_w[i] : lv_w[i-65536]);
        wh[131072 + i] = __float2half(i < 65536 ? gk_w[i] : gv_w[i-65536]);
    } else if(i < 147456){
        int j = i - 131072;
        wh[262144 + j] = __float2half(la_w1[j]);
        wh[278528 + j] = __float2half(la_w2[j]);
    }
    if(i < 65536) wc1[i] = rn_tf32(c1_w[i]);
    if(i < 512){
        sb[i]       = (i < 256) ? lk_b[i] : 0.f;
        sb[512 + i] = (i < 256) ? gk_b[i] : 0.f;
    }
}

// ---------------- border fill ----------------
__global__ void border_fill_kernel(float* __restrict__ out, const float* __restrict__ bias)
{
    const int idx = blockIdx.x*256 + threadIdx.x;
    const int total = BB*CC*228;
    if(idx >= total) return;
    const int bc = idx / 228, j = idx - bc*228;
    int h, w;
    if(j < 58){ h = 0; w = j; }
    else if(j < 116){ h = 57; w = j - 58; }
    else { int j2 = j - 116; h = 1 + (j2 >> 1); w = (j2 & 1) * 57; }
    out[((size_t)bc*OUTH + h)*OUTH + w] = bias[bc & 255];
}

// ---------------- per-(b,c) mean ----------------
__global__ void mean_kernel(const float* __restrict__ x, float* __restrict__ xbar)
{
    __shared__ float red[256];
    const int bc=blockIdx.x;
    const float* p = x + (size_t)bc*PP;
    float s=0.f;
    for(int i=threadIdx.x;i<PP;i+=256) s+=p[i];
    red[threadIdx.x]=s; __syncthreads();
    for(int o=128;o>0;o>>=1){ if(threadIdx.x<o) red[threadIdx.x]+=red[threadIdx.x+o]; __syncthreads(); }
    if(threadIdx.x==0) xbar[bc]=red[0]*(1.0f/PP);
}

// ---------------- global-branch query MLP ----------------
__global__ void gq_kernel(const float* __restrict__ xbar,
                          const float* __restrict__ c11_w, const float* __restrict__ c11_b,
                          const float* __restrict__ ga_w1, const float* __restrict__ ga_b1,
                          const float* __restrict__ ga_g1, const float* __restrict__ ga_be1,
                          const float* __restrict__ ga_w2, const float* __restrict__ ga_b2,
                          const float* __restrict__ ga_g2, const float* __restrict__ ga_be2,
                          float* __restrict__ gqs)
{
    __shared__ float xb[CC], pv[CC], tv[ICC];
    const int b=blockIdx.x, t=threadIdx.x;
    const float rs=rsqrtf(1.0f+EPSV);
    xb[t]=xbar[b*CC+t]; __syncthreads();
    { float d=0.f; const float* wr=c11_w+(size_t)t*CC;
      for(int c=0;c<CC;c++) d=fmaf(wr[c],xb[c],d);
      pv[t]=d+c11_b[t]; }
    __syncthreads();
    if(t<ICC){ float d=0.f; const float* wr=ga_w1+(size_t)t*CC;
      for(int c=0;c<CC;c++) d=fmaf(wr[c],pv[c],d);
      d=(d+ga_b1[t])*(ga_g1[t]*rs)+ga_be1[t];
      tv[t]=(d>=0.f)?d:0.2f*d; }
    __syncthreads();
    { float d=0.f; const float* wr=ga_w2+(size_t)t*ICC;
      for(int i=0;i<ICC;i++) d=fmaf(wr[i],tv[i],d);
      d=(d+ga_b2[t])*(ga_g2[t]*rs)+ga_be2[t];
      gqs[b*CC+t]=d*SCALEV; }
}

// ---------------- per-(b,c) attention ----------------
__global__ __launch_bounds__(256)
void attn_kernel(const float* __restrict__ lq, const float* __restrict__ kvs,
                 const float* __restrict__ kvfq, const float* __restrict__ gqs,
                 float* __restrict__ f)
{
    __shared__ float s0[HH*57];
    __shared__ float s1[HH*57];
    __shared__ float s2[HH*57];
    const int bc=blockIdx.x;
    const int b = bc >> 8, ch = bc & 255;
    const size_t base_q = (size_t)bc*PP;
    const size_t base_k = ((size_t)(b*512 + ch))*PP;
    const size_t base_v = base_k + (size_t)256*PP;
    const int t=threadIdx.x;
    const int hg=t>>4, wg=t&15;
    const bool act=(hg<14)&&(wg<14);
    const int h0=hg*4, w0=wg*4;

    for(int idx=t; idx<PP; idx+=256){
        int h=idx/HH, w=idx-h*HH;
        s0[h*57+w]=lq[base_q+idx];
        s1[h*57+w]=kvs[base_k+idx];
    }
    __syncthreads();
    if(act){
        float a[4][4];
        #pragma unroll
        for(int i=0;i<4;i++)
            #pragma unroll
            for(int j=0;j<4;j++) a[i][j]=0.f;
        for(int w=0;w<HH;w++){
            float qa[4],kb[4];
            #pragma unroll
            for(int i=0;i<4;i++) qa[i]=s0[(h0+i)*57+w];
            #pragma unroll
            for(int j=0;j<4;j++) kb[j]=s1[(w0+j)*57+w];
            #pragma unroll
            for(int i=0;i<4;i++)
                #pragma unroll
                for(int j=0;j<4;j++) a[i][j]=fmaf(qa[i],kb[j],a[i][j]);
        }
        #pragma unroll
        for(int i=0;i<4;i++)
            #pragma unroll
            for(int j=0;j<4;j++) s2[(h0+i)*57+(w0+j)]=a[i][j]*SCALEV;
    }
    __syncthreads();
    if(t<HH){
        float* r=s2+t*57;
        float m=-1e30f;
        for(int j=0;j<HH;j++) m=fmaxf(m,r[j]);
        float s=0.f;
        for(int j=0;j<HH;j++){ float e=__expf(r[j]-m); r[j]=e; s+=e; }
        float inv=1.f/s;
        for(int j=0;j<HH;j++) r[j]*=inv;
    }
    __syncthreads();
    for(int idx=t; idx<PP; idx+=256){
        int h=idx/HH, w=idx-h*HH;
        s0[h*57+w]=kvs[base_v+idx];
        s1[h*57+w]=kvfq[base_k+idx];
    }
    __syncthreads();
    float outv[4][4];
    #pragma unroll
    for(int i=0;i<4;i++)
        #pragma unroll
        for(int j=0;j<4;j++) outv[i][j]=0.f;
    if(act){
        for(int v=0;v<HH;v++){
            float aa[4],vb[4];
            #pragma unroll
            for(int i=0;i<4;i++) aa[i]=s2[(h0+i)*57+v];
            #pragma unroll
            for(int j=0;j<4;j++) vb[j]=s0[v*57+w0+j];
            #pragma unroll
            for(int i=0;i<4;i++)
                #pragma unroll
                for(int j=0;j<4;j++) outv[i][j]=fmaf(aa[i],vb[j],outv[i][j]);
        }
    }
    __syncthreads();
    for(int idx=t; idx<PP; idx+=256){
        int h=idx/HH, w=idx-h*HH;
        s0[h*57+w]=kvfq[base_v+idx];
    }
    const float gq=gqs[bc];
    if(t<HH){
        const float* r1=s1+t*57;
        float* r2=s2+t*57;
        float m=-1e30f;
        for(int k=0;k<HH;k++) m=fmaxf(m,gq*r1[k]);
        float s=0.f;
        for(int k=0;k<HH;k++){ float e=__expf(gq*r1[k]-m); r2[k]=e; s+=e; }
        float inv=1.f/s;
        for(int k=0;k<HH;k++) r2[k]*=inv;
    }
    __syncthreads();
    if(act){
        for(int v=0;v<HH;v++){
            float aa[4],vb[4];
            #pragma unroll
            for(int i=0;i<4;i++) aa[i]=s2[(h0+i)*57+v];
            #pragma unroll
            for(int j=0;j<4;j++) vb[j]=s0[v*57+w0+j];
            #pragma unroll
            for(int i=0;i<4;i++)
                #pragma unroll
                for(int j=0;j<4;j++) outv[i][j]=fmaf(aa[i],vb[j],outv[i][j]);
        }
        #pragma unroll
        for(int i=0;i<4;i++)
            #pragma unroll
            for(int j=0;j<4;j++)
                f[base_q+(h0+i)*HH+(w0+j)] = rn_tf32(outv[i][j]);
    }
}

// ---------------- launch ----------------
extern "C" void kernel_launch(void* const* d_in, const int* in_sizes, int n_in,
                              void* d_out, int out_size)
{
    const float* x_s  =(const float*)d_in[0];
    const float* x_fq =(const float*)d_in[1];
    const float* x_mt =(const float*)d_in[2];
    const float* la_w1=(const float*)d_in[3];
    const float* la_b1=(const float*)d_in[4];
    const float* la_g1=(const float*)d_in[5];
    const float* la_be1=(const float*)d_in[6];
    const float* la_w2=(const float*)d_in[7];
    const float* la_b2=(const float*)d_in[8];
    const float* la_g2=(const float*)d_in[9];
    const float* la_be2=(const float*)d_in[10];
    const float* lk_w =(const float*)d_in[11];
    const float* lk_b =(const float*)d_in[12];
    const float* lv_w =(const float*)d_in[13];
    const float* ga_w1=(const float*)d_in[14];
    const float* ga_b1=(const float*)d_in[15];
    const float* ga_g1=(const float*)d_in[16];
    const float* ga_be1=(const float*)d_in[17];
    const float* ga_w2=(const float*)d_in[18];
    const float* ga_b2=(const float*)d_in[19];
    const float* ga_g2=(const float*)d_in[20];
    const float* ga_be2=(const float*)d_in[21];
    const float* gk_w =(const float*)d_in[22];
    const float* gk_b =(const float*)d_in[23];
    const float* gv_w =(const float*)d_in[24];
    const float* c11_w=(const float*)d_in[25];
    const float* c11_b=(const float*)d_in[26];
    const float* c1_w =(const float*)d_in[27];
    const float* c1_b =(const float*)d_in[28];
    float* out=(float*)d_out;

    __half *xsT,*xfqT,*t1T,*wh;
    float *lq,*kvs,*kvfq,*fbuf,*xbar,*gqs,*wc1,*sb;
    cudaGetSymbolAddress((void**)&xsT, g_xsT);
    cudaGetSymbolAddress((void**)&xfqT,g_xfqT);
    cudaGetSymbolAddress((void**)&t1T, g_t1T);
    cudaGetSymbolAddress((void**)&lq,  g_lq);
    cudaGetSymbolAddress((void**)&kvs, g_kvs);
    cudaGetSymbolAddress((void**)&kvfq,g_kvfq);
    cudaGetSymbolAddress((void**)&fbuf,g_f);
    cudaGetSymbolAddress((void**)&xbar,g_xbar);
    cudaGetSymbolAddress((void**)&gqs, g_gqs);
    cudaGetSymbolAddress((void**)&wh,  g_wh);
    cudaGetSymbolAddress((void**)&wc1, g_wc1);
    cudaGetSymbolAddress((void**)&sb,  g_sb);

    __half* wh_kvs  = wh;
    __half* wh_kvfq = wh + 131072;
    __half* wh_la1  = wh + 262144;
    __half* wh_la2  = wh + 278528;

    const int NB = (PP + 127)/128;   // 25

    // 1: border fill
    border_fill_kernel<<<(BB*CC*228 + 255)/256, 256>>>(out, c1_b);
    // 2: mean
    mean_kernel<<<BB*CC, 256>>>(x_mt, xbar);
    // 3: gq MLP
    gq_kernel<<<BB, 256>>>(xbar, c11_w, c11_b, ga_w1, ga_b1, ga_g1, ga_be1,
                           ga_w2, ga_b2, ga_g2, ga_be2, gqs);
    // 4: weight prep
    prep_kernel<<<(147456 + 255)/256, 256>>>(lk_w, lv_w, gk_w, gv_w,
                                             la_w1, la_w2, c1_w, lk_b, gk_b,
                                             wh, wc1, sb);
    // 5: convert+transpose x_s
    {   dim3 g(PP/32, CC/32, BB); dim3 blk(32,8);
        cvt_kernel<<<g, blk>>>(x_s, xsT, CC);
    }
    // 6: fused l_k/l_v (fp16)  <-- ncu -s 5 captures this
    {   dim3 g(NB, 4, BB);
        hgemm<128, EPI_BIAS><<<g, 128>>>(wh_kvs, xsT, kvs, CC, 512, sb, sb, sb);
    }
    // 7: convert+transpose x_fq
    {   dim3 g(PP/32, CC/32, BB); dim3 blk(32,8);
        cvt_kernel<<<g, blk>>>(x_fq, xfqT, CC);
    }
    // 8: fused g_k/g_v (fp16)
    {   dim3 g(NB, 4, BB);
        hgemm<128, EPI_BIAS><<<g, 128>>>(wh_kvfq, xfqT, kvfq, CC, 512, sb+512, sb, sb);
    }
    // 9: t1 = lrelu(bn(la_w1 @ x_s)) -> half transposed [p][64]
    {   dim3 g(NB, 1, BB);
        hgemm<64, EPI_T1><<<g, 128>>>(wh_la1, xsT, t1T, CC, ICC, la_b1, la_g1, la_be1);
    }
    // 10: l_q = bn(la_w2 @ t1) (fp16, K=64)
    {   dim3 g(NB, CC/128, BB);
        hgemm<128, EPI_BN><<<g, 128>>>(wh_la2, t1T, lq, ICC, CC, la_b2, la_g2, la_be2);
    }
    // 11: attention
    attn_kernel<<<BB*CC, 256>>>(lq, kvs, kvfq, gqs, fbuf);
    // 12: padded output conv (tf32)
    {   dim3 g(NB, CC/128, BB);
        tgemm_pad<<<g, 128>>>(wc1, fbuf, out, c1_b);
    }
}

// round 8
// speedup vs baseline: 3.0409x; 1.5504x over previous
#include <cuda_runtime.h>
#include <cuda_fp16.h>
#include <math.h>
#include <stdint.h>

#define BB   16
#define CC   256
#define ICC  64
#define HH   56
#define PP   (HH*HH)
#define OUTH 58
#define EPSV 1e-5f
#define SCALEV (1.0f/896.0f)

// ---------------- scratch (all half where possible) ----------------
__device__ __half g_xsT [BB*PP*CC];
__device__ __half g_xfqT[BB*PP*CC];
__device__ __half g_t1T [BB*PP*ICC];
__device__ __half g_lqh [BB*CC*PP];
__device__ __half g_kvs [BB*2*CC*PP];   // rows 0-255 l_k, 256-511 l_v
__device__ __half g_kvfq[BB*2*CC*PP];
__device__ __half g_fH  [BB*CC*PP];     // attn out [b][c][p]
__device__ __half g_fT  [BB*PP*CC];     // transposed [b][p][c]
__device__ float  g_xbar[BB*CC];
__device__ float  g_gqs [BB*CC];
__device__ __half g_wh  [2*512*256 + 2*64*256 + 256*256];
__device__ float  g_sb  [1024];

#define EPI_T1     3
#define EPI_PAD    4
#define EPI_BIAS_H 5
#define EPI_BN_H   6

__device__ __forceinline__ uint32_t smem_u32(const void* p){
    uint32_t a;
    asm("{ .reg .u64 t; cvta.to.shared.u64 t, %1; cvt.u32.u64 %0, t; }":"=r"(a):"l"(p));
    return a;
}
__device__ __forceinline__ void mma16(float c[4],
    uint32_t a0, uint32_t a1, uint32_t a2, uint32_t a3, uint32_t b0, uint32_t b1){
    asm volatile(
        "mma.sync.aligned.m16n8k16.row.col.f32.f16.f16.f32 "
        "{%0,%1,%2,%3}, {%4,%5,%6,%7}, {%8,%9}, {%0,%1,%2,%3};"
        : "+f"(c[0]),"+f"(c[1]),"+f"(c[2]),"+f"(c[3])
        : "r"(a0),"r"(a1),"r"(a2),"r"(a3),"r"(b0),"r"(b1));
}

// ================= fp16 tensor-core batched GEMM =================
// Y[b,m,p] = sum_k W[m,k]*XT[b,p,k] (+epilogue). XT: [p][k] half, k contiguous.
template<int BM, int EPI>
__global__ __launch_bounds__(128)
void hgemm(const __half* __restrict__ W, const __half* __restrict__ XT,
           void* __restrict__ Yv, int K, int Mtot,
           const float* __restrict__ bias,
           const float* __restrict__ gamma,
           const float* __restrict__ beta)
{
    constexpr int BN = 128;
    constexpr int WM = (BM == 128) ? 2 : 1;
    constexpr int WN = 4 / WM;
    constexpr int MT = 4;
    constexpr int NT = BN / (WN * 8);
    constexpr int ASTR = 40;
    constexpr int BSTR = 40;
    constexpr int ASZ = BM * ASTR;
    constexpr int BSZ = BN * BSTR;

    __shared__ __half smh[2*ASZ + 2*BSZ];
    __half* sA = smh;
    __half* sB = smh + 2*ASZ;

    const int tid = threadIdx.x, wid = tid >> 5, lane = tid & 31;
    const int gid = lane >> 2, tig = lane & 3;
    const int warpM = wid / WN, warpN = wid - warpM * WN;
    const int m0 = blockIdx.y * BM, n0 = blockIdx.x * BN, b = blockIdx.z;
    const __half* Wt = W + (size_t)m0 * K;
    const __half* XTb = XT + (size_t)b * PP * K;
    const uint32_t sAb = smem_u32(sA);
    const uint32_t sBb = smem_u32(sB);

    float c[MT][NT][4];
    #pragma unroll
    for(int m=0;m<MT;m++)
        #pragma unroll
        for(int n=0;n<NT;n++)
            #pragma unroll
            for(int q=0;q<4;q++) c[m][n][q]=0.f;

    const int NK = K >> 5;

    auto load_tile = [&](int kt, int s){
        #pragma unroll
        for(int i = tid; i < BM*4; i += 128){
            int m = i >> 2, k8 = (i & 3) << 3;
            uint32_t dst = sAb + (s*ASZ + m*ASTR + k8) * 2;
            asm volatile("cp.async.cg.shared.global [%0], [%1], 16;"
                :: "r"(dst), "l"(Wt + (size_t)m*K + kt*32 + k8));
        }
        #pragma unroll
        for(int i = tid; i < 512; i += 128){
            int n = i >> 2, k8 = (i & 3) << 3;
            int p = n0 + n;
            const __half* src = (p < PP) ? (XTb + (size_t)p*K + kt*32 + k8) : XTb;
            uint32_t sz = (p < PP) ? 16u : 0u;
            uint32_t dst = sBb + (s*BSZ + n*BSTR + k8) * 2;
            asm volatile("cp.async.cg.shared.global [%0], [%1], 16, %2;"
                :: "r"(dst), "l"(src), "r"(sz));
        }
        asm volatile("cp.async.commit_group;" ::: "memory");
    };

    load_tile(0, 0);

    for(int kt = 0; kt < NK; kt++){
        const int s = kt & 1;
        if(kt + 1 < NK){
            load_tile(kt + 1, 1 - s);
            asm volatile("cp.async.wait_group 1;" ::: "memory");
        } else {
            asm volatile("cp.async.wait_group 0;" ::: "memory");
        }
        __syncthreads();

        const __half* As = sA + s*ASZ;
        const __half* Bs = sB + s*BSZ;
        #pragma unroll
        for(int kk = 0; kk < 32; kk += 16){
            uint32_t a[MT][4], bb[NT][2];
            #pragma unroll
            for(int m=0;m<MT;m++){
                int mr = warpM*64 + m*16;
                const __half* r0 = As + (mr+gid  )*ASTR + kk + 2*tig;
                const __half* r1 = As + (mr+gid+8)*ASTR + kk + 2*tig;
                a[m][0]=*reinterpret_cast<const uint32_t*>(r0);
                a[m][1]=*reinterpret_cast<const uint32_t*>(r1);
                a[m][2]=*reinterpret_cast<const uint32_t*>(r0+8);
                a[m][3]=*reinterpret_cast<const uint32_t*>(r1+8);
            }
            #pragma unroll
            for(int n=0;n<NT;n++){
                int nc = warpN*(NT*8) + n*8;
                const __half* br = Bs + (nc+gid)*BSTR + kk + 2*tig;
                bb[n][0]=*reinterpret_cast<const uint32_t*>(br);
                bb[n][1]=*reinterpret_cast<const uint32_t*>(br+8);
            }
            #pragma unroll
            for(int m=0;m<MT;m++)
                #pragma unroll
                for(int n=0;n<NT;n++)
                    mma16(c[m][n], a[m][0],a[m][1],a[m][2],a[m][3], bb[n][0],bb[n][1]);
        }
        __syncthreads();
    }

    const float rs = rsqrtf(1.0f + EPSV);

    if(EPI == EPI_T1){
        __syncthreads();
        __half* stage = smh;
        constexpr int SST = BM + 8;
        #pragma unroll
        for(int m=0;m<MT;m++){
            #pragma unroll
            for(int half_=0; half_<2; half_++){
                const int row = warpM*64 + m*16 + gid + half_*8;
                const int gr = m0 + row;
                float add0 = bias[gr], sc = gamma[gr]*rs, sh = beta[gr];
                #pragma unroll
                for(int n=0;n<NT;n++){
                    #pragma unroll
                    for(int q=0;q<2;q++){
                        int nl = warpN*(NT*8) + n*8 + 2*tig + q;
                        float y = (c[m][n][half_*2+q] + add0)*sc + sh;
                        y = (y>=0.f)? y : 0.2f*y;
                        stage[nl*SST + row] = __float2half(y);
                    }
                }
            }
        }
        __syncthreads();
        __half* Yh = (__half*)Yv;
        for(int r = tid; r < BN; r += 128){
            int p = n0 + r;
            if(p < PP){
                uint4* dst = reinterpret_cast<uint4*>(Yh + ((size_t)b*PP + p)*BM);
                const uint4* src = reinterpret_cast<const uint4*>(stage + r*SST);
                #pragma unroll
                for(int q=0;q<BM/8;q++) dst[q] = src[q];
            }
        }
        return;
    }

    #pragma unroll
    for(int m=0;m<MT;m++){
        #pragma unroll
        for(int half_=0; half_<2; half_++){
            const int row = m0 + warpM*64 + m*16 + gid + half_*8;
            float add0=0.f, sc=1.f, sh=0.f;
            if(EPI==EPI_BIAS_H || EPI==EPI_PAD) add0=bias[row];
            if(EPI==EPI_BN_H){ add0=bias[row]; sc=gamma[row]*rs; sh=beta[row]; }
            #pragma unroll
            for(int n=0;n<NT;n++){
                const int p = n0 + warpN*(NT*8) + n*8 + 2*tig;
                if(p < PP){
                    float y0 = c[m][n][half_*2+0];
                    float y1 = c[m][n][half_*2+1];
                    if(EPI==EPI_PAD){
                        float* Y = (float*)Yv;
                        y0 += add0; y1 += add0;
                        int h=p/HH, w=p-h*HH;
                        float* yb = Y + ((size_t)(b*CC+row)*OUTH)*OUTH;
                        yb[(h+1)*OUTH + w+1] = y0;
                        int p1=p+1, h1=p1/HH, w1=p1-h1*HH;
                        yb[(h1+1)*OUTH + w1+1] = y1;
                    } else {
                        if(EPI==EPI_BIAS_H){ y0+=add0; y1+=add0; }
                        if(EPI==EPI_BN_H){ y0=(y0+add0)*sc+sh; y1=(y1+add0)*sc+sh; }
                        __half* Yh = (__half*)Yv;
                        *reinterpret_cast<__half2*>(Yh + ((size_t)b*Mtot + row)*PP + p)
                            = __floats2half2_rn(y0, y1);
                    }
                }
            }
        }
    }
}

// ================= tensor-core attention =================
// Per (b,c): S=Q@K^T (fp16 mma), softmax (fp32 regs), O = P@V^T + GS@GV^T.
__global__ __launch_bounds__(128)
void attn_tc(const __half* __restrict__ lqh, const __half* __restrict__ kvsh,
             const __half* __restrict__ kvfqh, const float* __restrict__ gqs,
             __half* __restrict__ fH)
{
    constexpr int STR = 72;                   // halfs per smem row
    __shared__ __half sQ  [64*STR];           // later holds P
    __shared__ __half sK  [64*STR];
    __shared__ __half sVT [64*STR];
    __shared__ __half sGK [64*STR];           // later holds GS
    __shared__ __half sGVT[64*STR];

    const int bc = blockIdx.x;
    const int b = bc >> 8, ch = bc & 255;
    const size_t base_q = (size_t)bc * PP;
    const size_t base_k = ((size_t)(b*512 + ch)) * PP;
    const size_t base_v = base_k + (size_t)256 * PP;
    const int tid = threadIdx.x, wid = tid>>5, lane = tid&31;
    const int gid = lane>>2, tig = lane&3;

    const uint32_t* gQ  = (const uint32_t*)(lqh  + base_q);
    const uint32_t* gK  = (const uint32_t*)(kvsh + base_k);
    const uint32_t* gV  = (const uint32_t*)(kvsh + base_v);
    const uint32_t* gGK = (const uint32_t*)(kvfqh + base_k);
    const uint32_t* gGV = (const uint32_t*)(kvfqh + base_v);
    uint32_t* uQ  = (uint32_t*)sQ;
    uint32_t* uK  = (uint32_t*)sK;
    uint32_t* uGK = (uint32_t*)sGK;
    uint32_t* uVT = (uint32_t*)sVT;
    uint32_t* uGVT= (uint32_t*)sGVT;

    // row-layout loads (zero k-cols 56..63)
    for(int i = tid; i < 56*32; i += 128){
        int r = i >> 5, j = i & 31;
        uint32_t vq=0, vk=0, vg=0;
        if(j < 28){ int src = r*28 + j; vq = gQ[src]; vk = gK[src]; vg = gGK[src]; }
        int dst = r*36 + j;
        uQ[dst]=vq; uK[dst]=vk; uGK[dst]=vg;
    }
    // transposed loads V^T, GV^T
    for(int i = tid; i < 56*28; i += 128){
        int v = i/28, jw = i - v*28;
        uint32_t pv = gV[v*28+jw], pg = gGV[v*28+jw];
        __half2 hv = *reinterpret_cast<__half2*>(&pv);
        __half2 hg = *reinterpret_cast<__half2*>(&pg);
        sVT [(2*jw  )*STR + v] = __low2half(hv);
        sVT [(2*jw+1)*STR + v] = __high2half(hv);
        sGVT[(2*jw  )*STR + v] = __low2half(hg);
        sGVT[(2*jw+1)*STR + v] = __high2half(hg);
    }
    // zero k-cols 56..63 of VT/GVT (all 64 rows)
    for(int i = tid; i < 64*4; i += 128){
        int r = i>>2, j = i&3;
        uVT[r*36 + 28 + j] = 0; uGVT[r*36 + 28 + j] = 0;
    }
    __syncthreads();

    // ---- S = Q @ K^T ----
    float c[8][4];
    #pragma unroll
    for(int n=0;n<8;n++){ c[n][0]=0; c[n][1]=0; c[n][2]=0; c[n][3]=0; }
    const int m0 = wid*16;
    #pragma unroll
    for(int kk = 0; kk < 64; kk += 16){
        uint32_t a0,a1,a2,a3;
        const __half* r0 = sQ + (m0+gid)*STR + kk + 2*tig;
        const __half* r1 = r0 + 8*STR;
        a0=*(const uint32_t*)r0; a1=*(const uint32_t*)r1;
        a2=*(const uint32_t*)(r0+8); a3=*(const uint32_t*)(r1+8);
        #pragma unroll
        for(int n=0;n<8;n++){
            const __half* br = sK + (n*8+gid)*STR + kk + 2*tig;
            mma16(c[n], a0,a1,a2,a3,
                  *(const uint32_t*)br, *(const uint32_t*)(br+8));
        }
    }
    __syncthreads();   // sQ reads complete; reuse as P

    // ---- softmax (registers + quad shuffles), P -> sQ ----
    #pragma unroll
    for(int half_=0; half_<2; half_++){
        const int h2 = half_*2;
        float m = -1e30f;
        #pragma unroll
        for(int n=0;n<7;n++) m = fmaxf(m, fmaxf(c[n][h2], c[n][h2+1]));
        m = fmaxf(m, __shfl_xor_sync(0xffffffffu, m, 1));
        m = fmaxf(m, __shfl_xor_sync(0xffffffffu, m, 2));
        float s = 0.f;
        #pragma unroll
        for(int n=0;n<7;n++){
            float e0 = __expf((c[n][h2  ] - m)*SCALEV);
            float e1 = __expf((c[n][h2+1] - m)*SCALEV);
            c[n][h2]=e0; c[n][h2+1]=e1; s += e0+e1;
        }
        s += __shfl_xor_sync(0xffffffffu, s, 1);
        s += __shfl_xor_sync(0xffffffffu, s, 2);
        const float inv = 1.f/s;
        const int row = m0 + gid + half_*8;
        #pragma unroll
        for(int n=0;n<8;n++){
            __half2 hv = (n<7) ? __floats2half2_rn(c[n][h2]*inv, c[n][h2+1]*inv)
                               : __floats2half2_rn(0.f, 0.f);
            *reinterpret_cast<__half2*>(sQ + row*STR + n*8 + 2*tig) = hv;
        }
    }

    // ---- global scores in place: sGK row h -> softmax(gq*gk) ----
    if(tid < 56){
        const float gq = gqs[bc];
        __half* row = sGK + tid*STR;
        float m = -1e30f;
        for(int k=0;k<56;k++) m = fmaxf(m, gq*__half2float(row[k]));
        float s = 0.f;
        for(int k=0;k<56;k++){
            float e = __expf(gq*__half2float(row[k]) - m);
            row[k] = __float2half(e);
            s += e;
        }
        const float inv = 1.f/s;
        for(int k=0;k<56;k++)
            row[k] = __float2half(__half2float(row[k])*inv);
        uint32_t* ur = (uint32_t*)row;
        ur[28]=0; ur[29]=0; ur[30]=0; ur[31]=0;
    }
    __syncthreads();

    // ---- O = P@V^T + GS@GV^T ----
    #pragma unroll
    for(int n=0;n<8;n++){ c[n][0]=0; c[n][1]=0; c[n][2]=0; c[n][3]=0; }
    #pragma unroll
    for(int kk = 0; kk < 64; kk += 16){
        uint32_t a0,a1,a2,a3;
        const __half* r0 = sQ + (m0+gid)*STR + kk + 2*tig;
        const __half* r1 = r0 + 8*STR;
        a0=*(const uint32_t*)r0; a1=*(const uint32_t*)r1;
        a2=*(const uint32_t*)(r0+8); a3=*(const uint32_t*)(r1+8);
        #pragma unroll
        for(int n=0;n<8;n++){
            const __half* br = sVT + (n*8+gid)*STR + kk + 2*tig;
            mma16(c[n], a0,a1,a2,a3,
                  *(const uint32_t*)br, *(const uint32_t*)(br+8));
        }
    }
    #pragma unroll
    for(int kk = 0; kk < 64; kk += 16){
        uint32_t a0,a1,a2,a3;
        const __half* r0 = sGK + (m0+gid)*STR + kk + 2*tig;
        const __half* r1 = r0 + 8*STR;
        a0=*(const uint32_t*)r0; a1=*(const uint32_t*)r1;
        a2=*(const uint32_t*)(r0+8); a3=*(const uint32_t*)(r1+8);
        #pragma unroll
        for(int n=0;n<8;n++){
            const __half* br = sGVT + (n*8+gid)*STR + kk + 2*tig;
            mma16(c[n], a0,a1,a2,a3,
                  *(const uint32_t*)br, *(const uint32_t*)(br+8));
        }
    }

    // ---- write f [c][p] half ----
    #pragma unroll
    for(int half_=0; half_<2; half_++){
        const int row = m0 + gid + half_*8;
        if(row < 56){
            #pragma unroll
            for(int n=0;n<7;n++){
                *reinterpret_cast<__half2*>(fH + base_q + row*HH + n*8 + 2*tig)
                    = __floats2half2_rn(c[n][half_*2], c[n][half_*2+1]);
            }
        }
    }
}

// ---------------- transpose fH [b][c][p] -> fT [b][p][c] ----------------
__global__ void transpose_h(const __half* __restrict__ F, __half* __restrict__ FT)
{
    __shared__ __half tt[64][66];
    const int b = blockIdx.z, p0 = blockIdx.x*64, c0 = blockIdx.y*64;
    const int tid = threadIdx.x;
    for(int i = tid; i < 64*32; i += 256){
        int r = i>>5, j = i&31;
        uint32_t v = *reinterpret_cast<const uint32_t*>(
            F + ((size_t)b*CC + c0 + r)*PP + p0 + 2*j);
        __half2 h = *reinterpret_cast<__half2*>(&v);
        tt[2*j  ][r] = __low2half(h);
        tt[2*j+1][r] = __high2half(h);
    }
    __syncthreads();
    for(int i = tid; i < 64*32; i += 256){
        int r = i>>5, j = i&31;
        __half2 h = __halves2half2(tt[r][2*j], tt[r][2*j+1]);
        *reinterpret_cast<__half2*>(FT + ((size_t)b*PP + p0 + r)*CC + c0 + 2*j) = h;
    }
}

// ---------------- convert + transpose input: [C][P] fp32 -> [P][C] half ----------------
__global__ void cvt_kernel(const float* __restrict__ X, __half* __restrict__ XT, int C)
{
    __shared__ float t[32][33];
    const int b=blockIdx.z, p0=blockIdx.x*32, c0=blockIdx.y*32;
    const int tx=threadIdx.x, ty=threadIdx.y;
    const float* Xb = X + (size_t)b*C*PP;
    __half* Tb = XT + (size_t)b*PP*C;
    #pragma unroll
    for(int i=0;i<4;i++)
        t[ty+8*i][tx] = Xb[(size_t)(c0+ty+8*i)*PP + p0 + tx];
    __syncthreads();
    #pragma unroll
    for(int i=0;i<4;i++)
        Tb[(size_t)(p0+ty+8*i)*C + c0 + tx] = __float2half(t[tx][ty+8*i]);
}

// ---------------- weight prep ----------------
// wh: [0:131072) kv_s, [131072:262144) kv_fq, [262144:278528) la1,
//     [278528:294912) la2, [294912:360448) c1
__global__ void prep_kernel(const float* __restrict__ lk_w, const float* __restrict__ lv_w,
                            const float* __restrict__ gk_w, const float* __restrict__ gv_w,
                            const float* __restrict__ la_w1, const float* __restrict__ la_w2,
                            const float* __restrict__ c1_w,
                            const float* __restrict__ lk_b, const float* __restrict__ gk_b,
                            __half* __restrict__ wh, float* __restrict__ sb)
{
    const int i = blockIdx.x*256 + threadIdx.x;
    if(i < 131072){
        wh[i]          = __float2half(i < 65536 ? lk_w[i] : lv_w[i-65536]);
        wh[131072 + i] = __float2half(i < 65536 ? gk_w[i] : gv_w[i-65536]);
    } else if(i < 147456){
        int j = i - 131072;
        wh[262144 + j] = __float2half(la_w1[j]);
        wh[278528 + j] = __float2half(la_w2[j]);
    }
    if(i < 65536) wh[294912 + i] = __float2half(c1_w[i]);
    if(i < 512){
        sb[i]       = (i < 256) ? lk_b[i] : 0.f;
        sb[512 + i] = (i < 256) ? gk_b[i] : 0.f;
    }
}

// ---------------- border fill ----------------
__global__ void border_fill_kernel(float* __restrict__ out, const float* __restrict__ bias)
{
    const int idx = blockIdx.x*256 + threadIdx.x;
    const int total = BB*CC*228;
    if(idx >= total) return;
    const int bc = idx / 228, j = idx - bc*228;
    int h, w;
    if(j < 58){ h = 0; w = j; }
    else if(j < 116){ h = 57; w = j - 58; }
    else { int j2 = j - 116; h = 1 + (j2 >> 1); w = (j2 & 1) * 57; }
    out[((size_t)bc*OUTH + h)*OUTH + w] = bias[bc & 255];
}

// ---------------- per-(b,c) mean ----------------
__global__ void mean_kernel(const float* __restrict__ x, float* __restrict__ xbar)
{
    __shared__ float red[256];
    const int bc=blockIdx.x;
    const float* p = x + (size_t)bc*PP;
    float s=0.f;
    for(int i=threadIdx.x;i<PP;i+=256) s+=p[i];
    red[threadIdx.x]=s; __syncthreads();
    for(int o=128;o>0;o>>=1){ if(threadIdx.x<o) red[threadIdx.x]+=red[threadIdx.x+o]; __syncthreads(); }
    if(threadIdx.x==0) xbar[bc]=red[0]*(1.0f/PP);
}

// ---------------- global-branch query MLP ----------------
__global__ void gq_kernel(const float* __restrict__ xbar,
                          const float* __restrict__ c11_w, const float* __restrict__ c11_b,
                          const float* __restrict__ ga_w1, const float* __restrict__ ga_b1,
                          const float* __restrict__ ga_g1, const float* __restrict__ ga_be1,
                          const float* __restrict__ ga_w2, const float* __restrict__ ga_b2,
                          const float* __restrict__ ga_g2, const float* __restrict__ ga_be2,
                          float* __restrict__ gqs)
{
    __shared__ float xb[CC], pv[CC], tv[ICC];
    const int b=blockIdx.x, t=threadIdx.x;
    const float rs=rsqrtf(1.0f+EPSV);
    xb[t]=xbar[b*CC+t]; __syncthreads();
    { float d=0.f; const float* wr=c11_w+(size_t)t*CC;
      for(int c=0;c<CC;c++) d=fmaf(wr[c],xb[c],d);
      pv[t]=d+c11_b[t]; }
    __syncthreads();
    if(t<ICC){ float d=0.f; const float* wr=ga_w1+(size_t)t*CC;
      for(int c=0;c<CC;c++) d=fmaf(wr[c],pv[c],d);
      d=(d+ga_b1[t])*(ga_g1[t]*rs)+ga_be1[t];
      tv[t]=(d>=0.f)?d:0.2f*d; }
    __syncthreads();
    { float d=0.f; const float* wr=ga_w2+(size_t)t*ICC;
      for(int i=0;i<ICC;i++) d=fmaf(wr[i],tv[i],d);
      d=(d+ga_b2[t])*(ga_g2[t]*rs)+ga_be2[t];
      gqs[b*CC+t]=d*SCALEV; }
}

// ---------------- launch ----------------
extern "C" void kernel_launch(void* const* d_in, const int* in_sizes, int n_in,
                              void* d_out, int out_size)
{
    const float* x_s  =(const float*)d_in[0];
    const float* x_fq =(const float*)d_in[1];
    const float* x_mt =(const float*)d_in[2];
    const float* la_w1=(const float*)d_in[3];
    const float* la_b1=(const float*)d_in[4];
    const float* la_g1=(const float*)d_in[5];
    const float* la_be1=(const float*)d_in[6];
    const float* la_w2=(const float*)d_in[7];
    const float* la_b2=(const float*)d_in[8];
    const float* la_g2=(const float*)d_in[9];
    const float* la_be2=(const float*)d_in[10];
    const float* lk_w =(const float*)d_in[11];
    const float* lk_b =(const float*)d_in[12];
    const float* lv_w =(const float*)d_in[13];
    const float* ga_w1=(const float*)d_in[14];
    const float* ga_b1=(const float*)d_in[15];
    const float* ga_g1=(const float*)d_in[16];
    const float* ga_be1=(const float*)d_in[17];
    const float* ga_w2=(const float*)d_in[18];
    const float* ga_b2=(const float*)d_in[19];
    const float* ga_g2=(const float*)d_in[20];
    const float* ga_be2=(const float*)d_in[21];
    const float* gk_w =(const float*)d_in[22];
    const float* gk_b =(const float*)d_in[23];
    const float* gv_w =(const float*)d_in[24];
    const float* c11_w=(const float*)d_in[25];
    const float* c11_b=(const float*)d_in[26];
    const float* c1_w =(const float*)d_in[27];
    const float* c1_b =(const float*)d_in[28];
    float* out=(float*)d_out;

    __half *xsT,*xfqT,*t1T,*lqh,*kvs,*kvfq,*fH,*fT,*wh;
    float *xbar,*gqs,*sb;
    cudaGetSymbolAddress((void**)&xsT, g_xsT);
    cudaGetSymbolAddress((void**)&xfqT,g_xfqT);
    cudaGetSymbolAddress((void**)&t1T, g_t1T);
    cudaGetSymbolAddress((void**)&lqh, g_lqh);
    cudaGetSymbolAddress((void**)&kvs, g_kvs);
    cudaGetSymbolAddress((void**)&kvfq,g_kvfq);
    cudaGetSymbolAddress((void**)&fH,  g_fH);
    cudaGetSymbolAddress((void**)&fT,  g_fT);
    cudaGetSymbolAddress((void**)&xbar,g_xbar);
    cudaGetSymbolAddress((void**)&gqs, g_gqs);
    cudaGetSymbolAddress((void**)&wh,  g_wh);
    cudaGetSymbolAddress((void**)&sb,  g_sb);

    __half* wh_kvs  = wh;
    __half* wh_kvfq = wh + 131072;
    __half* wh_la1  = wh + 262144;
    __half* wh_la2  = wh + 278528;
    __half* wh_c1   = wh + 294912;

    const int NB = (PP + 127)/128;   // 25

    // 1: border fill
    border_fill_kernel<<<(BB*CC*228 + 255)/256, 256>>>(out, c1_b);
    // 2: mean
    mean_kernel<<<BB*CC, 256>>>(x_mt, xbar);
    // 3: gq MLP
    gq_kernel<<<BB, 256>>>(xbar, c11_w, c11_b, ga_w1, ga_b1, ga_g1, ga_be1,
                           ga_w2, ga_b2, ga_g2, ga_be2, gqs);
    // 4: weight prep
    prep_kernel<<<576, 256>>>(lk_w, lv_w, gk_w, gv_w, la_w1, la_w2, c1_w,
                              lk_b, gk_b, wh, sb);
    // 5: convert+transpose x_s
    {   dim3 g(PP/32, CC/32, BB); dim3 blk(32,8);
        cvt_kernel<<<g, blk>>>(x_s, xsT, CC);
    }
    // 6: fused l_k/l_v (half out)
    {   dim3 g(NB, 4, BB);
        hgemm<128, EPI_BIAS_H><<<g, 128>>>(wh_kvs, xsT, kvs, CC, 512, sb, sb, sb);
    }
    // 7: convert+transpose x_fq
    {   dim3 g(PP/32, CC/32, BB); dim3 blk(32,8);
        cvt_kernel<<<g, blk>>>(x_fq, xfqT, CC);
    }
    // 8: fused g_k/g_v
    {   dim3 g(NB, 4, BB);
        hgemm<128, EPI_BIAS_H><<<g, 128>>>(wh_kvfq, xfqT, kvfq, CC, 512, sb+512, sb, sb);
    }
    // 9: t1 -> half transposed [p][64]
    {   dim3 g(NB, 1, BB);
        hgemm<64, EPI_T1><<<g, 128>>>(wh_la1, xsT, t1T, CC, ICC, la_b1, la_g1, la_be1);
    }
    // 10: l_q (half out)
    {   dim3 g(NB, CC/128, BB);
        hgemm<128, EPI_BN_H><<<g, 128>>>(wh_la2, t1T, lqh, ICC, CC, la_b2, la_g2, la_be2);
    }
    // 11: tensor-core attention
    attn_tc<<<BB*CC, 128>>>(lqh, kvs, kvfq, gqs, fH);
    // 12: transpose f
    {   dim3 g(PP/64, CC/64, BB);
        transpose_h<<<g, 256>>>(fH, fT);
    }
    // 13: padded output conv (fp16)
    {   dim3 g(NB, CC/128, BB);
        hgemm<128, EPI_PAD><<<g, 128>>>(wh_c1, fT, out, CC, CC, c1_b, c1_b, c1_b);
    }
}

// round 9
// speedup vs baseline: 3.1146x; 1.0243x over previous
#include <cuda_runtime.h>
#include <cuda_fp16.h>
#include <math.h>
#include <stdint.h>

#define BB   16
#define CC   256
#define ICC  64
#define HH   56
#define PP   (HH*HH)
#define OUTH 58
#define EPSV 1e-5f
#define SCALEV (1.0f/896.0f)

// ---------------- scratch ----------------
__device__ __half g_xsT [BB*PP*CC];
__device__ __half g_xfqT[BB*PP*CC];
__device__ __half g_t1T [BB*PP*ICC];
__device__ __half g_lqh [BB*CC*PP];
__device__ __half g_kvs [BB*2*CC*PP];
__device__ __half g_kvfq[BB*2*CC*PP];
__device__ __half g_fH  [BB*CC*PP];
__device__ __half g_fT  [BB*PP*CC];
__device__ float  g_xbar[BB*CC];
__device__ float  g_gqs [BB*CC];
__device__ __half g_wh  [2*512*256 + 2*64*256 + 256*256];
__device__ float  g_sb  [1024];

#define EPI_T1     3
#define EPI_PAD    4
#define EPI_BIAS_H 5
#define EPI_BN_H   6

__device__ __forceinline__ uint32_t smem_u32(const void* p){
    uint32_t a;
    asm("{ .reg .u64 t; cvta.to.shared.u64 t, %1; cvt.u32.u64 %0, t; }":"=r"(a):"l"(p));
    return a;
}
__device__ __forceinline__ void mma16(float c[4],
    uint32_t a0, uint32_t a1, uint32_t a2, uint32_t a3, uint32_t b0, uint32_t b1){
    asm volatile(
        "mma.sync.aligned.m16n8k16.row.col.f32.f16.f16.f32 "
        "{%0,%1,%2,%3}, {%4,%5,%6,%7}, {%8,%9}, {%0,%1,%2,%3};"
        : "+f"(c[0]),"+f"(c[1]),"+f"(c[2]),"+f"(c[3])
        : "r"(a0),"r"(a1),"r"(a2),"r"(a3),"r"(b0),"r"(b1));
}
__device__ __forceinline__ void ldsm4(uint32_t& r0, uint32_t& r1, uint32_t& r2, uint32_t& r3,
                                      uint32_t addr){
    asm volatile("ldmatrix.sync.aligned.m8n8.x4.shared.b16 {%0,%1,%2,%3}, [%4];"
        : "=r"(r0),"=r"(r1),"=r"(r2),"=r"(r3) : "r"(addr));
}

// ================= fp16 tensor-core batched GEMM =================
// Y[b,m,p] = sum_k W[m,k]*XT[b,p,k] (+epilogue). XT: [p][k] half, k contiguous.
template<int BM, int EPI>
__global__ __launch_bounds__(128)
void hgemm(const __half* __restrict__ W, const __half* __restrict__ XT,
           void* __restrict__ Yv, int K, int Mtot,
           const float* __restrict__ bias,
           const float* __restrict__ gamma,
           const float* __restrict__ beta)
{
    constexpr int BN = 128;
    constexpr int WM = (BM == 128) ? 2 : 1;
    constexpr int WN = 4 / WM;
    constexpr int MT = 4;
    constexpr int NT = BN / (WN * 8);
    constexpr int ASTR = 40;
    constexpr int BSTR = 40;
    constexpr int ASZ = BM * ASTR;
    constexpr int BSZ = BN * BSTR;

    __shared__ __align__(16) __half smh[2*ASZ + 2*BSZ];
    __half* sA = smh;
    __half* sB = smh + 2*ASZ;

    const int tid = threadIdx.x, wid = tid >> 5, lane = tid & 31;
    const int gid = lane >> 2, tig = lane & 3;
    const int l8 = lane & 7, lb1 = (lane >> 3) & 1, lb2 = lane >> 4;
    const int warpM = wid / WN, warpN = wid - warpM * WN;
    const int m0 = blockIdx.y * BM, n0 = blockIdx.x * BN, b = blockIdx.z;
    const __half* Wt = W + (size_t)m0 * K;
    const __half* XTb = XT + (size_t)b * PP * K;
    const uint32_t sAb = smem_u32(sA);
    const uint32_t sBb = smem_u32(sB);

    float c[MT][NT][4];
    #pragma unroll
    for(int m=0;m<MT;m++)
        #pragma unroll
        for(int n=0;n<NT;n++)
            #pragma unroll
            for(int q=0;q<4;q++) c[m][n][q]=0.f;

    const int NK = K >> 5;

    auto load_tile = [&](int kt, int s){
        #pragma unroll
        for(int i = tid; i < BM*4; i += 128){
            int m = i >> 2, k8 = (i & 3) << 3;
            uint32_t dst = sAb + (s*ASZ + m*ASTR + k8) * 2;
            asm volatile("cp.async.cg.shared.global [%0], [%1], 16;"
                :: "r"(dst), "l"(Wt + (size_t)m*K + kt*32 + k8));
        }
        #pragma unroll
        for(int i = tid; i < 512; i += 128){
            int n = i >> 2, k8 = (i & 3) << 3;
            int p = n0 + n;
            const __half* src = (p < PP) ? (XTb + (size_t)p*K + kt*32 + k8) : XTb;
            uint32_t sz = (p < PP) ? 16u : 0u;
            uint32_t dst = sBb + (s*BSZ + n*BSTR + k8) * 2;
            asm volatile("cp.async.cg.shared.global [%0], [%1], 16, %2;"
                :: "r"(dst), "l"(src), "r"(sz));
        }
        asm volatile("cp.async.commit_group;" ::: "memory");
    };

    load_tile(0, 0);

    for(int kt = 0; kt < NK; kt++){
        const int s = kt & 1;
        if(kt + 1 < NK){
            load_tile(kt + 1, 1 - s);
            asm volatile("cp.async.wait_group 1;" ::: "memory");
        } else {
            asm volatile("cp.async.wait_group 0;" ::: "memory");
        }
        __syncthreads();

        const uint32_t aBase = sAb + s*ASZ*2;
        const uint32_t bBase = sBb + s*BSZ*2;
        #pragma unroll
        for(int kk = 0; kk < 32; kk += 16){
            uint32_t a[MT][4], bb[NT][2];
            #pragma unroll
            for(int m=0;m<MT;m++){
                int mr = warpM*64 + m*16;
                uint32_t addr = aBase + (uint32_t)(((mr + l8 + lb1*8)*ASTR + kk + lb2*8)*2);
                ldsm4(a[m][0],a[m][1],a[m][2],a[m][3], addr);
            }
            #pragma unroll
            for(int np=0; np<NT/2; np++){
                int nc = warpN*(NT*8) + np*16;
                uint32_t addr = bBase + (uint32_t)(((nc + l8 + lb2*8)*BSTR + kk + lb1*8)*2);
                ldsm4(bb[2*np][0], bb[2*np][1], bb[2*np+1][0], bb[2*np+1][1], addr);
            }
            #pragma unroll
            for(int m=0;m<MT;m++)
                #pragma unroll
                for(int n=0;n<NT;n++)
                    mma16(c[m][n], a[m][0],a[m][1],a[m][2],a[m][3], bb[n][0],bb[n][1]);
        }
        __syncthreads();
    }

    const float rs = rsqrtf(1.0f + EPSV);

    if(EPI == EPI_T1){
        __syncthreads();
        __half* stage = smh;
        constexpr int SST = BM + 8;
        #pragma unroll
        for(int m=0;m<MT;m++){
            #pragma unroll
            for(int half_=0; half_<2; half_++){
                const int row = warpM*64 + m*16 + gid + half_*8;
                const int gr = m0 + row;
                float add0 = bias[gr], sc = gamma[gr]*rs, sh = beta[gr];
                #pragma unroll
                for(int n=0;n<NT;n++){
                    #pragma unroll
                    for(int q=0;q<2;q++){
                        int nl = warpN*(NT*8) + n*8 + 2*tig + q;
                        float y = (c[m][n][half_*2+q] + add0)*sc + sh;
                        y = (y>=0.f)? y : 0.2f*y;
                        stage[nl*SST + row] = __float2half(y);
                    }
                }
            }
        }
        __syncthreads();
        __half* Yh = (__half*)Yv;
        for(int r = tid; r < BN; r += 128){
            int p = n0 + r;
            if(p < PP){
                uint4* dst = reinterpret_cast<uint4*>(Yh + ((size_t)b*PP + p)*BM);
                const uint4* src = reinterpret_cast<const uint4*>(stage + r*SST);
                #pragma unroll
                for(int q=0;q<BM/8;q++) dst[q] = src[q];
            }
        }
        return;
    }

    #pragma unroll
    for(int m=0;m<MT;m++){
        #pragma unroll
        for(int half_=0; half_<2; half_++){
            const int row = m0 + warpM*64 + m*16 + gid + half_*8;
            float add0=0.f, sc=1.f, sh=0.f;
            if(EPI==EPI_BIAS_H || EPI==EPI_PAD) add0=bias[row];
            if(EPI==EPI_BN_H){ add0=bias[row]; sc=gamma[row]*rs; sh=beta[row]; }
            #pragma unroll
            for(int n=0;n<NT;n++){
                const int p = n0 + warpN*(NT*8) + n*8 + 2*tig;
                if(p < PP){
                    float y0 = c[m][n][half_*2+0];
                    float y1 = c[m][n][half_*2+1];
                    if(EPI==EPI_PAD){
                        float* Y = (float*)Yv;
                        y0 += add0; y1 += add0;
                        int h=p/HH, w=p-h*HH;
                        float* yb = Y + ((size_t)(b*CC+row)*OUTH)*OUTH;
                        yb[(h+1)*OUTH + w+1] = y0;
                        int p1=p+1, h1=p1/HH, w1=p1-h1*HH;
                        yb[(h1+1)*OUTH + w1+1] = y1;
                    } else {
                        if(EPI==EPI_BIAS_H){ y0+=add0; y1+=add0; }
                        if(EPI==EPI_BN_H){ y0=(y0+add0)*sc+sh; y1=(y1+add0)*sc+sh; }
                        __half* Yh = (__half*)Yv;
                        *reinterpret_cast<__half2*>(Yh + ((size_t)b*Mtot + row)*PP + p)
                            = __floats2half2_rn(y0, y1);
                    }
                }
            }
        }
    }
}

// ================= tensor-core attention =================
__global__ __launch_bounds__(128)
void attn_tc(const __half* __restrict__ lqh, const __half* __restrict__ kvsh,
             const __half* __restrict__ kvfqh, const float* __restrict__ gqs,
             __half* __restrict__ fH)
{
    constexpr int STR = 72;
    __shared__ __align__(16) __half sQ  [64*STR];
    __shared__ __align__(16) __half sK  [64*STR];
    __shared__ __align__(16) __half sVT [64*STR];
    __shared__ __align__(16) __half sGK [64*STR];
    __shared__ __align__(16) __half sGVT[64*STR];

    const int bc = blockIdx.x;
    const int b = bc >> 8, ch = bc & 255;
    const size_t base_q = (size_t)bc * PP;
    const size_t base_k = ((size_t)(b*512 + ch)) * PP;
    const size_t base_v = base_k + (size_t)256 * PP;
    const int tid = threadIdx.x, wid = tid>>5, lane = tid&31;
    const int gid = lane>>2, tig = lane&3;
    const int l8 = lane&7, lb1 = (lane>>3)&1, lb2 = lane>>4;

    const uint32_t* gQ  = (const uint32_t*)(lqh  + base_q);
    const uint32_t* gK  = (const uint32_t*)(kvsh + base_k);
    const uint32_t* gV  = (const uint32_t*)(kvsh + base_v);
    const uint32_t* gGK = (const uint32_t*)(kvfqh + base_k);
    const uint32_t* gGV = (const uint32_t*)(kvfqh + base_v);
    uint32_t* uQ  = (uint32_t*)sQ;
    uint32_t* uK  = (uint32_t*)sK;
    uint32_t* uGK = (uint32_t*)sGK;
    uint32_t* uVT = (uint32_t*)sVT;
    uint32_t* uGVT= (uint32_t*)sGVT;

    for(int i = tid; i < 56*32; i += 128){
        int r = i >> 5, j = i & 31;
        uint32_t vq=0, vk=0, vg=0;
        if(j < 28){ int src = r*28 + j; vq = gQ[src]; vk = gK[src]; vg = gGK[src]; }
        int dst = r*36 + j;
        uQ[dst]=vq; uK[dst]=vk; uGK[dst]=vg;
    }
    for(int i = tid; i < 56*28; i += 128){
        int v = i/28, jw = i - v*28;
        uint32_t pv = gV[v*28+jw], pg = gGV[v*28+jw];
        __half2 hv = *reinterpret_cast<__half2*>(&pv);
        __half2 hg = *reinterpret_cast<__half2*>(&pg);
        sVT [(2*jw  )*STR + v] = __low2half(hv);
        sVT [(2*jw+1)*STR + v] = __high2half(hv);
        sGVT[(2*jw  )*STR + v] = __low2half(hg);
        sGVT[(2*jw+1)*STR + v] = __high2half(hg);
    }
    for(int i = tid; i < 64*4; i += 128){
        int r = i>>2, j = i&3;
        uVT[r*36 + 28 + j] = 0; uGVT[r*36 + 28 + j] = 0;
    }
    __syncthreads();

    const uint32_t qB = smem_u32(sQ), kB = smem_u32(sK), vB = smem_u32(sVT);
    const uint32_t gkB = smem_u32(sGK), gvB = smem_u32(sGVT);
    const int m0 = wid*16;
    const uint32_t aOff = (uint32_t)(((m0 + l8 + lb1*8)*STR)*2);
    const uint32_t bRow = (uint32_t)((l8 + lb2*8)*STR*2);

    // ---- S = Q @ K^T ----
    float c[8][4];
    #pragma unroll
    for(int n=0;n<8;n++){ c[n][0]=0; c[n][1]=0; c[n][2]=0; c[n][3]=0; }
    #pragma unroll
    for(int kk = 0; kk < 64; kk += 16){
        uint32_t a0,a1,a2,a3;
        ldsm4(a0,a1,a2,a3, qB + aOff + (kk + lb2*8)*2);
        uint32_t bb[8][2];
        #pragma unroll
        for(int np=0;np<4;np++){
            uint32_t addr = kB + bRow + (uint32_t)((np*16*STR + kk + lb1*8)*2);
            ldsm4(bb[2*np][0], bb[2*np][1], bb[2*np+1][0], bb[2*np+1][1], addr);
        }
        #pragma unroll
        for(int n=0;n<8;n++)
            mma16(c[n], a0,a1,a2,a3, bb[n][0], bb[n][1]);
    }
    __syncthreads();

    // ---- softmax (registers + quad shuffles), P -> sQ ----
    #pragma unroll
    for(int half_=0; half_<2; half_++){
        const int h2 = half_*2;
        float m = -1e30f;
        #pragma unroll
        for(int n=0;n<7;n++) m = fmaxf(m, fmaxf(c[n][h2], c[n][h2+1]));
        m = fmaxf(m, __shfl_xor_sync(0xffffffffu, m, 1));
        m = fmaxf(m, __shfl_xor_sync(0xffffffffu, m, 2));
        float s = 0.f;
        #pragma unroll
        for(int n=0;n<7;n++){
            float e0 = __expf((c[n][h2  ] - m)*SCALEV);
            float e1 = __expf((c[n][h2+1] - m)*SCALEV);
            c[n][h2]=e0; c[n][h2+1]=e1; s += e0+e1;
        }
        s += __shfl_xor_sync(0xffffffffu, s, 1);
        s += __shfl_xor_sync(0xffffffffu, s, 2);
        const float inv = 1.f/s;
        const int row = m0 + gid + half_*8;
        #pragma unroll
        for(int n=0;n<8;n++){
            __half2 hv = (n<7) ? __floats2half2_rn(c[n][h2]*inv, c[n][h2+1]*inv)
                               : __floats2half2_rn(0.f, 0.f);
            *reinterpret_cast<__half2*>(sQ + row*STR + n*8 + 2*tig) = hv;
        }
    }

    // ---- global scores: sGK row h -> softmax_k(gq*gk) ----
    if(tid < 56){
        const float gq = gqs[bc];
        __half* row = sGK + tid*STR;
        float m = -1e30f;
        for(int k=0;k<56;k++) m = fmaxf(m, gq*__half2float(row[k]));
        float s = 0.f;
        for(int k=0;k<56;k++){
            float e = __expf(gq*__half2float(row[k]) - m);
            row[k] = __float2half(e);
            s += e;
        }
        const float inv = 1.f/s;
        for(int k=0;k<56;k++)
            row[k] = __float2half(__half2float(row[k])*inv);
        uint32_t* ur = (uint32_t*)row;
        ur[28]=0; ur[29]=0; ur[30]=0; ur[31]=0;
    }
    __syncthreads();

    // ---- O = P@V^T + GS@GV^T ----
    #pragma unroll
    for(int n=0;n<8;n++){ c[n][0]=0; c[n][1]=0; c[n][2]=0; c[n][3]=0; }
    #pragma unroll
    for(int kk = 0; kk < 64; kk += 16){
        uint32_t a0,a1,a2,a3;
        ldsm4(a0,a1,a2,a3, qB + aOff + (kk + lb2*8)*2);
        uint32_t bb[8][2];
        #pragma unroll
        for(int np=0;np<4;np++){
            uint32_t addr = vB + bRow + (uint32_t)((np*16*STR + kk + lb1*8)*2);
            ldsm4(bb[2*np][0], bb[2*np][1], bb[2*np+1][0], bb[2*np+1][1], addr);
        }
        #pragma unroll
        for(int n=0;n<8;n++)
            mma16(c[n], a0,a1,a2,a3, bb[n][0], bb[n][1]);
    }
    #pragma unroll
    for(int kk = 0; kk < 64; kk += 16){
        uint32_t a0,a1,a2,a3;
        ldsm4(a0,a1,a2,a3, gkB + aOff + (kk + lb2*8)*2);
        uint32_t bb[8][2];
        #pragma unroll
        for(int np=0;np<4;np++){
            uint32_t addr = gvB + bRow + (uint32_t)((np*16*STR + kk + lb1*8)*2);
            ldsm4(bb[2*np][0], bb[2*np][1], bb[2*np+1][0], bb[2*np+1][1], addr);
        }
        #pragma unroll
        for(int n=0;n<8;n++)
            mma16(c[n], a0,a1,a2,a3, bb[n][0], bb[n][1]);
    }

    // ---- write f [c][p] half ----
    #pragma unroll
    for(int half_=0; half_<2; half_++){
        const int row = m0 + gid + half_*8;
        if(row < 56){
            #pragma unroll
            for(int n=0;n<7;n++){
                *reinterpret_cast<__half2*>(fH + base_q + row*HH + n*8 + 2*tig)
                    = __floats2half2_rn(c[n][half_*2], c[n][half_*2+1]);
            }
        }
    }
}

// ---------------- transpose fH [b][c][p] -> fT [b][p][c] ----------------
__global__ void transpose_h(const __half* __restrict__ F, __half* __restrict__ FT)
{
    __shared__ __half tt[64][66];
    const int b = blockIdx.z, p0 = blockIdx.x*64, c0 = blockIdx.y*64;
    const int tid = threadIdx.x;
    for(int i = tid; i < 64*32; i += 256){
        int r = i>>5, j = i&31;
        uint32_t v = *reinterpret_cast<const uint32_t*>(
            F + ((size_t)b*CC + c0 + r)*PP + p0 + 2*j);
        __half2 h = *reinterpret_cast<__half2*>(&v);
        tt[2*j  ][r] = __low2half(h);
        tt[2*j+1][r] = __high2half(h);
    }
    __syncthreads();
    for(int i = tid; i < 64*32; i += 256){
        int r = i>>5, j = i&31;
        __half2 h = __halves2half2(tt[r][2*j], tt[r][2*j+1]);
        *reinterpret_cast<__half2*>(FT + ((size_t)b*PP + p0 + r)*CC + c0 + 2*j) = h;
    }
}

// ---------------- convert + transpose input: [C][P] fp32 -> [P][C] half ----------------
__global__ void cvt_kernel(const float* __restrict__ X, __half* __restrict__ XT, int C)
{
    __shared__ float t[32][33];
    const int b=blockIdx.z, p0=blockIdx.x*32, c0=blockIdx.y*32;
    const int tx=threadIdx.x, ty=threadIdx.y;
    const float* Xb = X + (size_t)b*C*PP;
    __half* Tb = XT + (size_t)b*PP*C;
    #pragma unroll
    for(int i=0;i<4;i++)
        t[ty+8*i][tx] = Xb[(size_t)(c0+ty+8*i)*PP + p0 + tx];
    __syncthreads();
    #pragma unroll
    for(int i=0;i<4;i++)
        Tb[(size_t)(p0+ty+8*i)*C + c0 + tx] = __float2half(t[tx][ty+8*i]);
}

// ---------------- weight prep ----------------
__global__ void prep_kernel(const float* __restrict__ lk_w, const float* __restrict__ lv_w,
                            const float* __restrict__ gk_w, const float* __restrict__ gv_w,
                            const float* __restrict__ la_w1, const float* __restrict__ la_w2,
                            const float* __restrict__ c1_w,
                            const float* __restrict__ lk_b, const float* __restrict__ gk_b,
                            __half* __restrict__ wh, float* __restrict__ sb)
{
    const int i = blockIdx.x*256 + threadIdx.x;
    if(i < 131072){
        wh[i]          = __float2half(i < 65536 ? lk_w[i] : lv_w[i-65536]);
        wh[131072 + i] = __float2half(i < 65536 ? gk_w[i] : gv_w[i-65536]);
    } else if(i < 147456){
        int j = i - 131072;
        wh[262144 + j] = __float2half(la_w1[j]);
        wh[278528 + j] = __float2half(la_w2[j]);
    }
    if(i < 65536) wh[294912 + i] = __float2half(c1_w[i]);
    if(i < 512){
        sb[i]       = (i < 256) ? lk_b[i] : 0.f;
        sb[512 + i] = (i < 256) ? gk_b[i] : 0.f;
    }
}

// ---------------- border fill ----------------
__global__ void border_fill_kernel(float* __restrict__ out, const float* __restrict__ bias)
{
    const int idx = blockIdx.x*256 + threadIdx.x;
    const int total = BB*CC*228;
    if(idx >= total) return;
    const int bc = idx / 228, j = idx - bc*228;
    int h, w;
    if(j < 58){ h = 0; w = j; }
    else if(j < 116){ h = 57; w = j - 58; }
    else { int j2 = j - 116; h = 1 + (j2 >> 1); w = (j2 & 1) * 57; }
    out[((size_t)bc*OUTH + h)*OUTH + w] = bias[bc & 255];
}

// ---------------- per-(b,c) mean ----------------
__global__ void mean_kernel(const float* __restrict__ x, float* __restrict__ xbar)
{
    __shared__ float red[256];
    const int bc=blockIdx.x;
    const float* p = x + (size_t)bc*PP;
    float s=0.f;
    for(int i=threadIdx.x;i<PP;i+=256) s+=p[i];
    red[threadIdx.x]=s; __syncthreads();
    for(int o=128;o>0;o>>=1){ if(threadIdx.x<o) red[threadIdx.x]+=red[threadIdx.x+o]; __syncthreads(); }
    if(threadIdx.x==0) xbar[bc]=red[0]*(1.0f/PP);
}

// ---------------- global-branch query MLP ----------------
__global__ void gq_kernel(const float* __restrict__ xbar,
                          const float* __restrict__ c11_w, const float* __restrict__ c11_b,
                          const float* __restrict__ ga_w1, const float* __restrict__ ga_b1,
                          const float* __restrict__ ga_g1, const float* __restrict__ ga_be1,
                          const float* __restrict__ ga_w2, const float* __restrict__ ga_b2,
                          const float* __restrict__ ga_g2, const float* __restrict__ ga_be2,
                          float* __restrict__ gqs)
{
    __shared__ float xb[CC], pv[CC], tv[ICC];
    const int b=blockIdx.x, t=threadIdx.x;
    const float rs=rsqrtf(1.0f+EPSV);
    xb[t]=xbar[b*CC+t]; __syncthreads();
    { float d=0.f; const float* wr=c11_w+(size_t)t*CC;
      for(int c=0;c<CC;c++) d=fmaf(wr[c],xb[c],d);
      pv[t]=d+c11_b[t]; }
    __syncthreads();
    if(t<ICC){ float d=0.f; const float* wr=ga_w1+(size_t)t*CC;
      for(int c=0;c<CC;c++) d=fmaf(wr[c],pv[c],d);
      d=(d+ga_b1[t])*(ga_g1[t]*rs)+ga_be1[t];
      tv[t]=(d>=0.f)?d:0.2f*d; }
    __syncthreads();
    { float d=0.f; const float* wr=ga_w2+(size_t)t*ICC;
      for(int i=0;i<ICC;i++) d=fmaf(wr[i],tv[i],d);
      d=(d+ga_b2[t])*(ga_g2[t]*rs)+ga_be2[t];
      gqs[b*CC+t]=d*SCALEV; }
}

// ---------------- launch ----------------
extern "C" void kernel_launch(void* const* d_in, const int* in_sizes, int n_in,
                              void* d_out, int out_size)
{
    const float* x_s  =(const float*)d_in[0];
    const float* x_fq =(const float*)d_in[1];
    const float* x_mt =(const float*)d_in[2];
    const float* la_w1=(const float*)d_in[3];
    const float* la_b1=(const float*)d_in[4];
    const float* la_g1=(const float*)d_in[5];
    const float* la_be1=(const float*)d_in[6];
    const float* la_w2=(const float*)d_in[7];
    const float* la_b2=(const float*)d_in[8];
    const float* la_g2=(const float*)d_in[9];
    const float* la_be2=(const float*)d_in[10];
    const float* lk_w =(const float*)d_in[11];
    const float* lk_b =(const float*)d_in[12];
    const float* lv_w =(const float*)d_in[13];
    const float* ga_w1=(const float*)d_in[14];
    const float* ga_b1=(const float*)d_in[15];
    const float* ga_g1=(const float*)d_in[16];
    const float* ga_be1=(const float*)d_in[17];
    const float* ga_w2=(const float*)d_in[18];
    const float* ga_b2=(const float*)d_in[19];
    const float* ga_g2=(const float*)d_in[20];
    const float* ga_be2=(const float*)d_in[21];
    const float* gk_w =(const float*)d_in[22];
    const float* gk_b =(const float*)d_in[23];
    const float* gv_w =(const float*)d_in[24];
    const float* c11_w=(const float*)d_in[25];
    const float* c11_b=(const float*)d_in[26];
    const float* c1_w =(const float*)d_in[27];
    const float* c1_b =(const float*)d_in[28];
    float* out=(float*)d_out;

    __half *xsT,*xfqT,*t1T,*lqh,*kvs,*kvfq,*fH,*fT,*wh;
    float *xbar,*gqs,*sb;
    cudaGetSymbolAddress((void**)&xsT, g_xsT);
    cudaGetSymbolAddress((void**)&xfqT,g_xfqT);
    cudaGetSymbolAddress((void**)&t1T, g_t1T);
    cudaGetSymbolAddress((void**)&lqh, g_lqh);
    cudaGetSymbolAddress((void**)&kvs, g_kvs);
    cudaGetSymbolAddress((void**)&kvfq,g_kvfq);
    cudaGetSymbolAddress((void**)&fH,  g_fH);
    cudaGetSymbolAddress((void**)&fT,  g_fT);
    cudaGetSymbolAddress((void**)&xbar,g_xbar);
    cudaGetSymbolAddress((void**)&gqs, g_gqs);
    cudaGetSymbolAddress((void**)&wh,  g_wh);
    cudaGetSymbolAddress((void**)&sb,  g_sb);

    __half* wh_kvs  = wh;
    __half* wh_kvfq = wh + 131072;
    __half* wh_la1  = wh + 262144;
    __half* wh_la2  = wh + 278528;
    __half* wh_c1   = wh + 294912;

    const int NB = (PP + 127)/128;   // 25

    border_fill_kernel<<<(BB*CC*228 + 255)/256, 256>>>(out, c1_b);
    mean_kernel<<<BB*CC, 256>>>(x_mt, xbar);
    gq_kernel<<<BB, 256>>>(xbar, c11_w, c11_b, ga_w1, ga_b1, ga_g1, ga_be1,
                           ga_w2, ga_b2, ga_g2, ga_be2, gqs);
    prep_kernel<<<576, 256>>>(lk_w, lv_w, gk_w, gv_w, la_w1, la_w2, c1_w,
                              lk_b, gk_b, wh, sb);
    {   dim3 g(PP/32, CC/32, BB); dim3 blk(32,8);
        cvt_kernel<<<g, blk>>>(x_s, xsT, CC);
    }
    {   dim3 g(NB, 4, BB);
        hgemm<128, EPI_BIAS_H><<<g, 128>>>(wh_kvs, xsT, kvs, CC, 512, sb, sb, sb);
    }
    {   dim3 g(PP/32, CC/32, BB); dim3 blk(32,8);
        cvt_kernel<<<g, blk>>>(x_fq, xfqT, CC);
    }
    {   dim3 g(NB, 4, BB);
        hgemm<128, EPI_BIAS_H><<<g, 128>>>(wh_kvfq, xfqT, kvfq, CC, 512, sb+512, sb, sb);
    }
    {   dim3 g(NB, 1, BB);
        hgemm<64, EPI_T1><<<g, 128>>>(wh_la1, xsT, t1T, CC, ICC, la_b1, la_g1, la_be1);
    }
    {   dim3 g(NB, CC/128, BB);
        hgemm<128, EPI_BN_H><<<g, 128>>>(wh_la2, t1T, lqh, ICC, CC, la_b2, la_g2, la_be2);
    }
    attn_tc<<<BB*CC, 128>>>(lqh, kvs, kvfq, gqs, fH);
    {   dim3 g(PP/64, CC/64, BB);
        transpose_h<<<g, 256>>>(fH, fT);
    }
    {   dim3 g(NB, CC/128, BB);
        hgemm<128, EPI_PAD><<<g, 128>>>(wh_c1, fT, out, CC, CC, c1_b, c1_b, c1_b);
    }
}

// round 10
// speedup vs baseline: 3.3755x; 1.0837x over previous
#include <cuda_runtime.h>
#include <cuda_fp16.h>
#include <math.h>
#include <stdint.h>

#define BB   16
#define CC   256
#define ICC  64
#define HH   56
#define PP   (HH*HH)
#define OUTH 58
#define EPSV 1e-5f
#define SCALEV (1.0f/896.0f)

#define NXE (BB*CC*PP)      // elems per activation tensor

// ---------------- scratch ----------------
__device__ __half g_xH [2*NXE];            // [0]=x_s half, [1]=x_fq half  ([b][c][p])
__device__ __half g_t1H[BB*ICC*PP];        // t1 half [b][ic][p]
__device__ __half g_lqh[BB*CC*PP];
__device__ __half g_kv [2*BB*2*CC*PP];     // [which][b][512][p]
__device__ __half g_fH [BB*CC*PP];         // attn out [b][c][p]
__device__ float  g_xbar[BB*CC];
__device__ float  g_gqs [BB*CC];
__device__ __half g_wh  [2*512*256 + 2*64*256 + 256*256];
__device__ float  g_sb  [1024];

#define EPI_PAD    4
#define EPI_BIAS_H 5
#define EPI_BN_H   6
#define EPI_BNLR_H 7

__device__ __forceinline__ uint32_t smem_u32(const void* p){
    uint32_t a;
    asm("{ .reg .u64 t; cvta.to.shared.u64 t, %1; cvt.u32.u64 %0, t; }":"=r"(a):"l"(p));
    return a;
}
__device__ __forceinline__ void mma16(float c[4],
    uint32_t a0, uint32_t a1, uint32_t a2, uint32_t a3, uint32_t b0, uint32_t b1){
    asm volatile(
        "mma.sync.aligned.m16n8k16.row.col.f32.f16.f16.f32 "
        "{%0,%1,%2,%3}, {%4,%5,%6,%7}, {%8,%9}, {%0,%1,%2,%3};"
        : "+f"(c[0]),"+f"(c[1]),"+f"(c[2]),"+f"(c[3])
        : "r"(a0),"r"(a1),"r"(a2),"r"(a3),"r"(b0),"r"(b1));
}
__device__ __forceinline__ void ldsm4(uint32_t& r0, uint32_t& r1, uint32_t& r2, uint32_t& r3,
                                      uint32_t addr){
    asm volatile("ldmatrix.sync.aligned.m8n8.x4.shared.b16 {%0,%1,%2,%3}, [%4];"
        : "=r"(r0),"=r"(r1),"=r"(r2),"=r"(r3) : "r"(addr));
}
__device__ __forceinline__ void ldsm4t(uint32_t& r0, uint32_t& r1, uint32_t& r2, uint32_t& r3,
                                       uint32_t addr){
    asm volatile("ldmatrix.sync.aligned.m8n8.x4.trans.shared.b16 {%0,%1,%2,%3}, [%4];"
        : "=r"(r0),"=r"(r1),"=r"(r2),"=r"(r3) : "r"(addr));
}

// ================= fp16 tensor-core batched GEMM (trans-B path) =================
// Y[b,m,p] = sum_k W[m,k]*X[b,k,p] (+epilogue). X: half [b][K][PP] (k rows, p cols).
// Optional dual mode: gridDim.z = 2*BB, which = z/BB offsets W/X/Y/bias.
template<int BM, int EPI>
__global__ __launch_bounds__(128)
void hgemm(const __half* __restrict__ W, const __half* __restrict__ X,
           void* __restrict__ Yv, int K, int Mtot,
           const float* __restrict__ bias,
           const float* __restrict__ gamma,
           const float* __restrict__ beta,
           size_t wstride, size_t xstride, size_t ystride, int bstride)
{
    constexpr int BN = 128;
    constexpr int WM = (BM == 128) ? 2 : 1;
    constexpr int WN = 4 / WM;
    constexpr int MT = 4;
    constexpr int NT = BN / (WN * 8);
    constexpr int ASTR = 40;                 // A row: 32 k + pad
    constexpr int BSTR = 136;                // B row: 128 p + pad
    constexpr int ASZ = BM * ASTR;
    constexpr int BSZ = 32 * BSTR;

    __shared__ __align__(16) __half smh[2*ASZ + 2*BSZ];
    __half* sA = smh;
    __half* sB = smh + 2*ASZ;

    const int tid = threadIdx.x, wid = tid >> 5, lane = tid & 31;
    const int gid = lane >> 2, tig = lane & 3;
    const int l8 = lane & 7, lb1 = (lane >> 3) & 1, lb2 = lane >> 4;
    const int warpM = wid / WN, warpN = wid - warpM * WN;
    const int m0 = blockIdx.y * BM, n0 = blockIdx.x * BN;
    const int which = blockIdx.z / BB;
    const int b = blockIdx.z - which * BB;

    const __half* Wt = W + which*wstride + (size_t)m0 * K;
    const __half* Xb = X + which*xstride + (size_t)b * K * PP;
    const float* biasW = bias + which * bstride;
    const uint32_t sAb = smem_u32(sA);
    const uint32_t sBb = smem_u32(sB);

    float c[MT][NT][4];
    #pragma unroll
    for(int m=0;m<MT;m++)
        #pragma unroll
        for(int n=0;n<NT;n++)
            #pragma unroll
            for(int q=0;q<4;q++) c[m][n][q]=0.f;

    const int NK = K >> 5;

    auto load_tile = [&](int kt, int s){
        #pragma unroll
        for(int i = tid; i < BM*4; i += 128){
            int m = i >> 2, k8 = (i & 3) << 3;
            uint32_t dst = sAb + (s*ASZ + m*ASTR + k8) * 2;
            asm volatile("cp.async.cg.shared.global [%0], [%1], 16;"
                :: "r"(dst), "l"(Wt + (size_t)m*K + kt*32 + k8));
        }
        // B: 32 k-rows x 128 p-cols (natural layout; zero-fill p >= PP)
        #pragma unroll
        for(int i = tid; i < 512; i += 128){
            int kr = i >> 4, c8 = (i & 15) << 3;
            int p = n0 + c8;
            const __half* src = (p < PP) ? (Xb + (size_t)(kt*32 + kr)*PP + p) : Xb;
            uint32_t sz = (p < PP) ? 16u : 0u;
            uint32_t dst = sBb + (s*BSZ + kr*BSTR + c8) * 2;
            asm volatile("cp.async.cg.shared.global [%0], [%1], 16, %2;"
                :: "r"(dst), "l"(src), "r"(sz));
        }
        asm volatile("cp.async.commit_group;" ::: "memory");
    };

    load_tile(0, 0);

    for(int kt = 0; kt < NK; kt++){
        const int s = kt & 1;
        if(kt + 1 < NK){
            load_tile(kt + 1, 1 - s);
            asm volatile("cp.async.wait_group 1;" ::: "memory");
        } else {
            asm volatile("cp.async.wait_group 0;" ::: "memory");
        }
        __syncthreads();

        const uint32_t aBase = sAb + s*ASZ*2;
        const uint32_t bBase = sBb + s*BSZ*2;
        #pragma unroll
        for(int kk = 0; kk < 32; kk += 16){
            uint32_t a[MT][4], bb[NT][2];
            #pragma unroll
            for(int m=0;m<MT;m++){
                int mr = warpM*64 + m*16;
                uint32_t addr = aBase + (uint32_t)(((mr + l8 + lb1*8)*ASTR + kk + lb2*8)*2);
                ldsm4(a[m][0],a[m][1],a[m][2],a[m][3], addr);
            }
            #pragma unroll
            for(int np=0; np<NT/2; np++){
                int nc = warpN*(NT*8) + np*16;
                uint32_t addr = bBase + (uint32_t)(((kk + lb1*8 + l8)*BSTR + nc + lb2*8)*2);
                ldsm4t(bb[2*np][0], bb[2*np][1], bb[2*np+1][0], bb[2*np+1][1], addr);
            }
            #pragma unroll
            for(int m=0;m<MT;m++)
                #pragma unroll
                for(int n=0;n<NT;n++)
                    mma16(c[m][n], a[m][0],a[m][1],a[m][2],a[m][3], bb[n][0],bb[n][1]);
        }
        __syncthreads();
    }

    const float rs = rsqrtf(1.0f + EPSV);
    #pragma unroll
    for(int m=0;m<MT;m++){
        #pragma unroll
        for(int half_=0; half_<2; half_++){
            const int row = m0 + warpM*64 + m*16 + gid + half_*8;
            float add0=0.f, sc=1.f, sh=0.f;
            if(EPI==EPI_BIAS_H || EPI==EPI_PAD) add0=biasW[row];
            if(EPI==EPI_BN_H || EPI==EPI_BNLR_H){
                add0=biasW[row]; sc=gamma[row]*rs; sh=beta[row];
            }
            #pragma unroll
            for(int n=0;n<NT;n++){
                const int p = n0 + warpN*(NT*8) + n*8 + 2*tig;
                if(p < PP){
                    float y0 = c[m][n][half_*2+0];
                    float y1 = c[m][n][half_*2+1];
                    if(EPI==EPI_PAD){
                        float* Y = (float*)Yv;
                        y0 += add0; y1 += add0;
                        int h=p/HH, w=p-h*HH;
                        float* yb = Y + ((size_t)(b*CC+row)*OUTH)*OUTH;
                        yb[(h+1)*OUTH + w+1] = y0;
                        int p1=p+1, h1=p1/HH, w1=p1-h1*HH;
                        yb[(h1+1)*OUTH + w1+1] = y1;
                    } else {
                        if(EPI==EPI_BIAS_H){ y0+=add0; y1+=add0; }
                        if(EPI==EPI_BN_H){ y0=(y0+add0)*sc+sh; y1=(y1+add0)*sc+sh; }
                        if(EPI==EPI_BNLR_H){
                            y0=(y0+add0)*sc+sh; y0=(y0>=0.f)?y0:0.2f*y0;
                            y1=(y1+add0)*sc+sh; y1=(y1>=0.f)?y1:0.2f*y1;
                        }
                        __half* Yh = (__half*)Yv + which*ystride;
                        *reinterpret_cast<__half2*>(Yh + ((size_t)b*Mtot + row)*PP + p)
                            = __floats2half2_rn(y0, y1);
                    }
                }
            }
        }
    }
}

// ================= tensor-core attention =================
__global__ __launch_bounds__(128)
void attn_tc(const __half* __restrict__ lqh, const __half* __restrict__ kvsh,
             const __half* __restrict__ kvfqh, const float* __restrict__ gqs,
             __half* __restrict__ fH)
{
    constexpr int STR = 72;
    __shared__ __align__(16) __half sQ  [64*STR];
    __shared__ __align__(16) __half sK  [64*STR];
    __shared__ __align__(16) __half sVT [64*STR];
    __shared__ __align__(16) __half sGK [64*STR];
    __shared__ __align__(16) __half sGVT[64*STR];

    const int bc = blockIdx.x;
    const int b = bc >> 8, ch = bc & 255;
    const size_t base_q = (size_t)bc * PP;
    const size_t base_k = ((size_t)(b*512 + ch)) * PP;
    const size_t base_v = base_k + (size_t)256 * PP;
    const int tid = threadIdx.x, wid = tid>>5, lane = tid&31;
    const int gid = lane>>2, tig = lane&3;
    const int l8 = lane&7, lb1 = (lane>>3)&1, lb2 = lane>>4;

    const uint32_t* gQ  = (const uint32_t*)(lqh  + base_q);
    const uint32_t* gK  = (const uint32_t*)(kvsh + base_k);
    const uint32_t* gV  = (const uint32_t*)(kvsh + base_v);
    const uint32_t* gGK = (const uint32_t*)(kvfqh + base_k);
    const uint32_t* gGV = (const uint32_t*)(kvfqh + base_v);
    uint32_t* uQ  = (uint32_t*)sQ;
    uint32_t* uK  = (uint32_t*)sK;
    uint32_t* uGK = (uint32_t*)sGK;
    uint32_t* uVT = (uint32_t*)sVT;
    uint32_t* uGVT= (uint32_t*)sGVT;

    for(int i = tid; i < 56*32; i += 128){
        int r = i >> 5, j = i & 31;
        uint32_t vq=0, vk=0, vg=0;
        if(j < 28){ int src = r*28 + j; vq = gQ[src]; vk = gK[src]; vg = gGK[src]; }
        int dst = r*36 + j;
        uQ[dst]=vq; uK[dst]=vk; uGK[dst]=vg;
    }
    for(int i = tid; i < 56*28; i += 128){
        int v = i/28, jw = i - v*28;
        uint32_t pv = gV[v*28+jw], pg = gGV[v*28+jw];
        __half2 hv = *reinterpret_cast<__half2*>(&pv);
        __half2 hg = *reinterpret_cast<__half2*>(&pg);
        sVT [(2*jw  )*STR + v] = __low2half(hv);
        sVT [(2*jw+1)*STR + v] = __high2half(hv);
        sGVT[(2*jw  )*STR + v] = __low2half(hg);
        sGVT[(2*jw+1)*STR + v] = __high2half(hg);
    }
    for(int i = tid; i < 64*4; i += 128){
        int r = i>>2, j = i&3;
        uVT[r*36 + 28 + j] = 0; uGVT[r*36 + 28 + j] = 0;
    }
    __syncthreads();

    const uint32_t qB = smem_u32(sQ), kB = smem_u32(sK), vB = smem_u32(sVT);
    const uint32_t gkB = smem_u32(sGK), gvB = smem_u32(sGVT);
    const int m0 = wid*16;
    const uint32_t aOff = (uint32_t)(((m0 + l8 + lb1*8)*STR)*2);
    const uint32_t bRow = (uint32_t)((l8 + lb2*8)*STR*2);

    float c[8][4];
    #pragma unroll
    for(int n=0;n<8;n++){ c[n][0]=0; c[n][1]=0; c[n][2]=0; c[n][3]=0; }
    #pragma unroll
    for(int kk = 0; kk < 64; kk += 16){
        uint32_t a0,a1,a2,a3;
        ldsm4(a0,a1,a2,a3, qB + aOff + (kk + lb2*8)*2);
        uint32_t bb[8][2];
        #pragma unroll
        for(int np=0;np<4;np++){
            uint32_t addr = kB + bRow + (uint32_t)((np*16*STR + kk + lb1*8)*2);
            ldsm4(bb[2*np][0], bb[2*np][1], bb[2*np+1][0], bb[2*np+1][1], addr);
        }
        #pragma unroll
        for(int n=0;n<8;n++)
            mma16(c[n], a0,a1,a2,a3, bb[n][0], bb[n][1]);
    }
    __syncthreads();

    #pragma unroll
    for(int half_=0; half_<2; half_++){
        const int h2 = half_*2;
        float m = -1e30f;
        #pragma unroll
        for(int n=0;n<7;n++) m = fmaxf(m, fmaxf(c[n][h2], c[n][h2+1]));
        m = fmaxf(m, __shfl_xor_sync(0xffffffffu, m, 1));
        m = fmaxf(m, __shfl_xor_sync(0xffffffffu, m, 2));
        float s = 0.f;
        #pragma unroll
        for(int n=0;n<7;n++){
            float e0 = __expf((c[n][h2  ] - m)*SCALEV);
            float e1 = __expf((c[n][h2+1] - m)*SCALEV);
            c[n][h2]=e0; c[n][h2+1]=e1; s += e0+e1;
        }
        s += __shfl_xor_sync(0xffffffffu, s, 1);
        s += __shfl_xor_sync(0xffffffffu, s, 2);
        const float inv = 1.f/s;
        const int row = m0 + gid + half_*8;
        #pragma unroll
        for(int n=0;n<8;n++){
            __half2 hv = (n<7) ? __floats2half2_rn(c[n][h2]*inv, c[n][h2+1]*inv)
                               : __floats2half2_rn(0.f, 0.f);
            *reinterpret_cast<__half2*>(sQ + row*STR + n*8 + 2*tig) = hv;
        }
    }

    if(tid < 56){
        const float gq = gqs[bc];
        __half* row = sGK + tid*STR;
        float m = -1e30f;
        for(int k=0;k<56;k++) m = fmaxf(m, gq*__half2float(row[k]));
        float s = 0.f;
        for(int k=0;k<56;k++){
            float e = __expf(gq*__half2float(row[k]) - m);
            row[k] = __float2half(e);
            s += e;
        }
        const float inv = 1.f/s;
        for(int k=0;k<56;k++)
            row[k] = __float2half(__half2float(row[k])*inv);
        uint32_t* ur = (uint32_t*)row;
        ur[28]=0; ur[29]=0; ur[30]=0; ur[31]=0;
    }
    __syncthreads();

    #pragma unroll
    for(int n=0;n<8;n++){ c[n][0]=0; c[n][1]=0; c[n][2]=0; c[n][3]=0; }
    #pragma unroll
    for(int kk = 0; kk < 64; kk += 16){
        uint32_t a0,a1,a2,a3;
        ldsm4(a0,a1,a2,a3, qB + aOff + (kk + lb2*8)*2);
        uint32_t bb[8][2];
        #pragma unroll
        for(int np=0;np<4;np++){
            uint32_t addr = vB + bRow + (uint32_t)((np*16*STR + kk + lb1*8)*2);
            ldsm4(bb[2*np][0], bb[2*np][1], bb[2*np+1][0], bb[2*np+1][1], addr);
        }
        #pragma unroll
        for(int n=0;n<8;n++)
            mma16(c[n], a0,a1,a2,a3, bb[n][0], bb[n][1]);
    }
    #pragma unroll
    for(int kk = 0; kk < 64; kk += 16){
        uint32_t a0,a1,a2,a3;
        ldsm4(a0,a1,a2,a3, gkB + aOff + (kk + lb2*8)*2);
        uint32_t bb[8][2];
        #pragma unroll
        for(int np=0;np<4;np++){
            uint32_t addr = gvB + bRow + (uint32_t)((np*16*STR + kk + lb1*8)*2);
            ldsm4(bb[2*np][0], bb[2*np][1], bb[2*np+1][0], bb[2*np+1][1], addr);
        }
        #pragma unroll
        for(int n=0;n<8;n++)
            mma16(c[n], a0,a1,a2,a3, bb[n][0], bb[n][1]);
    }

    #pragma unroll
    for(int half_=0; half_<2; half_++){
        const int row = m0 + gid + half_*8;
        if(row < 56){
            #pragma unroll
            for(int n=0;n<7;n++){
                *reinterpret_cast<__half2*>(fH + base_q + row*HH + n*8 + 2*tig)
                    = __floats2half2_rn(c[n][half_*2], c[n][half_*2+1]);
            }
        }
    }
}

// ---------------- fp32 -> half streaming convert (both inputs) ----------------
__global__ void cvt_pair(const float* __restrict__ a, const float* __restrict__ bsrc,
                         __half* __restrict__ dst)
{
    const int idx = blockIdx.x*256 + threadIdx.x;
    const int N4 = NXE/4;
    if(idx < N4){
        float4 v = reinterpret_cast<const float4*>(a)[idx];
        __half2 h0 = __floats2half2_rn(v.x, v.y);
        __half2 h1 = __floats2half2_rn(v.z, v.w);
        uint2 o;
        o.x = *reinterpret_cast<uint32_t*>(&h0);
        o.y = *reinterpret_cast<uint32_t*>(&h1);
        reinterpret_cast<uint2*>(dst)[idx] = o;

        float4 w = reinterpret_cast<const float4*>(bsrc)[idx];
        __half2 g0 = __floats2half2_rn(w.x, w.y);
        __half2 g1 = __floats2half2_rn(w.z, w.w);
        uint2 o2;
        o2.x = *reinterpret_cast<uint32_t*>(&g0);
        o2.y = *reinterpret_cast<uint32_t*>(&g1);
        reinterpret_cast<uint2*>(dst + NXE)[idx] = o2;
    }
}

// ---------------- weight prep ----------------
__global__ void prep_kernel(const float* __restrict__ lk_w, const float* __restrict__ lv_w,
                            const float* __restrict__ gk_w, const float* __restrict__ gv_w,
                            const float* __restrict__ la_w1, const float* __restrict__ la_w2,
                            const float* __restrict__ c1_w,
                            const float* __restrict__ lk_b, const float* __restrict__ gk_b,
                            __half* __restrict__ wh, float* __restrict__ sb)
{
    const int i = blockIdx.x*256 + threadIdx.x;
    if(i < 131072){
        wh[i]          = __float2half(i < 65536 ? lk_w[i] : lv_w[i-65536]);
        wh[131072 + i] = __float2half(i < 65536 ? gk_w[i] : gv_w[i-65536]);
    } else if(i < 147456){
        int j = i - 131072;
        wh[262144 + j] = __float2half(la_w1[j]);
        wh[278528 + j] = __float2half(la_w2[j]);
    }
    if(i < 65536) wh[294912 + i] = __float2half(c1_w[i]);
    if(i < 512){
        sb[i]       = (i < 256) ? lk_b[i] : 0.f;
        sb[512 + i] = (i < 256) ? gk_b[i] : 0.f;
    }
}

// ---------------- border fill ----------------
__global__ void border_fill_kernel(float* __restrict__ out, const float* __restrict__ bias)
{
    const int idx = blockIdx.x*256 + threadIdx.x;
    const int total = BB*CC*228;
    if(idx >= total) return;
    const int bc = idx / 228, j = idx - bc*228;
    int h, w;
    if(j < 58){ h = 0; w = j; }
    else if(j < 116){ h = 57; w = j - 58; }
    else { int j2 = j - 116; h = 1 + (j2 >> 1); w = (j2 & 1) * 57; }
    out[((size_t)bc*OUTH + h)*OUTH + w] = bias[bc & 255];
}

// ---------------- per-(b,c) mean ----------------
__global__ void mean_kernel(const float* __restrict__ x, float* __restrict__ xbar)
{
    __shared__ float red[256];
    const int bc=blockIdx.x;
    const float* p = x + (size_t)bc*PP;
    float s=0.f;
    for(int i=threadIdx.x;i<PP;i+=256) s+=p[i];
    red[threadIdx.x]=s; __syncthreads();
    for(int o=128;o>0;o>>=1){ if(threadIdx.x<o) red[threadIdx.x]+=red[threadIdx.x+o]; __syncthreads(); }
    if(threadIdx.x==0) xbar[bc]=red[0]*(1.0f/PP);
}

// ---------------- global-branch query MLP ----------------
__global__ void gq_kernel(const float* __restrict__ xbar,
                          const float* __restrict__ c11_w, const float* __restrict__ c11_b,
                          const float* __restrict__ ga_w1, const float* __restrict__ ga_b1,
                          const float* __restrict__ ga_g1, const float* __restrict__ ga_be1,
                          const float* __restrict__ ga_w2, const float* __restrict__ ga_b2,
                          const float* __restrict__ ga_g2, const float* __restrict__ ga_be2,
                          float* __restrict__ gqs)
{
    __shared__ float xb[CC], pv[CC], tv[ICC];
    const int b=blockIdx.x, t=threadIdx.x;
    const float rs=rsqrtf(1.0f+EPSV);
    xb[t]=xbar[b*CC+t]; __syncthreads();
    { float d=0.f; const float* wr=c11_w+(size_t)t*CC;
      for(int c=0;c<CC;c++) d=fmaf(wr[c],xb[c],d);
      pv[t]=d+c11_b[t]; }
    __syncthreads();
    if(t<ICC){ float d=0.f; const float* wr=ga_w1+(size_t)t*CC;
      for(int c=0;c<CC;c++) d=fmaf(wr[c],pv[c],d);
      d=(d+ga_b1[t])*(ga_g1[t]*rs)+ga_be1[t];
      tv[t]=(d>=0.f)?d:0.2f*d; }
    __syncthreads();
    { float d=0.f; const float* wr=ga_w2+(size_t)t*ICC;
      for(int i=0;i<ICC;i++) d=fmaf(wr[i],tv[i],d);
      d=(d+ga_b2[t])*(ga_g2[t]*rs)+ga_be2[t];
      gqs[b*CC+t]=d*SCALEV; }
}

// ---------------- launch ----------------
extern "C" void kernel_launch(void* const* d_in, const int* in_sizes, int n_in,
                              void* d_out, int out_size)
{
    const float* x_s  =(const float*)d_in[0];
    const float* x_fq =(const float*)d_in[1];
    const float* x_mt =(const float*)d_in[2];
    const float* la_w1=(const float*)d_in[3];
    const float* la_b1=(const float*)d_in[4];
    const float* la_g1=(const float*)d_in[5];
    const float* la_be1=(const float*)d_in[6];
    const float* la_w2=(const float*)d_in[7];
    const float* la_b2=(const float*)d_in[8];
    const float* la_g2=(const float*)d_in[9];
    const float* la_be2=(const float*)d_in[10];
    const float* lk_w =(const float*)d_in[11];
    const float* lk_b =(const float*)d_in[12];
    const float* lv_w =(const float*)d_in[13];
    const float* ga_w1=(const float*)d_in[14];
    const float* ga_b1=(const float*)d_in[15];
    const float* ga_g1=(const float*)d_in[16];
    const float* ga_be1=(const float*)d_in[17];
    const float* ga_w2=(const float*)d_in[18];
    const float* ga_b2=(const float*)d_in[19];
    const float* ga_g2=(const float*)d_in[20];
    const float* ga_be2=(const float*)d_in[21];
    const float* gk_w =(const float*)d_in[22];
    const float* gk_b =(const float*)d_in[23];
    const float* gv_w =(const float*)d_in[24];
    const float* c11_w=(const float*)d_in[25];
    const float* c11_b=(const float*)d_in[26];
    const float* c1_w =(const float*)d_in[27];
    const float* c1_b =(const float*)d_in[28];
    float* out=(float*)d_out;

    __half *xH,*t1H,*lqh,*kv,*fH,*wh;
    float *xbar,*gqs,*sb;
    cudaGetSymbolAddress((void**)&xH,  g_xH);
    cudaGetSymbolAddress((void**)&t1H, g_t1H);
    cudaGetSymbolAddress((void**)&lqh, g_lqh);
    cudaGetSymbolAddress((void**)&kv,  g_kv);
    cudaGetSymbolAddress((void**)&fH,  g_fH);
    cudaGetSymbolAddress((void**)&xbar,g_xbar);
    cudaGetSymbolAddress((void**)&gqs, g_gqs);
    cudaGetSymbolAddress((void**)&wh,  g_wh);
    cudaGetSymbolAddress((void**)&sb,  g_sb);

    __half* wh_kvs  = wh;            // dual: which*131072 offset
    __half* wh_la1  = wh + 262144;
    __half* wh_la2  = wh + 278528;
    __half* wh_c1   = wh + 294912;

    const size_t KVN = (size_t)BB*2*CC*PP;
    const int NB = (PP + 127)/128;   // 25

    // 1: weight prep
    prep_kernel<<<576, 256>>>(lk_w, lv_w, gk_w, gv_w, la_w1, la_w2, c1_w,
                              lk_b, gk_b, wh, sb);
    // 2: convert both inputs to half (natural layout)
    cvt_pair<<<(NXE/4 + 255)/256, 256>>>(x_s, x_fq, xH);
    // 3: border fill
    border_fill_kernel<<<(BB*CC*228 + 255)/256, 256>>>(out, c1_b);
    // 4: fused dual KV GEMM (l_k/l_v and g_k/g_v in one launch) <-- profiled
    {   dim3 g(NB, 4, 2*BB);
        hgemm<128, EPI_BIAS_H><<<g, 128>>>(wh_kvs, xH, kv, CC, 512,
                                           sb, sb, sb,
                                           131072, (size_t)NXE, KVN, 512);
    }
    // 5: t1 = lrelu(bn(la_w1 @ x_s)) -> half [b][64][p]
    {   dim3 g(NB, 1, BB);
        hgemm<64, EPI_BNLR_H><<<g, 128>>>(wh_la1, xH, t1H, CC, ICC,
                                          la_b1, la_g1, la_be1, 0, 0, 0, 0);
    }
    // 6: l_q = bn(la_w2 @ t1) -> half [b][256][p]
    {   dim3 g(NB, CC/128, BB);
        hgemm<128, EPI_BN_H><<<g, 128>>>(wh_la2, t1H, lqh, ICC, CC,
                                         la_b2, la_g2, la_be2, 0, 0, 0, 0);
    }
    // 7: mean
    mean_kernel<<<BB*CC, 256>>>(x_mt, xbar);
    // 8: gq MLP
    gq_kernel<<<BB, 256>>>(xbar, c11_w, c11_b, ga_w1, ga_b1, ga_g1, ga_be1,
                           ga_w2, ga_b2, ga_g2, ga_be2, gqs);
    // 9: tensor-core attention -> fH [b][c][p]
    attn_tc<<<BB*CC, 128>>>(lqh, kv, kv + KVN, gqs, fH);
    // 10: padded output conv (reads fH directly, trans-B path)
    {   dim3 g(NB, CC/128, BB);
        hgemm<128, EPI_PAD><<<g, 128>>>(wh_c1, fH, out, CC, CC,
                                        c1_b, c1_b, c1_b, 0, 0, 0, 0);
    }
}